// round 1
// baseline (speedup 1.0000x reference)
#include <cuda_runtime.h>

#define Bn 2
#define Nn 768
#define CS 1024
#define CZ 128
#define NH 16
#define HD 64
#define MROWS (Bn*Nn)   // 1536
#define NPAIR (Bn*Nn*Nn)  // 1179648

// ---------------- scratch (device globals; no allocations allowed) ----------------
__device__ float d_q[MROWS*CS];
__device__ float d_k[MROWS*CS];
__device__ float d_v[MROWS*CS];
__device__ float d_g[MROWS*CS];
__device__ float d_go[MROWS*CS];
__device__ float d_bias[Bn*NH*Nn*Nn];     // 75.5 MB
__device__ float d_Gz[CZ*NH];
__device__ float d_Bh[NH];
__device__ float d_GzSum[NH];

// ---------------- SGEMM: C[M,N] = A[M,K] @ B[K,N] (+bias) (sigmoid?) ----------------
// BM=128, BN=64, BK=16, 256 threads, 8x4 per thread.
template<bool ADD_BIAS, bool SIGMOID>
__global__ void __launch_bounds__(256) sgemm_kernel(
    const float* __restrict__ A, const float* __restrict__ Bm,
    const float* __restrict__ bias, float* __restrict__ C,
    int M, int N, int K)
{
    __shared__ float As[16*132];   // transposed, padded
    __shared__ float Bs[16*64];

    int tid = threadIdx.x;
    int tx = tid & 15;        // 16 col-groups of 4
    int ty = tid >> 4;        // 16 row-groups of 8
    int m0 = blockIdx.y * 128;
    int n0 = blockIdx.x * 64;

    float4 acc[8];
    #pragma unroll
    for (int i = 0; i < 8; i++) acc[i] = make_float4(0.f,0.f,0.f,0.f);

    for (int k0 = 0; k0 < K; k0 += 16) {
        // load A tile 128x16 (512 float4), transpose into As[k][m]
        #pragma unroll
        for (int r = 0; r < 2; r++) {
            int idx = tid + 256*r;
            int row = idx >> 2, kq = idx & 3;
            float4 av = *(const float4*)(A + (size_t)(m0+row)*K + k0 + kq*4);
            As[(kq*4+0)*132 + row] = av.x;
            As[(kq*4+1)*132 + row] = av.y;
            As[(kq*4+2)*132 + row] = av.z;
            As[(kq*4+3)*132 + row] = av.w;
        }
        // load B tile 16x64 (256 float4)
        {
            int row = tid >> 4, nq = tid & 15;
            *(float4*)(Bs + row*64 + nq*4) =
                *(const float4*)(Bm + (size_t)(k0+row)*N + n0 + nq*4);
        }
        __syncthreads();

        #pragma unroll
        for (int kk = 0; kk < 16; kk++) {
            float4 b0 = *(float4*)(Bs + kk*64 + tx*4);
            float4 a0 = *(float4*)(As + kk*132 + ty*8);
            float4 a1 = *(float4*)(As + kk*132 + ty*8 + 4);
            float av[8] = {a0.x,a0.y,a0.z,a0.w,a1.x,a1.y,a1.z,a1.w};
            #pragma unroll
            for (int i = 0; i < 8; i++) {
                acc[i].x += av[i]*b0.x;
                acc[i].y += av[i]*b0.y;
                acc[i].z += av[i]*b0.z;
                acc[i].w += av[i]*b0.w;
            }
        }
        __syncthreads();
    }

    float4 bv = make_float4(0.f,0.f,0.f,0.f);
    if (ADD_BIAS) bv = *(const float4*)(bias + n0 + tx*4);
    #pragma unroll
    for (int i = 0; i < 8; i++) {
        float4 r = acc[i];
        if (ADD_BIAS) { r.x += bv.x; r.y += bv.y; r.z += bv.z; r.w += bv.w; }
        if (SIGMOID) {
            r.x = 1.f/(1.f + __expf(-r.x));
            r.y = 1.f/(1.f + __expf(-r.y));
            r.z = 1.f/(1.f + __expf(-r.z));
            r.w = 1.f/(1.f + __expf(-r.w));
        }
        *(float4*)(C + (size_t)(m0 + ty*8 + i)*N + n0 + tx*4) = r;
    }
}

// ---------------- fold LN affine into z-projection ----------------
__global__ void prep_kernel(const float* __restrict__ ln_g,
                            const float* __restrict__ ln_b,
                            const float* __restrict__ Wz)
{
    __shared__ float sB[CZ*NH];
    __shared__ float sG[CZ*NH];
    int c = threadIdx.x;   // 128 threads
    float g = ln_g[c], bb = ln_b[c];
    #pragma unroll
    for (int h = 0; h < NH; h++) {
        float w = Wz[c*NH + h];
        float gz = g*w;
        d_Gz[c*NH + h] = gz;
        sG[c*NH + h] = gz;
        sB[c*NH + h] = bb*w;
    }
    __syncthreads();
    if (c < NH) {
        float sb = 0.f, sg = 0.f;
        for (int cc = 0; cc < CZ; cc++) { sb += sB[cc*NH + c]; sg += sG[cc*NH + c]; }
        d_Bh[c] = sb;
        d_GzSum[c] = sg;
    }
}

// ---------------- fused LayerNorm + projection -> bias[b][h][i][j] ----------------
// 256 threads, 64 pair-rows/block, 4 threads per row (interleaved c).
__global__ void __launch_bounds__(256) bias_kernel(const float* __restrict__ z)
{
    __shared__ float GzS[CZ*24];   // padded rows (stride 24 floats, 16B aligned)
    __shared__ float BhS[NH], GzSumS[NH];
    __shared__ float stage[64*17];

    int tid = threadIdx.x;
    for (int t = tid; t < CZ*NH; t += 256) {
        int c = t >> 4, h = t & 15;
        GzS[c*24 + h] = d_Gz[t];
    }
    if (tid < NH) { BhS[tid] = d_Bh[tid]; GzSumS[tid] = d_GzSum[tid]; }
    __syncthreads();

    int r = tid >> 2;
    int lane4 = tid & 3;
    int p = blockIdx.x * 64 + r;
    const float* zr = z + (size_t)p * CZ;

    float s1 = 0.f, s2 = 0.f;
    float dots[16];
    #pragma unroll
    for (int t = 0; t < 16; t++) dots[t] = 0.f;

    #pragma unroll 8
    for (int i = 0; i < 32; i++) {
        int c = lane4 + 4*i;
        float zv = __ldg(zr + c);
        s1 += zv; s2 += zv*zv;
        const float4* grow = (const float4*)(GzS + c*24);
        float4 g0 = grow[0], g1 = grow[1], g2 = grow[2], g3 = grow[3];
        dots[0]  += zv*g0.x; dots[1]  += zv*g0.y; dots[2]  += zv*g0.z; dots[3]  += zv*g0.w;
        dots[4]  += zv*g1.x; dots[5]  += zv*g1.y; dots[6]  += zv*g1.z; dots[7]  += zv*g1.w;
        dots[8]  += zv*g2.x; dots[9]  += zv*g2.y; dots[10] += zv*g2.z; dots[11] += zv*g2.w;
        dots[12] += zv*g3.x; dots[13] += zv*g3.y; dots[14] += zv*g3.z; dots[15] += zv*g3.w;
    }
    #pragma unroll
    for (int off = 1; off <= 2; off <<= 1) {
        s1 += __shfl_xor_sync(0xFFFFFFFFu, s1, off);
        s2 += __shfl_xor_sync(0xFFFFFFFFu, s2, off);
        #pragma unroll
        for (int t = 0; t < 16; t++)
            dots[t] += __shfl_xor_sync(0xFFFFFFFFu, dots[t], off);
    }
    if (lane4 == 0) {
        float mu  = s1 * (1.f/128.f);
        float var = s2 * (1.f/128.f) - mu*mu;
        float rstd = rsqrtf(var + 1e-5f);
        float* st = stage + r*17;
        #pragma unroll
        for (int h = 0; h < NH; h++)
            st[h] = rstd*(dots[h] - mu*GzSumS[h]) + BhS[h];
    }
    __syncthreads();

    // cooperative coalesced write: all 64 rows share (b, i); j span = 64 contiguous
    int p0  = blockIdx.x * 64;
    int b   = p0 / (Nn*Nn);
    int rem = p0 % (Nn*Nn);
    int ii  = rem / Nn;
    int j0  = rem % Nn;
    for (int t = tid; t < 64*NH; t += 256) {
        int h = t >> 6, rr = t & 63;
        d_bias[((size_t)(b*NH + h)*Nn + ii)*Nn + j0 + rr] = stage[rr*17 + h];
    }
}

// ---------------- attention: block per (b, h, 16-row i-tile), 128 threads ----------------
#define SP 776   // padded score row stride
__global__ void __launch_bounds__(128) attn_kernel(const float* __restrict__ mask)
{
    extern __shared__ float sm[];
    float* sc   = sm;                    // 16*SP
    float* qs   = sm + 16*SP;            // 16*64
    float* Osm  = qs + 16*64;            // 2*16*64
    float* invs = Osm + 2*16*64;         // 16

    int tid = threadIdx.x;
    int h = blockIdx.y, b = blockIdx.z;
    int i0 = blockIdx.x * 16;

    // load q tile (16 rows x 64)
    for (int t = tid; t < 16*16; t += 128) {
        int i = t >> 4, dc = t & 15;
        ((float4*)qs)[i*16 + dc] =
            *(const float4*)(d_q + (size_t)(b*Nn + i0 + i)*CS + h*HD + dc*4);
    }
    __syncthreads();

    // pass A: scores
    for (int jt = 0; jt < 6; jt++) {
        int j = jt*128 + tid;
        const float4* kp = (const float4*)(d_k + (size_t)(b*Nn + j)*CS + h*HD);
        float acc[16];
        #pragma unroll
        for (int i = 0; i < 16; i++) acc[i] = 0.f;
        #pragma unroll
        for (int dc = 0; dc < 16; dc++) {
            float4 kv = kp[dc];
            #pragma unroll
            for (int i = 0; i < 16; i++) {
                float4 qv = ((float4*)qs)[i*16 + dc];
                acc[i] += kv.x*qv.x + kv.y*qv.y + kv.z*qv.z + kv.w*qv.w;
            }
        }
        float mk = (1.0f - __ldg(mask + b*Nn + j)) * (-1000000.0f);
        const float* bp = d_bias + ((size_t)(b*NH + h)*Nn + i0)*Nn + j;
        #pragma unroll
        for (int i = 0; i < 16; i++)
            sc[i*SP + j] = acc[i]*0.125f + bp[(size_t)i*Nn] + mk;
    }
    __syncthreads();

    // softmax: warp w handles rows {w, w+4, w+8, w+12}
    int warp = tid >> 5, lane = tid & 31;
    #pragma unroll
    for (int rr = 0; rr < 4; rr++) {
        int i = warp + rr*4;
        float m = -3.4e38f;
        for (int j = lane; j < Nn; j += 32) m = fmaxf(m, sc[i*SP + j]);
        #pragma unroll
        for (int o = 16; o; o >>= 1) m = fmaxf(m, __shfl_xor_sync(0xFFFFFFFFu, m, o));
        float s = 0.f;
        for (int j = lane; j < Nn; j += 32) {
            float e = __expf(sc[i*SP + j] - m);
            sc[i*SP + j] = e;
            s += e;
        }
        #pragma unroll
        for (int o = 16; o; o >>= 1) s += __shfl_xor_sync(0xFFFFFFFFu, s, o);
        if (lane == 0) invs[i] = 1.0f / s;
    }
    __syncthreads();

    // pass B: O = P @ V, split j across two halves of the block
    int d = tid & 63, half = tid >> 6;
    float o[16];
    #pragma unroll
    for (int i = 0; i < 16; i++) o[i] = 0.f;
    const float* vbase = d_v + (size_t)(b*Nn)*CS + h*HD + d;
    for (int jc = 0; jc < 96; jc++) {
        int j = half*384 + jc*4;
        float v0 = vbase[(size_t)(j+0)*CS];
        float v1 = vbase[(size_t)(j+1)*CS];
        float v2 = vbase[(size_t)(j+2)*CS];
        float v3 = vbase[(size_t)(j+3)*CS];
        #pragma unroll
        for (int i = 0; i < 16; i++) {
            float4 pp = *(const float4*)(sc + i*SP + j);
            o[i] += pp.x*v0 + pp.y*v1 + pp.z*v2 + pp.w*v3;
        }
    }
    #pragma unroll
    for (int i = 0; i < 16; i++) Osm[(half*16 + i)*64 + d] = o[i];
    __syncthreads();
    if (half == 0) {
        #pragma unroll
        for (int i = 0; i < 16; i++) {
            float val = (Osm[i*64 + d] + Osm[(16 + i)*64 + d]) * invs[i];
            size_t idx = (size_t)(b*Nn + i0 + i)*CS + h*HD + d;
            d_go[idx] = d_g[idx] * val;
        }
    }
}

// ---------------- launch ----------------
extern "C" void kernel_launch(void* const* d_in, const int* in_sizes, int n_in,
                              void* d_out, int out_size)
{
    const float* s    = (const float*)d_in[0];
    const float* z    = (const float*)d_in[1];
    const float* mask = (const float*)d_in[2];
    const float* k_in = (const float*)d_in[3];
    const float* Wq   = (const float*)d_in[4];
    const float* bq   = (const float*)d_in[5];
    const float* Wk   = (const float*)d_in[6];
    const float* Wv   = (const float*)d_in[7];
    const float* Wg   = (const float*)d_in[8];
    const float* ln_g = (const float*)d_in[9];
    const float* ln_b = (const float*)d_in[10];
    const float* Wz   = (const float*)d_in[11];
    const float* Wo   = (const float*)d_in[12];
    float* out = (float*)d_out;

    float *q, *k, *v, *g, *go;
    cudaGetSymbolAddress((void**)&q,  d_q);
    cudaGetSymbolAddress((void**)&k,  d_k);
    cudaGetSymbolAddress((void**)&v,  d_v);
    cudaGetSymbolAddress((void**)&g,  d_g);
    cudaGetSymbolAddress((void**)&go, d_go);

    dim3 gg(CS/64, MROWS/128);  // (16, 12)
    sgemm_kernel<true,  false><<<gg, 256>>>(s,    Wq, bq,      q,  MROWS, CS, CS);
    sgemm_kernel<false, false><<<gg, 256>>>(k_in, Wk, nullptr, k,  MROWS, CS, CS);
    sgemm_kernel<false, false><<<gg, 256>>>(k_in, Wv, nullptr, v,  MROWS, CS, CS);
    sgemm_kernel<false, true ><<<gg, 256>>>(s,    Wg, nullptr, g,  MROWS, CS, CS);

    prep_kernel<<<1, 128>>>(ln_g, ln_b, Wz);
    bias_kernel<<<NPAIR/64, 256>>>(z);

    cudaFuncSetAttribute(attn_kernel, cudaFuncAttributeMaxDynamicSharedMemorySize, 62016);
    attn_kernel<<<dim3(Nn/16, NH, Bn), 128, 62016>>>(mask);

    sgemm_kernel<false, false><<<gg, 256>>>(go, Wo, nullptr, out, MROWS, CS, CS);
}

// round 3
// speedup vs baseline: 1.2683x; 1.2683x over previous
#include <cuda_runtime.h>
#include <cuda_bf16.h>
#include <cstdint>
#include <cstddef>

#define Bn 2
#define Nn 768
#define CS 1024
#define CZ 128
#define NH 16
#define HD 64
#define MROWS (Bn*Nn)     // 1536
#define NPAIR (Bn*Nn*Nn)  // 1179648

// ---------------- scratch (device globals; no allocations allowed) ----------------
__device__ float d_q[MROWS*CS];
__device__ float d_k[MROWS*CS];
__device__ float d_v[MROWS*CS];
__device__ float d_g[MROWS*CS];
__device__ float d_go[MROWS*CS];
__device__ float d_bias[Bn*NH*Nn*Nn];     // 75.5 MB
__device__ float d_Gz[CZ*NH];
__device__ float d_Bh[NH];
__device__ float d_GzSum[NH];

// ================= bf16 split-precision tensor-core GEMM ====================
// C[M,N] = A[M,K] @ B[K,N] (+bias) (sigmoid?)
// BM=128, BN=64, BK=32, 256 threads (8 warps), warp tile 32x32.
// 3-term split: A_hi*B_hi + A_lo*B_hi + A_hi*B_lo with fp32 accumulate.

#define ASTRIDE 40   // bf16 elements per A smem row (32 + 8 pad)
#define BSTRIDE 72   // bf16 elements per B smem row (64 + 8 pad)
#define AHI_OFF 0
#define ALO_OFF 10240            // 128*40*2
#define BHI_OFF 20480
#define BLO_OFF 25088            // +32*72*2
#define BUFBYTES 29696
#define GEMM_SMEM (2*BUFBYTES)   // 59392

__device__ __forceinline__ void ldsm4(uint32_t* r, uint32_t a) {
    asm volatile("ldmatrix.sync.aligned.m8n8.x4.shared.b16 {%0,%1,%2,%3}, [%4];"
                 : "=r"(r[0]), "=r"(r[1]), "=r"(r[2]), "=r"(r[3]) : "r"(a));
}
__device__ __forceinline__ void ldsm4t(uint32_t* r, uint32_t a) {
    asm volatile("ldmatrix.sync.aligned.m8n8.x4.trans.shared.b16 {%0,%1,%2,%3}, [%4];"
                 : "=r"(r[0]), "=r"(r[1]), "=r"(r[2]), "=r"(r[3]) : "r"(a));
}
__device__ __forceinline__ void mma_bf16(float* c, const uint32_t* a, const uint32_t* b) {
    asm volatile("mma.sync.aligned.m16n8k16.row.col.f32.bf16.bf16.f32 "
                 "{%0,%1,%2,%3}, {%4,%5,%6,%7}, {%8,%9}, {%0,%1,%2,%3};"
                 : "+f"(c[0]), "+f"(c[1]), "+f"(c[2]), "+f"(c[3])
                 : "r"(a[0]), "r"(a[1]), "r"(a[2]), "r"(a[3]), "r"(b[0]), "r"(b[1]));
}
__device__ __forceinline__ void split2(float x, float y, uint32_t& hi, uint32_t& lo) {
    __nv_bfloat162 h = __float22bfloat162_rn(make_float2(x, y));
    float2 hf = __bfloat1622float2(h);
    __nv_bfloat162 l = __float22bfloat162_rn(make_float2(x - hf.x, y - hf.y));
    hi = *(uint32_t*)&h;
    lo = *(uint32_t*)&l;
}

template<bool ADD_BIAS, bool SIGMOID>
__global__ void __launch_bounds__(256) mma_gemm(
    const float* __restrict__ A, const float* __restrict__ Bm,
    const float* __restrict__ bias, float* __restrict__ C,
    int M, int N, int K)
{
    extern __shared__ char sm_raw[];
    uint32_t sbase = (uint32_t)__cvta_generic_to_shared(sm_raw);

    int tid = threadIdx.x;
    int wid = tid >> 5, lane = tid & 31;
    int warpM = wid >> 1, warpN = wid & 1;
    int m0 = blockIdx.y * 128, n0 = blockIdx.x * 64;

    // gmem staging assignments
    int rowA = tid >> 1, halfA = tid & 1;            // A: 128 rows x 32 cols, 16 floats/thread
    int rowB = tid >> 3, colB = (tid & 7) * 8;       // B: 32 rows x 64 cols, 8 floats/thread
    const float* gA = A + (size_t)(m0 + rowA) * K + halfA * 16;
    const float* gB = Bm + (size_t)rowB * N + n0 + colB;

    float acc[2][4][4];
    #pragma unroll
    for (int mt = 0; mt < 2; mt++)
        #pragma unroll
        for (int nt = 0; nt < 4; nt++)
            #pragma unroll
            for (int i = 0; i < 4; i++) acc[mt][nt][i] = 0.f;

    const int CHUNKS = K / 32;
    float4 ra[4], rb[2];

    // ldmatrix per-lane address components
    int matr = lane >> 3, rr = lane & 7;
    int aRowBase = warpM * 32 + (matr & 1) * 8 + rr;     // + mt*16
    int aColBase = (matr >> 1) * 8;                      // + ks
    int bRowBase = (matr & 1) * 8 + rr;                  // + ks
    int bColBase = warpN * 32 + (matr >> 1) * 8;         // + ntp*16

    // convert+store one chunk of staged regs into buffer `buf`
    auto store_chunk = [&](int buf) {
        uint32_t off = buf * BUFBYTES;
        uint32_t* ahi = (uint32_t*)(sm_raw + off + AHI_OFF);
        uint32_t* alo = (uint32_t*)(sm_raw + off + ALO_OFF);
        uint32_t* bhi = (uint32_t*)(sm_raw + off + BHI_OFF);
        uint32_t* blo = (uint32_t*)(sm_raw + off + BLO_OFF);
        #pragma unroll
        for (int q = 0; q < 4; q++) {
            int col = halfA * 16 + q * 4;
            int e0 = (rowA * ASTRIDE + col) >> 1;
            uint32_t h0, l0, h1, l1;
            split2(ra[q].x, ra[q].y, h0, l0);
            split2(ra[q].z, ra[q].w, h1, l1);
            ahi[e0] = h0; ahi[e0 + 1] = h1;
            alo[e0] = l0; alo[e0 + 1] = l1;
        }
        #pragma unroll
        for (int q = 0; q < 2; q++) {
            int col = colB + q * 4;
            int e0 = (rowB * BSTRIDE + col) >> 1;
            uint32_t h0, l0, h1, l1;
            split2(rb[q].x, rb[q].y, h0, l0);
            split2(rb[q].z, rb[q].w, h1, l1);
            bhi[e0] = h0; bhi[e0 + 1] = h1;
            blo[e0] = l0; blo[e0 + 1] = l1;
        }
    };

    // prologue: chunk 0
    #pragma unroll
    for (int q = 0; q < 4; q++) ra[q] = *(const float4*)(gA + q * 4);
    #pragma unroll
    for (int q = 0; q < 2; q++) rb[q] = *(const float4*)(gB + q * 4);
    store_chunk(0);

    for (int c = 0; c < CHUNKS; c++) {
        __syncthreads();
        int buf = c & 1;
        if (c + 1 < CHUNKS) {
            const float* pA = gA + (c + 1) * 32;
            const float* pB = gB + (size_t)(c + 1) * 32 * N;
            #pragma unroll
            for (int q = 0; q < 4; q++) ra[q] = *(const float4*)(pA + q * 4);
            #pragma unroll
            for (int q = 0; q < 2; q++) rb[q] = *(const float4*)(pB + q * 4);
        }

        uint32_t off = sbase + buf * BUFBYTES;
        #pragma unroll
        for (int ks = 0; ks < 32; ks += 16) {
            uint32_t Ah[2][4], Al[2][4], Bh[2][4], Bl[2][4];
            #pragma unroll
            for (int mt = 0; mt < 2; mt++)
                ldsm4(Ah[mt], off + AHI_OFF +
                      (((aRowBase + mt * 16) * ASTRIDE) + aColBase + ks) * 2);
            #pragma unroll
            for (int ntp = 0; ntp < 2; ntp++)
                ldsm4t(Bh[ntp], off + BHI_OFF +
                       (((bRowBase + ks) * BSTRIDE) + bColBase + ntp * 16) * 2);
            #pragma unroll
            for (int mt = 0; mt < 2; mt++)
                #pragma unroll
                for (int nt = 0; nt < 4; nt++)
                    mma_bf16(acc[mt][nt], Ah[mt], &Bh[nt >> 1][(nt & 1) * 2]);

            #pragma unroll
            for (int mt = 0; mt < 2; mt++)
                ldsm4(Al[mt], off + ALO_OFF +
                      (((aRowBase + mt * 16) * ASTRIDE) + aColBase + ks) * 2);
            #pragma unroll
            for (int mt = 0; mt < 2; mt++)
                #pragma unroll
                for (int nt = 0; nt < 4; nt++)
                    mma_bf16(acc[mt][nt], Al[mt], &Bh[nt >> 1][(nt & 1) * 2]);

            #pragma unroll
            for (int ntp = 0; ntp < 2; ntp++)
                ldsm4t(Bl[ntp], off + BLO_OFF +
                       (((bRowBase + ks) * BSTRIDE) + bColBase + ntp * 16) * 2);
            #pragma unroll
            for (int mt = 0; mt < 2; mt++)
                #pragma unroll
                for (int nt = 0; nt < 4; nt++)
                    mma_bf16(acc[mt][nt], Ah[mt], &Bl[nt >> 1][(nt & 1) * 2]);
        }

        if (c + 1 < CHUNKS) store_chunk(buf ^ 1);
    }

    // epilogue
    int grp = lane >> 2, tL = lane & 3;
    #pragma unroll
    for (int mt = 0; mt < 2; mt++) {
        #pragma unroll
        for (int nt = 0; nt < 4; nt++) {
            int row = m0 + warpM * 32 + mt * 16 + grp;
            int col = n0 + warpN * 32 + nt * 8 + tL * 2;
            float b0 = 0.f, b1 = 0.f;
            if (ADD_BIAS) { b0 = bias[col]; b1 = bias[col + 1]; }
            float v0 = acc[mt][nt][0] + b0, v1 = acc[mt][nt][1] + b1;
            float v2 = acc[mt][nt][2] + b0, v3 = acc[mt][nt][3] + b1;
            if (SIGMOID) {
                v0 = 1.f / (1.f + __expf(-v0));
                v1 = 1.f / (1.f + __expf(-v1));
                v2 = 1.f / (1.f + __expf(-v2));
                v3 = 1.f / (1.f + __expf(-v3));
            }
            *(float2*)(C + (size_t)row * N + col)       = make_float2(v0, v1);
            *(float2*)(C + (size_t)(row + 8) * N + col) = make_float2(v2, v3);
        }
    }
}

// ---------------- fold LN affine into z-projection ----------------
__global__ void prep_kernel(const float* __restrict__ ln_g,
                            const float* __restrict__ ln_b,
                            const float* __restrict__ Wz)
{
    __shared__ float sB[CZ*NH];
    __shared__ float sG[CZ*NH];
    int c = threadIdx.x;   // 128 threads
    float g = ln_g[c], bb = ln_b[c];
    #pragma unroll
    for (int h = 0; h < NH; h++) {
        float w = Wz[c*NH + h];
        float gz = g*w;
        d_Gz[c*NH + h] = gz;
        sG[c*NH + h] = gz;
        sB[c*NH + h] = bb*w;
    }
    __syncthreads();
    if (c < NH) {
        float sb = 0.f, sg = 0.f;
        for (int cc = 0; cc < CZ; cc++) { sb += sB[cc*NH + c]; sg += sG[cc*NH + c]; }
        d_Bh[c] = sb;
        d_GzSum[c] = sg;
    }
}

// ---------------- fused LayerNorm + projection -> bias[b][h][i][j] ----------------
__global__ void __launch_bounds__(256) bias_kernel(const float* __restrict__ z)
{
    __shared__ float GzS[CZ*24];
    __shared__ float BhS[NH], GzSumS[NH];
    __shared__ float stage[64*17];

    int tid = threadIdx.x;
    for (int t = tid; t < CZ*NH; t += 256) {
        int c = t >> 4, h = t & 15;
        GzS[c*24 + h] = d_Gz[t];
    }
    if (tid < NH) { BhS[tid] = d_Bh[tid]; GzSumS[tid] = d_GzSum[tid]; }
    __syncthreads();

    int r = tid >> 2;
    int lane4 = tid & 3;
    int p = blockIdx.x * 64 + r;
    const float* zr = z + (size_t)p * CZ;

    float s1 = 0.f, s2 = 0.f;
    float dots[16];
    #pragma unroll
    for (int t = 0; t < 16; t++) dots[t] = 0.f;

    #pragma unroll 8
    for (int i = 0; i < 32; i++) {
        int c = lane4 + 4*i;
        float zv = __ldg(zr + c);
        s1 += zv; s2 += zv*zv;
        const float4* grow = (const float4*)(GzS + c*24);
        float4 g0 = grow[0], g1 = grow[1], g2 = grow[2], g3 = grow[3];
        dots[0]  += zv*g0.x; dots[1]  += zv*g0.y; dots[2]  += zv*g0.z; dots[3]  += zv*g0.w;
        dots[4]  += zv*g1.x; dots[5]  += zv*g1.y; dots[6]  += zv*g1.z; dots[7]  += zv*g1.w;
        dots[8]  += zv*g2.x; dots[9]  += zv*g2.y; dots[10] += zv*g2.z; dots[11] += zv*g2.w;
        dots[12] += zv*g3.x; dots[13] += zv*g3.y; dots[14] += zv*g3.z; dots[15] += zv*g3.w;
    }
    #pragma unroll
    for (int off = 1; off <= 2; off <<= 1) {
        s1 += __shfl_xor_sync(0xFFFFFFFFu, s1, off);
        s2 += __shfl_xor_sync(0xFFFFFFFFu, s2, off);
        #pragma unroll
        for (int t = 0; t < 16; t++)
            dots[t] += __shfl_xor_sync(0xFFFFFFFFu, dots[t], off);
    }
    if (lane4 == 0) {
        float mu  = s1 * (1.f/128.f);
        float var = s2 * (1.f/128.f) - mu*mu;
        float rstd = rsqrtf(var + 1e-5f);
        float* st = stage + r*17;
        #pragma unroll
        for (int h = 0; h < NH; h++)
            st[h] = rstd*(dots[h] - mu*GzSumS[h]) + BhS[h];
    }
    __syncthreads();

    int p0  = blockIdx.x * 64;
    int b   = p0 / (Nn*Nn);
    int rem = p0 % (Nn*Nn);
    int ii  = rem / Nn;
    int j0  = rem % Nn;
    for (int t = tid; t < 64*NH; t += 256) {
        int h = t >> 6, rr2 = t & 63;
        d_bias[((size_t)(b*NH + h)*Nn + ii)*Nn + j0 + rr2] = stage[rr2*17 + h];
    }
}

// ---------------- attention: block per (b, h, 16-row i-tile), 128 threads ----------------
#define SP 776
__global__ void __launch_bounds__(128) attn_kernel(const float* __restrict__ mask)
{
    extern __shared__ float sm[];
    float* sc   = sm;
    float* qs   = sm + 16*SP;
    float* Osm  = qs + 16*64;
    float* invs = Osm + 2*16*64;

    int tid = threadIdx.x;
    int h = blockIdx.y, b = blockIdx.z;
    int i0 = blockIdx.x * 16;

    for (int t = tid; t < 16*16; t += 128) {
        int i = t >> 4, dc = t & 15;
        ((float4*)qs)[i*16 + dc] =
            *(const float4*)(d_q + (size_t)(b*Nn + i0 + i)*CS + h*HD + dc*4);
    }
    __syncthreads();

    for (int jt = 0; jt < 6; jt++) {
        int j = jt*128 + tid;
        const float4* kp = (const float4*)(d_k + (size_t)(b*Nn + j)*CS + h*HD);
        float acc[16];
        #pragma unroll
        for (int i = 0; i < 16; i++) acc[i] = 0.f;
        #pragma unroll
        for (int dc = 0; dc < 16; dc++) {
            float4 kv = kp[dc];
            #pragma unroll
            for (int i = 0; i < 16; i++) {
                float4 qv = ((float4*)qs)[i*16 + dc];
                acc[i] += kv.x*qv.x + kv.y*qv.y + kv.z*qv.z + kv.w*qv.w;
            }
        }
        float mk = (1.0f - __ldg(mask + b*Nn + j)) * (-1000000.0f);
        const float* bp = d_bias + ((size_t)(b*NH + h)*Nn + i0)*Nn + j;
        #pragma unroll
        for (int i = 0; i < 16; i++)
            sc[i*SP + j] = acc[i]*0.125f + bp[(size_t)i*Nn] + mk;
    }
    __syncthreads();

    int warp = tid >> 5, lane = tid & 31;
    #pragma unroll
    for (int rr = 0; rr < 4; rr++) {
        int i = warp + rr*4;
        float m = -3.4e38f;
        for (int j = lane; j < Nn; j += 32) m = fmaxf(m, sc[i*SP + j]);
        #pragma unroll
        for (int o = 16; o; o >>= 1) m = fmaxf(m, __shfl_xor_sync(0xFFFFFFFFu, m, o));
        float s = 0.f;
        for (int j = lane; j < Nn; j += 32) {
            float e = __expf(sc[i*SP + j] - m);
            sc[i*SP + j] = e;
            s += e;
        }
        #pragma unroll
        for (int o = 16; o; o >>= 1) s += __shfl_xor_sync(0xFFFFFFFFu, s, o);
        if (lane == 0) invs[i] = 1.0f / s;
    }
    __syncthreads();

    int d = tid & 63, half = tid >> 6;
    float o[16];
    #pragma unroll
    for (int i = 0; i < 16; i++) o[i] = 0.f;
    const float* vbase = d_v + (size_t)(b*Nn)*CS + h*HD + d;
    for (int jc = 0; jc < 96; jc++) {
        int j = half*384 + jc*4;
        float v0 = vbase[(size_t)(j+0)*CS];
        float v1 = vbase[(size_t)(j+1)*CS];
        float v2 = vbase[(size_t)(j+2)*CS];
        float v3 = vbase[(size_t)(j+3)*CS];
        #pragma unroll
        for (int i = 0; i < 16; i++) {
            float4 pp = *(const float4*)(sc + i*SP + j);
            o[i] += pp.x*v0 + pp.y*v1 + pp.z*v2 + pp.w*v3;
        }
    }
    #pragma unroll
    for (int i = 0; i < 16; i++) Osm[(half*16 + i)*64 + d] = o[i];
    __syncthreads();
    if (half == 0) {
        #pragma unroll
        for (int i = 0; i < 16; i++) {
            float val = (Osm[i*64 + d] + Osm[(16 + i)*64 + d]) * invs[i];
            size_t idx = (size_t)(b*Nn + i0 + i)*CS + h*HD + d;
            d_go[idx] = d_g[idx] * val;
        }
    }
}

// ---------------- launch ----------------
extern "C" void kernel_launch(void* const* d_in, const int* in_sizes, int n_in,
                              void* d_out, int out_size)
{
    const float* s    = (const float*)d_in[0];
    const float* z    = (const float*)d_in[1];
    const float* mask = (const float*)d_in[2];
    const float* k_in = (const float*)d_in[3];
    const float* Wq   = (const float*)d_in[4];
    const float* bq   = (const float*)d_in[5];
    const float* Wk   = (const float*)d_in[6];
    const float* Wv   = (const float*)d_in[7];
    const float* Wg   = (const float*)d_in[8];
    const float* ln_g = (const float*)d_in[9];
    const float* ln_b = (const float*)d_in[10];
    const float* Wz   = (const float*)d_in[11];
    const float* Wo   = (const float*)d_in[12];
    float* out = (float*)d_out;

    float *q, *k, *v, *g, *go;
    cudaGetSymbolAddress((void**)&q,  d_q);
    cudaGetSymbolAddress((void**)&k,  d_k);
    cudaGetSymbolAddress((void**)&v,  d_v);
    cudaGetSymbolAddress((void**)&g,  d_g);
    cudaGetSymbolAddress((void**)&go, d_go);

    cudaFuncSetAttribute(mma_gemm<true,  false>, cudaFuncAttributeMaxDynamicSharedMemorySize, GEMM_SMEM);
    cudaFuncSetAttribute(mma_gemm<false, false>, cudaFuncAttributeMaxDynamicSharedMemorySize, GEMM_SMEM);
    cudaFuncSetAttribute(mma_gemm<false, true >, cudaFuncAttributeMaxDynamicSharedMemorySize, GEMM_SMEM);

    dim3 gg(CS/64, MROWS/128);  // (16, 12)
    mma_gemm<true,  false><<<gg, 256, GEMM_SMEM>>>(s,    Wq, bq,      q,  MROWS, CS, CS);
    mma_gemm<false, false><<<gg, 256, GEMM_SMEM>>>(k_in, Wk, nullptr, k,  MROWS, CS, CS);
    mma_gemm<false, false><<<gg, 256, GEMM_SMEM>>>(k_in, Wv, nullptr, v,  MROWS, CS, CS);
    mma_gemm<false, true ><<<gg, 256, GEMM_SMEM>>>(s,    Wg, nullptr, g,  MROWS, CS, CS);

    prep_kernel<<<1, 128>>>(ln_g, ln_b, Wz);
    bias_kernel<<<NPAIR/64, 256>>>(z);

    cudaFuncSetAttribute(attn_kernel, cudaFuncAttributeMaxDynamicSharedMemorySize, 62016);
    attn_kernel<<<dim3(Nn/16, NH, Bn), 128, 62016>>>(mask);

    mma_gemm<false, false><<<gg, 256, GEMM_SMEM>>>(go, Wo, nullptr, out, MROWS, CS, CS);
}

// round 4
// speedup vs baseline: 1.8726x; 1.4764x over previous
#include <cuda_runtime.h>
#include <cuda_bf16.h>
#include <cstdint>
#include <cstddef>

#define Bn 2
#define Nn 768
#define CS 1024
#define CZ 128
#define NH 16
#define HD 64
#define MROWS (Bn*Nn)     // 1536
#define NPAIR (Bn*Nn*Nn)  // 1179648

// ---------------- scratch (device globals; no allocations allowed) ----------------
__device__ float d_q[MROWS*CS];
__device__ float d_k[MROWS*CS];
__device__ float d_v[MROWS*CS];
__device__ float d_g[MROWS*CS];
__device__ float d_go[MROWS*CS];
__device__ float d_bias[Bn*NH*Nn*Nn];     // 75.5 MB
__device__ float d_Gz[CZ*NH];
__device__ float d_Bh[NH];
__device__ float d_GzSum[NH];

// ================= shared bf16 split-precision MMA helpers ====================
__device__ __forceinline__ void ldsm4(uint32_t* r, uint32_t a) {
    asm volatile("ldmatrix.sync.aligned.m8n8.x4.shared.b16 {%0,%1,%2,%3}, [%4];"
                 : "=r"(r[0]), "=r"(r[1]), "=r"(r[2]), "=r"(r[3]) : "r"(a));
}
__device__ __forceinline__ void ldsm4t(uint32_t* r, uint32_t a) {
    asm volatile("ldmatrix.sync.aligned.m8n8.x4.trans.shared.b16 {%0,%1,%2,%3}, [%4];"
                 : "=r"(r[0]), "=r"(r[1]), "=r"(r[2]), "=r"(r[3]) : "r"(a));
}
__device__ __forceinline__ void mma_bf16(float* c, const uint32_t* a, const uint32_t* b) {
    asm volatile("mma.sync.aligned.m16n8k16.row.col.f32.bf16.bf16.f32 "
                 "{%0,%1,%2,%3}, {%4,%5,%6,%7}, {%8,%9}, {%0,%1,%2,%3};"
                 : "+f"(c[0]), "+f"(c[1]), "+f"(c[2]), "+f"(c[3])
                 : "r"(a[0]), "r"(a[1]), "r"(a[2]), "r"(a[3]), "r"(b[0]), "r"(b[1]));
}
__device__ __forceinline__ void split2(float x, float y, uint32_t& hi, uint32_t& lo) {
    __nv_bfloat162 h = __float22bfloat162_rn(make_float2(x, y));
    float2 hf = __bfloat1622float2(h);
    __nv_bfloat162 l = __float22bfloat162_rn(make_float2(x - hf.x, y - hf.y));
    hi = *(uint32_t*)&h;
    lo = *(uint32_t*)&l;
}

// ================= bf16 split-precision tensor-core GEMM (1536x1024x1024) =====
// BM=128, BN=64, BK=32, 256 threads (8 warps), warp tile 32x32.
#define ASTRIDE 40
#define BSTRIDE 72
#define AHI_OFF 0
#define ALO_OFF 10240
#define BHI_OFF 20480
#define BLO_OFF 25088
#define BUFBYTES 29696
#define GEMM_SMEM (2*BUFBYTES)   // 59392

__device__ __forceinline__ void gemm_body(
    const float* __restrict__ A, const float* __restrict__ Bm,
    const float* __restrict__ bias, float* __restrict__ C,
    bool addb, bool sig)
{
    extern __shared__ char sm_raw[];
    uint32_t sbase = (uint32_t)__cvta_generic_to_shared(sm_raw);
    const int N = CS, K = CS;

    int tid = threadIdx.x;
    int wid = tid >> 5, lane = tid & 31;
    int warpM = wid >> 1, warpN = wid & 1;
    int m0 = blockIdx.y * 128, n0 = blockIdx.x * 64;

    int rowA = tid >> 1, halfA = tid & 1;
    int rowB = tid >> 3, colB = (tid & 7) * 8;
    const float* gA = A + (size_t)(m0 + rowA) * K + halfA * 16;
    const float* gB = Bm + (size_t)rowB * N + n0 + colB;

    float acc[2][4][4];
    #pragma unroll
    for (int mt = 0; mt < 2; mt++)
        #pragma unroll
        for (int nt = 0; nt < 4; nt++)
            #pragma unroll
            for (int i = 0; i < 4; i++) acc[mt][nt][i] = 0.f;

    const int CHUNKS = K / 32;
    float4 ra[4], rb[2];

    int matr = lane >> 3, rr = lane & 7;
    int aRowBase = warpM * 32 + (matr & 1) * 8 + rr;
    int aColBase = (matr >> 1) * 8;
    int bRowBase = (matr & 1) * 8 + rr;
    int bColBase = warpN * 32 + (matr >> 1) * 8;

    auto store_chunk = [&](int buf) {
        uint32_t off = buf * BUFBYTES;
        uint32_t* ahi = (uint32_t*)(sm_raw + off + AHI_OFF);
        uint32_t* alo = (uint32_t*)(sm_raw + off + ALO_OFF);
        uint32_t* bhi = (uint32_t*)(sm_raw + off + BHI_OFF);
        uint32_t* blo = (uint32_t*)(sm_raw + off + BLO_OFF);
        #pragma unroll
        for (int q = 0; q < 4; q++) {
            int col = halfA * 16 + q * 4;
            int e0 = (rowA * ASTRIDE + col) >> 1;
            uint32_t h0, l0, h1, l1;
            split2(ra[q].x, ra[q].y, h0, l0);
            split2(ra[q].z, ra[q].w, h1, l1);
            ahi[e0] = h0; ahi[e0 + 1] = h1;
            alo[e0] = l0; alo[e0 + 1] = l1;
        }
        #pragma unroll
        for (int q = 0; q < 2; q++) {
            int col = colB + q * 4;
            int e0 = (rowB * BSTRIDE + col) >> 1;
            uint32_t h0, l0, h1, l1;
            split2(rb[q].x, rb[q].y, h0, l0);
            split2(rb[q].z, rb[q].w, h1, l1);
            bhi[e0] = h0; bhi[e0 + 1] = h1;
            blo[e0] = l0; blo[e0 + 1] = l1;
        }
    };

    #pragma unroll
    for (int q = 0; q < 4; q++) ra[q] = *(const float4*)(gA + q * 4);
    #pragma unroll
    for (int q = 0; q < 2; q++) rb[q] = *(const float4*)(gB + q * 4);
    store_chunk(0);

    for (int c = 0; c < CHUNKS; c++) {
        __syncthreads();
        int buf = c & 1;
        if (c + 1 < CHUNKS) {
            const float* pA = gA + (c + 1) * 32;
            const float* pB = gB + (size_t)(c + 1) * 32 * N;
            #pragma unroll
            for (int q = 0; q < 4; q++) ra[q] = *(const float4*)(pA + q * 4);
            #pragma unroll
            for (int q = 0; q < 2; q++) rb[q] = *(const float4*)(pB + q * 4);
        }

        uint32_t off = sbase + buf * BUFBYTES;
        #pragma unroll
        for (int ks = 0; ks < 32; ks += 16) {
            uint32_t Ah[2][4], Al[2][4], Bh[2][4], Bl[2][4];
            #pragma unroll
            for (int mt = 0; mt < 2; mt++)
                ldsm4(Ah[mt], off + AHI_OFF +
                      (((aRowBase + mt * 16) * ASTRIDE) + aColBase + ks) * 2);
            #pragma unroll
            for (int ntp = 0; ntp < 2; ntp++)
                ldsm4t(Bh[ntp], off + BHI_OFF +
                       (((bRowBase + ks) * BSTRIDE) + bColBase + ntp * 16) * 2);
            #pragma unroll
            for (int mt = 0; mt < 2; mt++)
                #pragma unroll
                for (int nt = 0; nt < 4; nt++)
                    mma_bf16(acc[mt][nt], Ah[mt], &Bh[nt >> 1][(nt & 1) * 2]);

            #pragma unroll
            for (int mt = 0; mt < 2; mt++)
                ldsm4(Al[mt], off + ALO_OFF +
                      (((aRowBase + mt * 16) * ASTRIDE) + aColBase + ks) * 2);
            #pragma unroll
            for (int mt = 0; mt < 2; mt++)
                #pragma unroll
                for (int nt = 0; nt < 4; nt++)
                    mma_bf16(acc[mt][nt], Al[mt], &Bh[nt >> 1][(nt & 1) * 2]);

            #pragma unroll
            for (int ntp = 0; ntp < 2; ntp++)
                ldsm4t(Bl[ntp], off + BLO_OFF +
                       (((bRowBase + ks) * BSTRIDE) + bColBase + ntp * 16) * 2);
            #pragma unroll
            for (int mt = 0; mt < 2; mt++)
                #pragma unroll
                for (int nt = 0; nt < 4; nt++)
                    mma_bf16(acc[mt][nt], Ah[mt], &Bl[nt >> 1][(nt & 1) * 2]);
        }

        if (c + 1 < CHUNKS) store_chunk(buf ^ 1);
    }

    int grp = lane >> 2, tL = lane & 3;
    #pragma unroll
    for (int mt = 0; mt < 2; mt++) {
        #pragma unroll
        for (int nt = 0; nt < 4; nt++) {
            int row = m0 + warpM * 32 + mt * 16 + grp;
            int col = n0 + warpN * 32 + nt * 8 + tL * 2;
            float b0 = 0.f, b1 = 0.f;
            if (addb) { b0 = bias[col]; b1 = bias[col + 1]; }
            float v0 = acc[mt][nt][0] + b0, v1 = acc[mt][nt][1] + b1;
            float v2 = acc[mt][nt][2] + b0, v3 = acc[mt][nt][3] + b1;
            if (sig) {
                v0 = 1.f / (1.f + __expf(-v0));
                v1 = 1.f / (1.f + __expf(-v1));
                v2 = 1.f / (1.f + __expf(-v2));
                v3 = 1.f / (1.f + __expf(-v3));
            }
            *(float2*)(C + (size_t)row * CS + col)       = make_float2(v0, v1);
            *(float2*)(C + (size_t)(row + 8) * CS + col) = make_float2(v2, v3);
        }
    }
}

// one launch for all four projections: z-dim selects {q, k, v, g}
__global__ void __launch_bounds__(256) proj4_kernel(
    const float* __restrict__ s, const float* __restrict__ k_in,
    const float* __restrict__ Wq, const float* __restrict__ bq,
    const float* __restrict__ Wk, const float* __restrict__ Wv,
    const float* __restrict__ Wg)
{
    int which = blockIdx.z;
    const float* A = (which == 0 || which == 3) ? s : k_in;
    const float* B = which == 0 ? Wq : which == 1 ? Wk : which == 2 ? Wv : Wg;
    float* C = which == 0 ? d_q : which == 1 ? d_k : which == 2 ? d_v : d_g;
    gemm_body(A, B, bq, C, which == 0, which == 3);
}

__global__ void __launch_bounds__(256) final_gemm(const float* __restrict__ Wo,
                                                  float* __restrict__ out)
{
    gemm_body(d_go, Wo, nullptr, out, false, false);
}

// ---------------- fold LN affine into z-projection ----------------
__global__ void prep_kernel(const float* __restrict__ ln_g,
                            const float* __restrict__ ln_b,
                            const float* __restrict__ Wz)
{
    __shared__ float sB[CZ*NH];
    __shared__ float sG[CZ*NH];
    int c = threadIdx.x;
    float g = ln_g[c], bb = ln_b[c];
    #pragma unroll
    for (int h = 0; h < NH; h++) {
        float w = Wz[c*NH + h];
        float gz = g*w;
        d_Gz[c*NH + h] = gz;
        sG[c*NH + h] = gz;
        sB[c*NH + h] = bb*w;
    }
    __syncthreads();
    if (c < NH) {
        float sb = 0.f, sg = 0.f;
        for (int cc = 0; cc < CZ; cc++) { sb += sB[cc*NH + c]; sg += sG[cc*NH + c]; }
        d_Bh[c] = sb;
        d_GzSum[c] = sg;
    }
}

// ---------------- fused LayerNorm + projection -> bias[b][h][i][j] ----------------
__global__ void __launch_bounds__(256) bias_kernel(const float* __restrict__ z)
{
    __shared__ float GzS[CZ*24];
    __shared__ float BhS[NH], GzSumS[NH];
    __shared__ float stage[64*17];

    int tid = threadIdx.x;
    for (int t = tid; t < CZ*NH; t += 256) {
        int c = t >> 4, h = t & 15;
        GzS[c*24 + h] = d_Gz[t];
    }
    if (tid < NH) { BhS[tid] = d_Bh[tid]; GzSumS[tid] = d_GzSum[tid]; }
    __syncthreads();

    int r = tid >> 2;
    int lane4 = tid & 3;
    int p = blockIdx.x * 64 + r;
    const float* zr = z + (size_t)p * CZ;

    float s1 = 0.f, s2 = 0.f;
    float dots[16];
    #pragma unroll
    for (int t = 0; t < 16; t++) dots[t] = 0.f;

    #pragma unroll 8
    for (int i = 0; i < 32; i++) {
        int c = lane4 + 4*i;
        float zv = __ldg(zr + c);
        s1 += zv; s2 += zv*zv;
        const float4* grow = (const float4*)(GzS + c*24);
        float4 g0 = grow[0], g1 = grow[1], g2 = grow[2], g3 = grow[3];
        dots[0]  += zv*g0.x; dots[1]  += zv*g0.y; dots[2]  += zv*g0.z; dots[3]  += zv*g0.w;
        dots[4]  += zv*g1.x; dots[5]  += zv*g1.y; dots[6]  += zv*g1.z; dots[7]  += zv*g1.w;
        dots[8]  += zv*g2.x; dots[9]  += zv*g2.y; dots[10] += zv*g2.z; dots[11] += zv*g2.w;
        dots[12] += zv*g3.x; dots[13] += zv*g3.y; dots[14] += zv*g3.z; dots[15] += zv*g3.w;
    }
    #pragma unroll
    for (int off = 1; off <= 2; off <<= 1) {
        s1 += __shfl_xor_sync(0xFFFFFFFFu, s1, off);
        s2 += __shfl_xor_sync(0xFFFFFFFFu, s2, off);
        #pragma unroll
        for (int t = 0; t < 16; t++)
            dots[t] += __shfl_xor_sync(0xFFFFFFFFu, dots[t], off);
    }
    if (lane4 == 0) {
        float mu  = s1 * (1.f/128.f);
        float var = s2 * (1.f/128.f) - mu*mu;
        float rstd = rsqrtf(var + 1e-5f);
        float* st = stage + r*17;
        #pragma unroll
        for (int h = 0; h < NH; h++)
            st[h] = rstd*(dots[h] - mu*GzSumS[h]) + BhS[h];
    }
    __syncthreads();

    int p0  = blockIdx.x * 64;
    int b   = p0 / (Nn*Nn);
    int rem = p0 % (Nn*Nn);
    int ii  = rem / Nn;
    int j0  = rem % Nn;
    for (int t = tid; t < 64*NH; t += 256) {
        int h = t >> 6, rr2 = t & 63;
        d_bias[((size_t)(b*NH + h)*Nn + ii)*Nn + j0 + rr2] = stage[rr2*17 + h];
    }
}

// ========== tensor-core flash attention: block per (b, h, 64-row i-tile) ==========
// 256 threads (8 warps): warpM = wid>>1 (16-row group), warpN = wid&1 (32-col j half).
// 3-term split bf16 MMA for both QK^T and P·V. Online softmax, per-warp partials.
#define AT_STRIDE 72
#define QH_OFF 0
#define QL_OFF 9216
#define KH_OFF 18432
#define KL_OFF 27648
#define VH_OFF 36864
#define VL_OFF 46080
#define OSM_OFF 18432
#define OSM_STRIDE 68
#define STAT_OFF (OSM_OFF + 8*16*OSM_STRIDE*4)   // 53248
#define ATT_SMEM 55296

__global__ void __launch_bounds__(256, 2) attn_mma(const float* __restrict__ mask)
{
    extern __shared__ char smraw[];
    uint32_t sb = (uint32_t)__cvta_generic_to_shared(smraw);
    int tid = threadIdx.x, lane = tid & 31, wid = tid >> 5;
    int warpM = wid >> 1, warpN = wid & 1;
    int b = blockIdx.z, h = blockIdx.y, i0 = blockIdx.x * 64;
    int grp = lane >> 2, tL = lane & 3;
    int t8 = lane >> 3, r8 = lane & 7;

    int lrow = tid >> 2, lcol = (tid & 3) * 16;

    // ---- load Q tile (pre-scaled by 1/8 = exact), split into Qh/Ql ----
    {
        const float* src = d_q + (size_t)(b*Nn + i0 + lrow)*CS + h*HD + lcol;
        uint32_t* qh = (uint32_t*)(smraw + QH_OFF);
        uint32_t* ql = (uint32_t*)(smraw + QL_OFF);
        #pragma unroll
        for (int qq = 0; qq < 4; qq++) {
            float4 vv = *(const float4*)(src + qq*4);
            int e0 = (lrow*AT_STRIDE + lcol + qq*4) >> 1;
            uint32_t h0, l0, h1, l1;
            split2(vv.x*0.125f, vv.y*0.125f, h0, l0);
            split2(vv.z*0.125f, vv.w*0.125f, h1, l1);
            qh[e0] = h0; qh[e0+1] = h1;
            ql[e0] = l0; ql[e0+1] = l1;
        }
    }

    float Oa[8][4];
    #pragma unroll
    for (int t = 0; t < 8; t++) { Oa[t][0]=0.f; Oa[t][1]=0.f; Oa[t][2]=0.f; Oa[t][3]=0.f; }
    float mrow0 = -1e30f, mrow1 = -1e30f, lsum0 = 0.f, lsum1 = 0.f;

    const float* maskp = mask + b*Nn;
    const float* biasbase = d_bias + ((size_t)(b*NH + h)*Nn + (i0 + warpM*16 + grp))*Nn;

    // ldmatrix lane-address components
    int aRow  = warpM*16 + (t8 & 1)*8 + r8;    // Q rows; col += kk*16
    int aCol  = (t8 >> 1)*8;
    int kRowB = warpN*32 + (t8 >> 1)*8 + r8;   // K n-rows (+ ntp*16)
    int kColB = (t8 & 1)*8;                    // (+ kk*16)
    int vRowB = (t8 & 1)*8 + r8;               // V k-rows (+ kbase)
    int vColB = (t8 >> 1)*8;                   // (+ ntp*16)

    #pragma unroll 1
    for (int jt = 0; jt < 12; jt++) {
        int j0c = jt * 64;
        const float* ksrc = d_k + (size_t)(b*Nn + j0c + lrow)*CS + h*HD + lcol;
        const float* vsrc = d_v + (size_t)(b*Nn + j0c + lrow)*CS + h*HD + lcol;
        float4 kr[4], vr[4];
        #pragma unroll
        for (int qq = 0; qq < 4; qq++) {
            kr[qq] = *(const float4*)(ksrc + qq*4);
            vr[qq] = *(const float4*)(vsrc + qq*4);
        }
        __syncthreads();   // prev iteration's MMA reads done
        {
            uint32_t* kh = (uint32_t*)(smraw + KH_OFF);
            uint32_t* kl = (uint32_t*)(smraw + KL_OFF);
            uint32_t* vh = (uint32_t*)(smraw + VH_OFF);
            uint32_t* vl = (uint32_t*)(smraw + VL_OFF);
            #pragma unroll
            for (int qq = 0; qq < 4; qq++) {
                int e0 = (lrow*AT_STRIDE + lcol + qq*4) >> 1;
                uint32_t h0, l0, h1, l1;
                split2(kr[qq].x, kr[qq].y, h0, l0);
                split2(kr[qq].z, kr[qq].w, h1, l1);
                kh[e0] = h0; kh[e0+1] = h1; kl[e0] = l0; kl[e0+1] = l1;
                split2(vr[qq].x, vr[qq].y, h0, l0);
                split2(vr[qq].z, vr[qq].w, h1, l1);
                vh[e0] = h0; vh[e0+1] = h1; vl[e0] = l0; vl[e0+1] = l1;
            }
        }
        __syncthreads();   // tiles ready

        // ---- S = (Q/8) . K^T  (3-term split) ----
        float S[4][4];
        #pragma unroll
        for (int nt = 0; nt < 4; nt++) { S[nt][0]=0.f; S[nt][1]=0.f; S[nt][2]=0.f; S[nt][3]=0.f; }
        #pragma unroll
        for (int kk = 0; kk < 4; kk++) {
            uint32_t qh_[4], ql_[4], khf[2][4], klf[2][4];
            uint32_t aoff = (uint32_t)((aRow*AT_STRIDE + kk*16 + aCol) * 2);
            ldsm4(qh_, sb + QH_OFF + aoff);
            ldsm4(ql_, sb + QL_OFF + aoff);
            uint32_t koff0 = (uint32_t)((kRowB*AT_STRIDE + kk*16 + kColB) * 2);
            uint32_t koff1 = (uint32_t)(((kRowB+16)*AT_STRIDE + kk*16 + kColB) * 2);
            ldsm4(khf[0], sb + KH_OFF + koff0);
            ldsm4(khf[1], sb + KH_OFF + koff1);
            #pragma unroll
            for (int nt = 0; nt < 4; nt++)
                mma_bf16(S[nt], qh_, &khf[nt >> 1][(nt & 1)*2]);
            #pragma unroll
            for (int nt = 0; nt < 4; nt++)
                mma_bf16(S[nt], ql_, &khf[nt >> 1][(nt & 1)*2]);
            ldsm4(klf[0], sb + KL_OFF + koff0);
            ldsm4(klf[1], sb + KL_OFF + koff1);
            #pragma unroll
            for (int nt = 0; nt < 4; nt++)
                mma_bf16(S[nt], qh_, &klf[nt >> 1][(nt & 1)*2]);
        }

        // ---- + bias + mask ----
        #pragma unroll
        for (int nt = 0; nt < 4; nt++) {
            int jc = j0c + warpN*32 + nt*8 + tL*2;
            float2 b0 = *(const float2*)(biasbase + jc);
            float2 b1 = *(const float2*)(biasbase + (size_t)8*Nn + jc);
            float2 mv = *(const float2*)(maskp + jc);
            float mk0 = (1.f - mv.x) * (-1000000.0f);
            float mk1 = (1.f - mv.y) * (-1000000.0f);
            S[nt][0] += b0.x + mk0; S[nt][1] += b0.y + mk1;
            S[nt][2] += b1.x + mk0; S[nt][3] += b1.y + mk1;
        }

        // ---- online softmax update ----
        float cm0 = fmaxf(fmaxf(S[0][0], S[0][1]), fmaxf(S[1][0], S[1][1]));
        cm0 = fmaxf(cm0, fmaxf(fmaxf(S[2][0], S[2][1]), fmaxf(S[3][0], S[3][1])));
        float cm1 = fmaxf(fmaxf(S[0][2], S[0][3]), fmaxf(S[1][2], S[1][3]));
        cm1 = fmaxf(cm1, fmaxf(fmaxf(S[2][2], S[2][3]), fmaxf(S[3][2], S[3][3])));
        cm0 = fmaxf(cm0, __shfl_xor_sync(0xFFFFFFFFu, cm0, 1));
        cm0 = fmaxf(cm0, __shfl_xor_sync(0xFFFFFFFFu, cm0, 2));
        cm1 = fmaxf(cm1, __shfl_xor_sync(0xFFFFFFFFu, cm1, 1));
        cm1 = fmaxf(cm1, __shfl_xor_sync(0xFFFFFFFFu, cm1, 2));
        float mn0 = fmaxf(mrow0, cm0), mn1 = fmaxf(mrow1, cm1);
        float sc0 = __expf(mrow0 - mn0), sc1 = __expf(mrow1 - mn1);
        mrow0 = mn0; mrow1 = mn1;
        float rs0 = 0.f, rs1 = 0.f;
        #pragma unroll
        for (int nt = 0; nt < 4; nt++) {
            S[nt][0] = __expf(S[nt][0] - mn0);
            S[nt][1] = __expf(S[nt][1] - mn0);
            S[nt][2] = __expf(S[nt][2] - mn1);
            S[nt][3] = __expf(S[nt][3] - mn1);
            rs0 += S[nt][0] + S[nt][1];
            rs1 += S[nt][2] + S[nt][3];
        }
        rs0 += __shfl_xor_sync(0xFFFFFFFFu, rs0, 1);
        rs0 += __shfl_xor_sync(0xFFFFFFFFu, rs0, 2);
        rs1 += __shfl_xor_sync(0xFFFFFFFFu, rs1, 1);
        rs1 += __shfl_xor_sync(0xFFFFFFFFu, rs1, 2);
        lsum0 = lsum0*sc0 + rs0;
        lsum1 = lsum1*sc1 + rs1;
        #pragma unroll
        for (int t = 0; t < 8; t++) {
            Oa[t][0] *= sc0; Oa[t][1] *= sc0;
            Oa[t][2] *= sc1; Oa[t][3] *= sc1;
        }

        // ---- P fragments (split) ----
        uint32_t Ph[2][4], Pl[2][4];
        #pragma unroll
        for (int kf = 0; kf < 2; kf++) {
            split2(S[2*kf][0],   S[2*kf][1],   Ph[kf][0], Pl[kf][0]);
            split2(S[2*kf][2],   S[2*kf][3],   Ph[kf][1], Pl[kf][1]);
            split2(S[2*kf+1][0], S[2*kf+1][1], Ph[kf][2], Pl[kf][2]);
            split2(S[2*kf+1][2], S[2*kf+1][3], Ph[kf][3], Pl[kf][3]);
        }

        // ---- O += P . V  (3-term split) ----
        #pragma unroll
        for (int kf = 0; kf < 2; kf++) {
            int kb = warpN*32 + kf*16;
            #pragma unroll
            for (int ntp = 0; ntp < 4; ntp++) {
                uint32_t vhf[4], vlf[4];
                uint32_t voff = (uint32_t)(((kb + vRowB)*AT_STRIDE + ntp*16 + vColB) * 2);
                ldsm4t(vhf, sb + VH_OFF + voff);
                ldsm4t(vlf, sb + VL_OFF + voff);
                mma_bf16(Oa[ntp*2],   Ph[kf], &vhf[0]);
                mma_bf16(Oa[ntp*2+1], Ph[kf], &vhf[2]);
                mma_bf16(Oa[ntp*2],   Pl[kf], &vhf[0]);
                mma_bf16(Oa[ntp*2+1], Pl[kf], &vhf[2]);
                mma_bf16(Oa[ntp*2],   Ph[kf], &vlf[0]);
                mma_bf16(Oa[ntp*2+1], Ph[kf], &vlf[2]);
            }
        }
    }

    // ---- combine the two warpN partials per row, apply gate, write ----
    __syncthreads();
    float* Osm  = (float*)(smraw + OSM_OFF);
    float* stat = (float*)(smraw + STAT_OFF);
    #pragma unroll
    for (int t = 0; t < 8; t++) {
        int dcol = t*8 + tL*2;
        Osm[(wid*16 + grp)*OSM_STRIDE + dcol]       = Oa[t][0];
        Osm[(wid*16 + grp)*OSM_STRIDE + dcol + 1]   = Oa[t][1];
        Osm[(wid*16 + grp+8)*OSM_STRIDE + dcol]     = Oa[t][2];
        Osm[(wid*16 + grp+8)*OSM_STRIDE + dcol + 1] = Oa[t][3];
    }
    if (tL == 0) {
        stat[wid*32 + grp*2]       = mrow0;
        stat[wid*32 + grp*2 + 1]   = lsum0;
        stat[wid*32 + (grp+8)*2]     = mrow1;
        stat[wid*32 + (grp+8)*2 + 1] = lsum1;
    }
    __syncthreads();

    for (int t = tid; t < 64*64; t += 256) {
        int row = t >> 6, d = t & 63;
        int w0 = (row >> 4)*2, rl = row & 15;
        float m0 = stat[w0*32 + rl*2],     l0 = stat[w0*32 + rl*2 + 1];
        float m1 = stat[(w0+1)*32 + rl*2], l1 = stat[(w0+1)*32 + rl*2 + 1];
        float mm = fmaxf(m0, m1);
        float a0 = __expf(m0 - mm), a1 = __expf(m1 - mm);
        float oo = (a0*Osm[(w0*16 + rl)*OSM_STRIDE + d] +
                    a1*Osm[((w0+1)*16 + rl)*OSM_STRIDE + d]) / (a0*l0 + a1*l1);
        size_t gi = (size_t)(b*Nn + i0 + row)*CS + h*HD + d;
        d_go[gi] = d_g[gi] * oo;
    }
}

// ---------------- launch ----------------
extern "C" void kernel_launch(void* const* d_in, const int* in_sizes, int n_in,
                              void* d_out, int out_size)
{
    const float* s    = (const float*)d_in[0];
    const float* z    = (const float*)d_in[1];
    const float* mask = (const float*)d_in[2];
    const float* k_in = (const float*)d_in[3];
    const float* Wq   = (const float*)d_in[4];
    const float* bq   = (const float*)d_in[5];
    const float* Wk   = (const float*)d_in[6];
    const float* Wv   = (const float*)d_in[7];
    const float* Wg   = (const float*)d_in[8];
    const float* ln_g = (const float*)d_in[9];
    const float* ln_b = (const float*)d_in[10];
    const float* Wz   = (const float*)d_in[11];
    const float* Wo   = (const float*)d_in[12];
    float* out = (float*)d_out;

    cudaFuncSetAttribute(proj4_kernel, cudaFuncAttributeMaxDynamicSharedMemorySize, GEMM_SMEM);
    cudaFuncSetAttribute(final_gemm,   cudaFuncAttributeMaxDynamicSharedMemorySize, GEMM_SMEM);
    cudaFuncSetAttribute(attn_mma,     cudaFuncAttributeMaxDynamicSharedMemorySize, ATT_SMEM);

    proj4_kernel<<<dim3(CS/64, MROWS/128, 4), 256, GEMM_SMEM>>>(s, k_in, Wq, bq, Wk, Wv, Wg);

    prep_kernel<<<1, 128>>>(ln_g, ln_b, Wz);
    bias_kernel<<<NPAIR/64, 256>>>(z);

    attn_mma<<<dim3(Nn/64, NH, Bn), 256, ATT_SMEM>>>(mask);

    final_gemm<<<dim3(CS/64, MROWS/128), 256, GEMM_SMEM>>>(Wo, out);
}

// round 5
// speedup vs baseline: 2.2388x; 1.1956x over previous
#include <cuda_runtime.h>
#include <cuda_bf16.h>
#include <cstdint>
#include <cstddef>

#define Bn 2
#define Nn 768
#define CS 1024
#define CZ 128
#define NH 16
#define HD 64
#define MROWS (Bn*Nn)     // 1536
#define NPAIR (Bn*Nn*Nn)  // 1179648

// ---------------- scratch (device globals; no allocations allowed) ----------------
__device__ float d_q[MROWS*CS];
__device__ float d_k[MROWS*CS];
__device__ float d_v[MROWS*CS];
__device__ float d_g[MROWS*CS];
__device__ float d_go[MROWS*CS];
__device__ float d_bias[Bn*NH*Nn*Nn];     // 75.5 MB
__device__ float d_Gz[CZ*NH];
__device__ float d_Bh[NH];
__device__ float d_GzSum[NH];

// ================= shared bf16 split-precision MMA helpers ====================
__device__ __forceinline__ void ldsm4(uint32_t* r, uint32_t a) {
    asm volatile("ldmatrix.sync.aligned.m8n8.x4.shared.b16 {%0,%1,%2,%3}, [%4];"
                 : "=r"(r[0]), "=r"(r[1]), "=r"(r[2]), "=r"(r[3]) : "r"(a));
}
__device__ __forceinline__ void ldsm4t(uint32_t* r, uint32_t a) {
    asm volatile("ldmatrix.sync.aligned.m8n8.x4.trans.shared.b16 {%0,%1,%2,%3}, [%4];"
                 : "=r"(r[0]), "=r"(r[1]), "=r"(r[2]), "=r"(r[3]) : "r"(a));
}
__device__ __forceinline__ void mma_bf16(float* c, const uint32_t* a, const uint32_t* b) {
    asm volatile("mma.sync.aligned.m16n8k16.row.col.f32.bf16.bf16.f32 "
                 "{%0,%1,%2,%3}, {%4,%5,%6,%7}, {%8,%9}, {%0,%1,%2,%3};"
                 : "+f"(c[0]), "+f"(c[1]), "+f"(c[2]), "+f"(c[3])
                 : "r"(a[0]), "r"(a[1]), "r"(a[2]), "r"(a[3]), "r"(b[0]), "r"(b[1]));
}
__device__ __forceinline__ void split2(float x, float y, uint32_t& hi, uint32_t& lo) {
    __nv_bfloat162 h = __float22bfloat162_rn(make_float2(x, y));
    float2 hf = __bfloat1622float2(h);
    __nv_bfloat162 l = __float22bfloat162_rn(make_float2(x - hf.x, y - hf.y));
    hi = *(uint32_t*)&h;
    lo = *(uint32_t*)&l;
}

// ================= bf16 split-precision tensor-core GEMM (1536x1024x1024) =====
#define ASTRIDE 40
#define BSTRIDE 72
#define AHI_OFF 0
#define ALO_OFF 10240
#define BHI_OFF 20480
#define BLO_OFF 25088
#define BUFBYTES 29696
#define GEMM_SMEM (2*BUFBYTES)   // 59392

__device__ __forceinline__ void gemm_body(
    const float* __restrict__ A, const float* __restrict__ Bm,
    const float* __restrict__ bias, float* __restrict__ C,
    bool addb, bool sig)
{
    extern __shared__ char sm_raw[];
    uint32_t sbase = (uint32_t)__cvta_generic_to_shared(sm_raw);
    const int N = CS, K = CS;

    int tid = threadIdx.x;
    int wid = tid >> 5, lane = tid & 31;
    int warpM = wid >> 1, warpN = wid & 1;
    int m0 = blockIdx.y * 128, n0 = blockIdx.x * 64;

    int rowA = tid >> 1, halfA = tid & 1;
    int rowB = tid >> 3, colB = (tid & 7) * 8;
    const float* gA = A + (size_t)(m0 + rowA) * K + halfA * 16;
    const float* gB = Bm + (size_t)rowB * N + n0 + colB;

    float acc[2][4][4];
    #pragma unroll
    for (int mt = 0; mt < 2; mt++)
        #pragma unroll
        for (int nt = 0; nt < 4; nt++)
            #pragma unroll
            for (int i = 0; i < 4; i++) acc[mt][nt][i] = 0.f;

    const int CHUNKS = K / 32;
    float4 ra[4], rb[2];

    int matr = lane >> 3, rr = lane & 7;
    int aRowBase = warpM * 32 + (matr & 1) * 8 + rr;
    int aColBase = (matr >> 1) * 8;
    int bRowBase = (matr & 1) * 8 + rr;
    int bColBase = warpN * 32 + (matr >> 1) * 8;

    auto store_chunk = [&](int buf) {
        uint32_t off = buf * BUFBYTES;
        uint32_t* ahi = (uint32_t*)(sm_raw + off + AHI_OFF);
        uint32_t* alo = (uint32_t*)(sm_raw + off + ALO_OFF);
        uint32_t* bhi = (uint32_t*)(sm_raw + off + BHI_OFF);
        uint32_t* blo = (uint32_t*)(sm_raw + off + BLO_OFF);
        #pragma unroll
        for (int q = 0; q < 4; q++) {
            int col = halfA * 16 + q * 4;
            int e0 = (rowA * ASTRIDE + col) >> 1;
            uint32_t h0, l0, h1, l1;
            split2(ra[q].x, ra[q].y, h0, l0);
            split2(ra[q].z, ra[q].w, h1, l1);
            ahi[e0] = h0; ahi[e0 + 1] = h1;
            alo[e0] = l0; alo[e0 + 1] = l1;
        }
        #pragma unroll
        for (int q = 0; q < 2; q++) {
            int col = colB + q * 4;
            int e0 = (rowB * BSTRIDE + col) >> 1;
            uint32_t h0, l0, h1, l1;
            split2(rb[q].x, rb[q].y, h0, l0);
            split2(rb[q].z, rb[q].w, h1, l1);
            bhi[e0] = h0; bhi[e0 + 1] = h1;
            blo[e0] = l0; blo[e0 + 1] = l1;
        }
    };

    #pragma unroll
    for (int q = 0; q < 4; q++) ra[q] = *(const float4*)(gA + q * 4);
    #pragma unroll
    for (int q = 0; q < 2; q++) rb[q] = *(const float4*)(gB + q * 4);
    store_chunk(0);

    for (int c = 0; c < CHUNKS; c++) {
        __syncthreads();
        int buf = c & 1;
        if (c + 1 < CHUNKS) {
            const float* pA = gA + (c + 1) * 32;
            const float* pB = gB + (size_t)(c + 1) * 32 * N;
            #pragma unroll
            for (int q = 0; q < 4; q++) ra[q] = *(const float4*)(pA + q * 4);
            #pragma unroll
            for (int q = 0; q < 2; q++) rb[q] = *(const float4*)(pB + q * 4);
        }

        uint32_t off = sbase + buf * BUFBYTES;
        #pragma unroll
        for (int ks = 0; ks < 32; ks += 16) {
            uint32_t Ah[2][4], Al[2][4], Bh[2][4], Bl[2][4];
            #pragma unroll
            for (int mt = 0; mt < 2; mt++)
                ldsm4(Ah[mt], off + AHI_OFF +
                      (((aRowBase + mt * 16) * ASTRIDE) + aColBase + ks) * 2);
            #pragma unroll
            for (int ntp = 0; ntp < 2; ntp++)
                ldsm4t(Bh[ntp], off + BHI_OFF +
                       (((bRowBase + ks) * BSTRIDE) + bColBase + ntp * 16) * 2);
            #pragma unroll
            for (int mt = 0; mt < 2; mt++)
                #pragma unroll
                for (int nt = 0; nt < 4; nt++)
                    mma_bf16(acc[mt][nt], Ah[mt], &Bh[nt >> 1][(nt & 1) * 2]);

            #pragma unroll
            for (int mt = 0; mt < 2; mt++)
                ldsm4(Al[mt], off + ALO_OFF +
                      (((aRowBase + mt * 16) * ASTRIDE) + aColBase + ks) * 2);
            #pragma unroll
            for (int mt = 0; mt < 2; mt++)
                #pragma unroll
                for (int nt = 0; nt < 4; nt++)
                    mma_bf16(acc[mt][nt], Al[mt], &Bh[nt >> 1][(nt & 1) * 2]);

            #pragma unroll
            for (int ntp = 0; ntp < 2; ntp++)
                ldsm4t(Bl[ntp], off + BLO_OFF +
                       (((bRowBase + ks) * BSTRIDE) + bColBase + ntp * 16) * 2);
            #pragma unroll
            for (int mt = 0; mt < 2; mt++)
                #pragma unroll
                for (int nt = 0; nt < 4; nt++)
                    mma_bf16(acc[mt][nt], Ah[mt], &Bl[nt >> 1][(nt & 1) * 2]);
        }

        if (c + 1 < CHUNKS) store_chunk(buf ^ 1);
    }

    int grp = lane >> 2, tL = lane & 3;
    #pragma unroll
    for (int mt = 0; mt < 2; mt++) {
        #pragma unroll
        for (int nt = 0; nt < 4; nt++) {
            int row = m0 + warpM * 32 + mt * 16 + grp;
            int col = n0 + warpN * 32 + nt * 8 + tL * 2;
            float b0 = 0.f, b1 = 0.f;
            if (addb) { b0 = bias[col]; b1 = bias[col + 1]; }
            float v0 = acc[mt][nt][0] + b0, v1 = acc[mt][nt][1] + b1;
            float v2 = acc[mt][nt][2] + b0, v3 = acc[mt][nt][3] + b1;
            if (sig) {
                v0 = 1.f / (1.f + __expf(-v0));
                v1 = 1.f / (1.f + __expf(-v1));
                v2 = 1.f / (1.f + __expf(-v2));
                v3 = 1.f / (1.f + __expf(-v3));
            }
            *(float2*)(C + (size_t)row * CS + col)       = make_float2(v0, v1);
            *(float2*)(C + (size_t)(row + 8) * CS + col) = make_float2(v2, v3);
        }
    }
}

__global__ void __launch_bounds__(256) proj4_kernel(
    const float* __restrict__ s, const float* __restrict__ k_in,
    const float* __restrict__ Wq, const float* __restrict__ bq,
    const float* __restrict__ Wk, const float* __restrict__ Wv,
    const float* __restrict__ Wg)
{
    int which = blockIdx.z;
    const float* A = (which == 0 || which == 3) ? s : k_in;
    const float* B = which == 0 ? Wq : which == 1 ? Wk : which == 2 ? Wv : Wg;
    float* C = which == 0 ? d_q : which == 1 ? d_k : which == 2 ? d_v : d_g;
    gemm_body(A, B, bq, C, which == 0, which == 3);
}

__global__ void __launch_bounds__(256) final_gemm(const float* __restrict__ Wo,
                                                  float* __restrict__ out)
{
    gemm_body(d_go, Wo, nullptr, out, false, false);
}

// ---------------- fold LN affine into z-projection ----------------
__global__ void prep_kernel(const float* __restrict__ ln_g,
                            const float* __restrict__ ln_b,
                            const float* __restrict__ Wz)
{
    __shared__ float sB[CZ*NH];
    __shared__ float sG[CZ*NH];
    int c = threadIdx.x;
    float g = ln_g[c], bb = ln_b[c];
    #pragma unroll
    for (int h = 0; h < NH; h++) {
        float w = Wz[c*NH + h];
        float gz = g*w;
        d_Gz[c*NH + h] = gz;
        sG[c*NH + h] = gz;
        sB[c*NH + h] = bb*w;
    }
    __syncthreads();
    if (c < NH) {
        float sb = 0.f, sg = 0.f;
        for (int cc = 0; cc < CZ; cc++) { sb += sB[cc*NH + c]; sg += sG[cc*NH + c]; }
        d_Bh[c] = sb;
        d_GzSum[c] = sg;
    }
}

// ====== bias: LN+proj as tensor-core GEMM.  bias = rstd*(z.Gz - mu*GzSum) + Bh ======
// Block: 128 pair-rows (one (b,i), 128 consecutive j), 256 threads, 8 warps x 16 rows.
#define ZROW 136                 // bf16 elems per z smem row (128 + 8 pad)
#define BZ_ZH 0
#define BZ_ZL 34816              // 128*136*2
#define BZ_GH 69632
#define BZ_GL 75776              // +128*24*2
#define BZ_ST 81920              // stats float2[128]
#define BZ_SG 82944              // stage float[128*17]
#define BIAS_SMEM 91648

__global__ void __launch_bounds__(256) bias_mma(const float* __restrict__ z)
{
    extern __shared__ char smraw[];
    uint32_t sb = (uint32_t)__cvta_generic_to_shared(smraw);
    int tid = threadIdx.x, lane = tid & 31, wid = tid >> 5;

    // ---- stage Gz (fp32 -> split bf16), rows c=128, cols h=16, stride 24 ----
    for (int t = tid; t < CZ*NH; t += 256) {
        int c = t >> 4, h = t & 15;
        float w = d_Gz[t];
        __nv_bfloat16 hi = __float2bfloat16(w);
        __nv_bfloat16 lo = __float2bfloat16(w - __bfloat162float(hi));
        ((__nv_bfloat16*)(smraw + BZ_GH))[c*24 + h] = hi;
        ((__nv_bfloat16*)(smraw + BZ_GL))[c*24 + h] = lo;
    }

    // ---- load z tile: 128 rows x 128 ch, coalesced; stats inline ----
    int row = tid >> 1, half = tid & 1;
    {
        const float* zr = z + (size_t)(blockIdx.x*128 + row)*CZ + half*64;
        uint32_t* zh = (uint32_t*)(smraw + BZ_ZH);
        uint32_t* zl = (uint32_t*)(smraw + BZ_ZL);
        float s1 = 0.f, s2 = 0.f;
        #pragma unroll
        for (int f = 0; f < 16; f++) {
            float4 v = *(const float4*)(zr + f*4);
            s1 += (v.x + v.y) + (v.z + v.w);
            s2 = fmaf(v.x, v.x, s2); s2 = fmaf(v.y, v.y, s2);
            s2 = fmaf(v.z, v.z, s2); s2 = fmaf(v.w, v.w, s2);
            uint32_t h0, l0, h1, l1;
            split2(v.x, v.y, h0, l0);
            split2(v.z, v.w, h1, l1);
            int e0 = (row*ZROW + half*64 + f*4) >> 1;
            zh[e0] = h0; zh[e0+1] = h1;
            zl[e0] = l0; zl[e0+1] = l1;
        }
        s1 += __shfl_xor_sync(0xFFFFFFFFu, s1, 1);
        s2 += __shfl_xor_sync(0xFFFFFFFFu, s2, 1);
        if (half == 0) {
            float mu  = s1 * (1.f/128.f);
            float var = s2 * (1.f/128.f) - mu*mu;
            ((float2*)(smraw + BZ_ST))[row] = make_float2(mu, rsqrtf(var + 1e-5f));
        }
    }
    __syncthreads();

    // ---- MMA: warp w -> rows w*16..w*16+15; dots[16 heads] ----
    int t8 = lane >> 3, r8 = lane & 7;
    int aRow = wid*16 + (t8 & 1)*8 + r8;
    int aCol = (t8 >> 1)*8;
    int gRow = (t8 & 1)*8 + r8;
    int gCol = (t8 >> 1)*8;

    float acc0[4] = {0.f,0.f,0.f,0.f}, acc1[4] = {0.f,0.f,0.f,0.f};
    #pragma unroll
    for (int kc = 0; kc < 8; kc++) {
        uint32_t Ah[4], Al[4], Gh[4], Gl[4];
        uint32_t aoff = (uint32_t)((aRow*ZROW + kc*16 + aCol) * 2);
        uint32_t goff = (uint32_t)(((gRow + kc*16)*24 + gCol) * 2);
        ldsm4(Ah, sb + BZ_ZH + aoff);
        ldsm4(Al, sb + BZ_ZL + aoff);
        ldsm4t(Gh, sb + BZ_GH + goff);
        ldsm4t(Gl, sb + BZ_GL + goff);
        mma_bf16(acc0, Ah, &Gh[0]); mma_bf16(acc1, Ah, &Gh[2]);
        mma_bf16(acc0, Al, &Gh[0]); mma_bf16(acc1, Al, &Gh[2]);
        mma_bf16(acc0, Ah, &Gl[0]); mma_bf16(acc1, Ah, &Gl[2]);
    }

    // ---- affine epilogue into stage[row][h] ----
    {
        int grp = lane >> 2, tL = lane & 3;
        int r0 = wid*16 + grp, r1 = r0 + 8;
        float2 st0 = ((float2*)(smraw + BZ_ST))[r0];
        float2 st1 = ((float2*)(smraw + BZ_ST))[r1];
        float* stage = (float*)(smraw + BZ_SG);
        #pragma unroll
        for (int n = 0; n < 2; n++) {
            float* a = n ? acc1 : acc0;
            int h = n*8 + tL*2;
            float gs0 = d_GzSum[h], gs1 = d_GzSum[h+1];
            float bh0 = d_Bh[h],    bh1 = d_Bh[h+1];
            stage[r0*17 + h]     = st0.y*(a[0] - st0.x*gs0) + bh0;
            stage[r0*17 + h + 1] = st0.y*(a[1] - st0.x*gs1) + bh1;
            stage[r1*17 + h]     = st1.y*(a[2] - st1.x*gs0) + bh0;
            stage[r1*17 + h + 1] = st1.y*(a[3] - st1.x*gs1) + bh1;
        }
    }
    __syncthreads();

    // ---- transposed coalesced write: all 128 rows share (b, i) ----
    {
        int p0  = blockIdx.x * 128;
        int b   = p0 / (Nn*Nn);
        int rem = p0 % (Nn*Nn);
        int ii  = rem / Nn;
        int j0  = rem % Nn;
        float* stage = (float*)(smraw + BZ_SG);
        #pragma unroll
        for (int t = tid; t < 128*NH; t += 256) {
            int h = t >> 7, rr = t & 127;
            d_bias[((size_t)(b*NH + h)*Nn + ii)*Nn + j0 + rr] = stage[rr*17 + h];
        }
    }
}

// ========== tensor-core flash attention: block per (b, h, 64-row i-tile) ==========
#define AT_STRIDE 72
#define QH_OFF 0
#define QL_OFF 9216
#define KH_OFF 18432
#define KL_OFF 27648
#define VH_OFF 36864
#define VL_OFF 46080
#define OSM_OFF 18432
#define OSM_STRIDE 68
#define STAT_OFF (OSM_OFF + 8*16*OSM_STRIDE*4)   // 53248
#define ATT_SMEM 55296

__global__ void __launch_bounds__(256, 2) attn_mma(const float* __restrict__ mask)
{
    extern __shared__ char smraw[];
    uint32_t sb = (uint32_t)__cvta_generic_to_shared(smraw);
    int tid = threadIdx.x, lane = tid & 31, wid = tid >> 5;
    int warpM = wid >> 1, warpN = wid & 1;
    int b = blockIdx.z, h = blockIdx.y, i0 = blockIdx.x * 64;
    int grp = lane >> 2, tL = lane & 3;
    int t8 = lane >> 3, r8 = lane & 7;

    int lrow = tid >> 2, lcol = (tid & 3) * 16;

    {
        const float* src = d_q + (size_t)(b*Nn + i0 + lrow)*CS + h*HD + lcol;
        uint32_t* qh = (uint32_t*)(smraw + QH_OFF);
        uint32_t* ql = (uint32_t*)(smraw + QL_OFF);
        #pragma unroll
        for (int qq = 0; qq < 4; qq++) {
            float4 vv = *(const float4*)(src + qq*4);
            int e0 = (lrow*AT_STRIDE + lcol + qq*4) >> 1;
            uint32_t h0, l0, h1, l1;
            split2(vv.x*0.125f, vv.y*0.125f, h0, l0);
            split2(vv.z*0.125f, vv.w*0.125f, h1, l1);
            qh[e0] = h0; qh[e0+1] = h1;
            ql[e0] = l0; ql[e0+1] = l1;
        }
    }

    float Oa[8][4];
    #pragma unroll
    for (int t = 0; t < 8; t++) { Oa[t][0]=0.f; Oa[t][1]=0.f; Oa[t][2]=0.f; Oa[t][3]=0.f; }
    float mrow0 = -1e30f, mrow1 = -1e30f, lsum0 = 0.f, lsum1 = 0.f;

    const float* maskp = mask + b*Nn;
    const float* biasbase = d_bias + ((size_t)(b*NH + h)*Nn + (i0 + warpM*16 + grp))*Nn;

    int aRow  = warpM*16 + (t8 & 1)*8 + r8;
    int aCol  = (t8 >> 1)*8;
    int kRowB = warpN*32 + (t8 >> 1)*8 + r8;
    int kColB = (t8 & 1)*8;
    int vRowB = (t8 & 1)*8 + r8;
    int vColB = (t8 >> 1)*8;

    #pragma unroll 1
    for (int jt = 0; jt < 12; jt++) {
        int j0c = jt * 64;
        const float* ksrc = d_k + (size_t)(b*Nn + j0c + lrow)*CS + h*HD + lcol;
        const float* vsrc = d_v + (size_t)(b*Nn + j0c + lrow)*CS + h*HD + lcol;
        float4 kr[4], vr[4];
        #pragma unroll
        for (int qq = 0; qq < 4; qq++) {
            kr[qq] = *(const float4*)(ksrc + qq*4);
            vr[qq] = *(const float4*)(vsrc + qq*4);
        }
        __syncthreads();
        {
            uint32_t* kh = (uint32_t*)(smraw + KH_OFF);
            uint32_t* kl = (uint32_t*)(smraw + KL_OFF);
            uint32_t* vh = (uint32_t*)(smraw + VH_OFF);
            uint32_t* vl = (uint32_t*)(smraw + VL_OFF);
            #pragma unroll
            for (int qq = 0; qq < 4; qq++) {
                int e0 = (lrow*AT_STRIDE + lcol + qq*4) >> 1;
                uint32_t h0, l0, h1, l1;
                split2(kr[qq].x, kr[qq].y, h0, l0);
                split2(kr[qq].z, kr[qq].w, h1, l1);
                kh[e0] = h0; kh[e0+1] = h1; kl[e0] = l0; kl[e0+1] = l1;
                split2(vr[qq].x, vr[qq].y, h0, l0);
                split2(vr[qq].z, vr[qq].w, h1, l1);
                vh[e0] = h0; vh[e0+1] = h1; vl[e0] = l0; vl[e0+1] = l1;
            }
        }
        __syncthreads();

        float S[4][4];
        #pragma unroll
        for (int nt = 0; nt < 4; nt++) { S[nt][0]=0.f; S[nt][1]=0.f; S[nt][2]=0.f; S[nt][3]=0.f; }
        #pragma unroll
        for (int kk = 0; kk < 4; kk++) {
            uint32_t qh_[4], ql_[4], khf[2][4], klf[2][4];
            uint32_t aoff = (uint32_t)((aRow*AT_STRIDE + kk*16 + aCol) * 2);
            ldsm4(qh_, sb + QH_OFF + aoff);
            ldsm4(ql_, sb + QL_OFF + aoff);
            uint32_t koff0 = (uint32_t)((kRowB*AT_STRIDE + kk*16 + kColB) * 2);
            uint32_t koff1 = (uint32_t)(((kRowB+16)*AT_STRIDE + kk*16 + kColB) * 2);
            ldsm4(khf[0], sb + KH_OFF + koff0);
            ldsm4(khf[1], sb + KH_OFF + koff1);
            #pragma unroll
            for (int nt = 0; nt < 4; nt++)
                mma_bf16(S[nt], qh_, &khf[nt >> 1][(nt & 1)*2]);
            #pragma unroll
            for (int nt = 0; nt < 4; nt++)
                mma_bf16(S[nt], ql_, &khf[nt >> 1][(nt & 1)*2]);
            ldsm4(klf[0], sb + KL_OFF + koff0);
            ldsm4(klf[1], sb + KL_OFF + koff1);
            #pragma unroll
            for (int nt = 0; nt < 4; nt++)
                mma_bf16(S[nt], qh_, &klf[nt >> 1][(nt & 1)*2]);
        }

        #pragma unroll
        for (int nt = 0; nt < 4; nt++) {
            int jc = j0c + warpN*32 + nt*8 + tL*2;
            float2 b0 = *(const float2*)(biasbase + jc);
            float2 b1 = *(const float2*)(biasbase + (size_t)8*Nn + jc);
            float2 mv = *(const float2*)(maskp + jc);
            float mk0 = (1.f - mv.x) * (-1000000.0f);
            float mk1 = (1.f - mv.y) * (-1000000.0f);
            S[nt][0] += b0.x + mk0; S[nt][1] += b0.y + mk1;
            S[nt][2] += b1.x + mk0; S[nt][3] += b1.y + mk1;
        }

        float cm0 = fmaxf(fmaxf(S[0][0], S[0][1]), fmaxf(S[1][0], S[1][1]));
        cm0 = fmaxf(cm0, fmaxf(fmaxf(S[2][0], S[2][1]), fmaxf(S[3][0], S[3][1])));
        float cm1 = fmaxf(fmaxf(S[0][2], S[0][3]), fmaxf(S[1][2], S[1][3]));
        cm1 = fmaxf(cm1, fmaxf(fmaxf(S[2][2], S[2][3]), fmaxf(S[3][2], S[3][3])));
        cm0 = fmaxf(cm0, __shfl_xor_sync(0xFFFFFFFFu, cm0, 1));
        cm0 = fmaxf(cm0, __shfl_xor_sync(0xFFFFFFFFu, cm0, 2));
        cm1 = fmaxf(cm1, __shfl_xor_sync(0xFFFFFFFFu, cm1, 1));
        cm1 = fmaxf(cm1, __shfl_xor_sync(0xFFFFFFFFu, cm1, 2));
        float mn0 = fmaxf(mrow0, cm0), mn1 = fmaxf(mrow1, cm1);
        float sc0 = __expf(mrow0 - mn0), sc1 = __expf(mrow1 - mn1);
        mrow0 = mn0; mrow1 = mn1;
        float rs0 = 0.f, rs1 = 0.f;
        #pragma unroll
        for (int nt = 0; nt < 4; nt++) {
            S[nt][0] = __expf(S[nt][0] - mn0);
            S[nt][1] = __expf(S[nt][1] - mn0);
            S[nt][2] = __expf(S[nt][2] - mn1);
            S[nt][3] = __expf(S[nt][3] - mn1);
            rs0 += S[nt][0] + S[nt][1];
            rs1 += S[nt][2] + S[nt][3];
        }
        rs0 += __shfl_xor_sync(0xFFFFFFFFu, rs0, 1);
        rs0 += __shfl_xor_sync(0xFFFFFFFFu, rs0, 2);
        rs1 += __shfl_xor_sync(0xFFFFFFFFu, rs1, 1);
        rs1 += __shfl_xor_sync(0xFFFFFFFFu, rs1, 2);
        lsum0 = lsum0*sc0 + rs0;
        lsum1 = lsum1*sc1 + rs1;
        #pragma unroll
        for (int t = 0; t < 8; t++) {
            Oa[t][0] *= sc0; Oa[t][1] *= sc0;
            Oa[t][2] *= sc1; Oa[t][3] *= sc1;
        }

        uint32_t Ph[2][4], Pl[2][4];
        #pragma unroll
        for (int kf = 0; kf < 2; kf++) {
            split2(S[2*kf][0],   S[2*kf][1],   Ph[kf][0], Pl[kf][0]);
            split2(S[2*kf][2],   S[2*kf][3],   Ph[kf][1], Pl[kf][1]);
            split2(S[2*kf+1][0], S[2*kf+1][1], Ph[kf][2], Pl[kf][2]);
            split2(S[2*kf+1][2], S[2*kf+1][3], Ph[kf][3], Pl[kf][3]);
        }

        #pragma unroll
        for (int kf = 0; kf < 2; kf++) {
            int kb = warpN*32 + kf*16;
            #pragma unroll
            for (int ntp = 0; ntp < 4; ntp++) {
                uint32_t vhf[4], vlf[4];
                uint32_t voff = (uint32_t)(((kb + vRowB)*AT_STRIDE + ntp*16 + vColB) * 2);
                ldsm4t(vhf, sb + VH_OFF + voff);
                ldsm4t(vlf, sb + VL_OFF + voff);
                mma_bf16(Oa[ntp*2],   Ph[kf], &vhf[0]);
                mma_bf16(Oa[ntp*2+1], Ph[kf], &vhf[2]);
                mma_bf16(Oa[ntp*2],   Pl[kf], &vhf[0]);
                mma_bf16(Oa[ntp*2+1], Pl[kf], &vhf[2]);
                mma_bf16(Oa[ntp*2],   Ph[kf], &vlf[0]);
                mma_bf16(Oa[ntp*2+1], Ph[kf], &vlf[2]);
            }
        }
    }

    __syncthreads();
    float* Osm  = (float*)(smraw + OSM_OFF);
    float* stat = (float*)(smraw + STAT_OFF);
    #pragma unroll
    for (int t = 0; t < 8; t++) {
        int dcol = t*8 + tL*2;
        Osm[(wid*16 + grp)*OSM_STRIDE + dcol]       = Oa[t][0];
        Osm[(wid*16 + grp)*OSM_STRIDE + dcol + 1]   = Oa[t][1];
        Osm[(wid*16 + grp+8)*OSM_STRIDE + dcol]     = Oa[t][2];
        Osm[(wid*16 + grp+8)*OSM_STRIDE + dcol + 1] = Oa[t][3];
    }
    if (tL == 0) {
        stat[wid*32 + grp*2]       = mrow0;
        stat[wid*32 + grp*2 + 1]   = lsum0;
        stat[wid*32 + (grp+8)*2]     = mrow1;
        stat[wid*32 + (grp+8)*2 + 1] = lsum1;
    }
    __syncthreads();

    for (int t = tid; t < 64*64; t += 256) {
        int row = t >> 6, d = t & 63;
        int w0 = (row >> 4)*2, rl = row & 15;
        float m0 = stat[w0*32 + rl*2],     l0 = stat[w0*32 + rl*2 + 1];
        float m1 = stat[(w0+1)*32 + rl*2], l1 = stat[(w0+1)*32 + rl*2 + 1];
        float mm = fmaxf(m0, m1);
        float a0 = __expf(m0 - mm), a1 = __expf(m1 - mm);
        float oo = (a0*Osm[(w0*16 + rl)*OSM_STRIDE + d] +
                    a1*Osm[((w0+1)*16 + rl)*OSM_STRIDE + d]) / (a0*l0 + a1*l1);
        size_t gi = (size_t)(b*Nn + i0 + row)*CS + h*HD + d;
        d_go[gi] = d_g[gi] * oo;
    }
}

// ---------------- launch ----------------
extern "C" void kernel_launch(void* const* d_in, const int* in_sizes, int n_in,
                              void* d_out, int out_size)
{
    const float* s    = (const float*)d_in[0];
    const float* z    = (const float*)d_in[1];
    const float* mask = (const float*)d_in[2];
    const float* k_in = (const float*)d_in[3];
    const float* Wq   = (const float*)d_in[4];
    const float* bq   = (const float*)d_in[5];
    const float* Wk   = (const float*)d_in[6];
    const float* Wv   = (const float*)d_in[7];
    const float* Wg   = (const float*)d_in[8];
    const float* ln_g = (const float*)d_in[9];
    const float* ln_b = (const float*)d_in[10];
    const float* Wz   = (const float*)d_in[11];
    const float* Wo   = (const float*)d_in[12];
    float* out = (float*)d_out;

    cudaFuncSetAttribute(proj4_kernel, cudaFuncAttributeMaxDynamicSharedMemorySize, GEMM_SMEM);
    cudaFuncSetAttribute(final_gemm,   cudaFuncAttributeMaxDynamicSharedMemorySize, GEMM_SMEM);
    cudaFuncSetAttribute(attn_mma,     cudaFuncAttributeMaxDynamicSharedMemorySize, ATT_SMEM);
    cudaFuncSetAttribute(bias_mma,     cudaFuncAttributeMaxDynamicSharedMemorySize, BIAS_SMEM);

    proj4_kernel<<<dim3(CS/64, MROWS/128, 4), 256, GEMM_SMEM>>>(s, k_in, Wq, bq, Wk, Wv, Wg);

    prep_kernel<<<1, 128>>>(ln_g, ln_b, Wz);
    bias_mma<<<NPAIR/128, 256, BIAS_SMEM>>>(z);

    attn_mma<<<dim3(Nn/64, NH, Bn), 256, ATT_SMEM>>>(mask);

    final_gemm<<<dim3(CS/64, MROWS/128), 256, GEMM_SMEM>>>(Wo, out);
}

// round 6
// speedup vs baseline: 2.4332x; 1.0869x over previous
#include <cuda_runtime.h>
#include <cuda_bf16.h>
#include <cstdint>
#include <cstddef>

#define Bn 2
#define Nn 768
#define CS 1024
#define CZ 128
#define NH 16
#define HD 64
#define MROWS (Bn*Nn)     // 1536
#define NPAIR (Bn*Nn*Nn)  // 1179648
#define WSZ (CS*CS)

// ---------------- scratch (device globals; no allocations allowed) ----------------
__device__ __nv_bfloat16 d_Wh[5*WSZ], d_Wl[5*WSZ];          // Wq,Wk,Wv,Wg,Wo split
__device__ __nv_bfloat16 d_inh[2*MROWS*CS], d_inl[2*MROWS*CS]; // s, k_in split
__device__ __nv_bfloat16 d_qh[MROWS*CS], d_ql[MROWS*CS];
__device__ __nv_bfloat16 d_kh[MROWS*CS], d_kl[MROWS*CS];
__device__ __nv_bfloat16 d_vh[MROWS*CS], d_vl[MROWS*CS];
__device__ __nv_bfloat16 d_goh[MROWS*CS], d_gol[MROWS*CS];
__device__ float d_g[MROWS*CS];
__device__ float d_bias[Bn*NH*Nn*Nn];     // 75.5 MB
__device__ float d_Gz[CZ*NH];
__device__ float d_Bh[NH];
__device__ float d_GzSum[NH];

// ================= helpers ====================
__device__ __forceinline__ void ldsm4(uint32_t* r, uint32_t a) {
    asm volatile("ldmatrix.sync.aligned.m8n8.x4.shared.b16 {%0,%1,%2,%3}, [%4];"
                 : "=r"(r[0]), "=r"(r[1]), "=r"(r[2]), "=r"(r[3]) : "r"(a));
}
__device__ __forceinline__ void ldsm4t(uint32_t* r, uint32_t a) {
    asm volatile("ldmatrix.sync.aligned.m8n8.x4.trans.shared.b16 {%0,%1,%2,%3}, [%4];"
                 : "=r"(r[0]), "=r"(r[1]), "=r"(r[2]), "=r"(r[3]) : "r"(a));
}
__device__ __forceinline__ void mma_bf16(float* c, const uint32_t* a, const uint32_t* b) {
    asm volatile("mma.sync.aligned.m16n8k16.row.col.f32.bf16.bf16.f32 "
                 "{%0,%1,%2,%3}, {%4,%5,%6,%7}, {%8,%9}, {%0,%1,%2,%3};"
                 : "+f"(c[0]), "+f"(c[1]), "+f"(c[2]), "+f"(c[3])
                 : "r"(a[0]), "r"(a[1]), "r"(a[2]), "r"(a[3]), "r"(b[0]), "r"(b[1]));
}
__device__ __forceinline__ void split2(float x, float y, uint32_t& hi, uint32_t& lo) {
    __nv_bfloat162 h = __float22bfloat162_rn(make_float2(x, y));
    float2 hf = __bfloat1622float2(h);
    __nv_bfloat162 l = __float22bfloat162_rn(make_float2(x - hf.x, y - hf.y));
    hi = *(uint32_t*)&h;
    lo = *(uint32_t*)&l;
}
#define CPA(dst, src) asm volatile("cp.async.cg.shared.global [%0], [%1], 16;" :: "r"(dst), "l"(src))
#define CPCOMMIT()    asm volatile("cp.async.commit_group;")
#define CPWAIT1()     asm volatile("cp.async.wait_group 1;")

// ---------------- pre-split converters ----------------
__global__ void __launch_bounds__(256) wconv_kernel(
    const float* __restrict__ W0, const float* __restrict__ W1,
    const float* __restrict__ W2, const float* __restrict__ W3,
    const float* __restrict__ W4)
{
    int which = blockIdx.y;
    const float* src = which == 0 ? W0 : which == 1 ? W1 : which == 2 ? W2 :
                       which == 3 ? W3 : W4;
    size_t idx = ((size_t)blockIdx.x * 256 + threadIdx.x) * 4;
    float4 v = *(const float4*)(src + idx);
    uint32_t h0, l0, h1, l1;
    split2(v.x, v.y, h0, l0);
    split2(v.z, v.w, h1, l1);
    size_t o = (size_t)which * WSZ + idx;
    *(uint2*)((char*)d_Wh + o*2) = make_uint2(h0, h1);
    *(uint2*)((char*)d_Wl + o*2) = make_uint2(l0, l1);
}
__global__ void __launch_bounds__(256) aconv_kernel(
    const float* __restrict__ A0, const float* __restrict__ A1)
{
    int which = blockIdx.y;
    const float* src = which == 0 ? A0 : A1;
    size_t idx = ((size_t)blockIdx.x * 256 + threadIdx.x) * 4;
    float4 v = *(const float4*)(src + idx);
    uint32_t h0, l0, h1, l1;
    split2(v.x, v.y, h0, l0);
    split2(v.z, v.w, h1, l1);
    size_t o = (size_t)which * MROWS * CS + idx;
    *(uint2*)((char*)d_inh + o*2) = make_uint2(h0, h1);
    *(uint2*)((char*)d_inl + o*2) = make_uint2(l0, l1);
}

// ================= GEMM v2: pre-split bf16 inputs, cp.async 3-stage =====
// BM=128, BN=64, BK=32, 256 threads, warp 32x32. 3-term split MMA.
#define ASTRIDE 40
#define BSTRIDE 72
#define AHI_OFF 0
#define ALO_OFF 10240
#define BHI_OFF 20480
#define BLO_OFF 25088
#define BUFBYTES 29696
#define GEMM_SMEM (3*BUFBYTES)   // 89088

__device__ __forceinline__ void gemm_core(
    const __nv_bfloat16* __restrict__ Ah, const __nv_bfloat16* __restrict__ Al,
    const __nv_bfloat16* __restrict__ Bh, const __nv_bfloat16* __restrict__ Bl,
    const float* __restrict__ bq, int mode,
    float* __restrict__ Cf, __nv_bfloat16* __restrict__ Ch, __nv_bfloat16* __restrict__ Cl)
{
    extern __shared__ char sm_raw[];
    uint32_t sbase = (uint32_t)__cvta_generic_to_shared(sm_raw);

    int tid = threadIdx.x;
    int wid = tid >> 5, lane = tid & 31;
    int warpM = wid >> 1, warpN = wid & 1;
    int m0 = blockIdx.y * 128, n0 = blockIdx.x * 64;

    float acc[2][4][4];
    #pragma unroll
    for (int mt = 0; mt < 2; mt++)
        #pragma unroll
        for (int nt = 0; nt < 4; nt++)
            #pragma unroll
            for (int i = 0; i < 4; i++) acc[mt][nt][i] = 0.f;

    int matr = lane >> 3, rr = lane & 7;
    int aRowBase = warpM * 32 + (matr & 1) * 8 + rr;
    int aColBase = (matr >> 1) * 8;
    int bRowBase = (matr & 1) * 8 + rr;
    int bColBase = warpN * 32 + (matr >> 1) * 8;

    int arow = tid >> 2, aq = tid & 3;       // A: chunk pairs
    int brow = tid >> 3, bqc = tid & 7;      // B

    auto issue = [&](int c, int buf) {
        uint32_t st = sbase + buf * BUFBYTES;
        #pragma unroll
        for (int r = 0; r < 2; r++) {
            int row = arow + r * 64;
            const __nv_bfloat16* sh = Ah + (size_t)(m0 + row) * CS + c * 32 + aq * 8;
            const __nv_bfloat16* sl = Al + (size_t)(m0 + row) * CS + c * 32 + aq * 8;
            uint32_t d = st + row * 80 + aq * 16;
            CPA(d + AHI_OFF, sh);
            CPA(d + ALO_OFF, sl);
        }
        {
            const __nv_bfloat16* sh = Bh + (size_t)(c * 32 + brow) * CS + n0 + bqc * 8;
            const __nv_bfloat16* sl = Bl + (size_t)(c * 32 + brow) * CS + n0 + bqc * 8;
            uint32_t d = st + brow * 144 + bqc * 16;
            CPA(d + BHI_OFF, sh);
            CPA(d + BLO_OFF, sl);
        }
    };

    issue(0, 0); CPCOMMIT();
    issue(1, 1); CPCOMMIT();

    const int CHUNKS = 32;
    for (int c = 0; c < CHUNKS; c++) {
        CPWAIT1();
        __syncthreads();
        if (c + 2 < CHUNKS) issue(c + 2, (c + 2) % 3);
        CPCOMMIT();

        uint32_t off = sbase + (c % 3) * BUFBYTES;
        #pragma unroll
        for (int ks = 0; ks < 32; ks += 16) {
            uint32_t Ahf[2][4], Alf[2][4], Bhf[2][4], Blf[2][4];
            #pragma unroll
            for (int mt = 0; mt < 2; mt++)
                ldsm4(Ahf[mt], off + AHI_OFF +
                      (((aRowBase + mt * 16) * ASTRIDE) + aColBase + ks) * 2);
            #pragma unroll
            for (int ntp = 0; ntp < 2; ntp++)
                ldsm4t(Bhf[ntp], off + BHI_OFF +
                       (((bRowBase + ks) * BSTRIDE) + bColBase + ntp * 16) * 2);
            #pragma unroll
            for (int mt = 0; mt < 2; mt++)
                #pragma unroll
                for (int nt = 0; nt < 4; nt++)
                    mma_bf16(acc[mt][nt], Ahf[mt], &Bhf[nt >> 1][(nt & 1) * 2]);
            #pragma unroll
            for (int mt = 0; mt < 2; mt++)
                ldsm4(Alf[mt], off + ALO_OFF +
                      (((aRowBase + mt * 16) * ASTRIDE) + aColBase + ks) * 2);
            #pragma unroll
            for (int mt = 0; mt < 2; mt++)
                #pragma unroll
                for (int nt = 0; nt < 4; nt++)
                    mma_bf16(acc[mt][nt], Alf[mt], &Bhf[nt >> 1][(nt & 1) * 2]);
            #pragma unroll
            for (int ntp = 0; ntp < 2; ntp++)
                ldsm4t(Blf[ntp], off + BLO_OFF +
                       (((bRowBase + ks) * BSTRIDE) + bColBase + ntp * 16) * 2);
            #pragma unroll
            for (int mt = 0; mt < 2; mt++)
                #pragma unroll
                for (int nt = 0; nt < 4; nt++)
                    mma_bf16(acc[mt][nt], Ahf[mt], &Blf[nt >> 1][(nt & 1) * 2]);
        }
    }

    int grp = lane >> 2, tL = lane & 3;
    #pragma unroll
    for (int mt = 0; mt < 2; mt++) {
        #pragma unroll
        for (int nt = 0; nt < 4; nt++) {
            int row = m0 + warpM * 32 + mt * 16 + grp;
            int col = n0 + warpN * 32 + nt * 8 + tL * 2;
            float v0 = acc[mt][nt][0], v1 = acc[mt][nt][1];
            float v2 = acc[mt][nt][2], v3 = acc[mt][nt][3];
            if (mode == 0) {
                float b0 = bq[col], b1 = bq[col + 1];
                v0 = (v0 + b0) * 0.125f; v1 = (v1 + b1) * 0.125f;
                v2 = (v2 + b0) * 0.125f; v3 = (v3 + b1) * 0.125f;
            }
            if (mode == 3) {
                v0 = 1.f/(1.f + __expf(-v0)); v1 = 1.f/(1.f + __expf(-v1));
                v2 = 1.f/(1.f + __expf(-v2)); v3 = 1.f/(1.f + __expf(-v3));
                *(float2*)(Cf + (size_t)row * CS + col)       = make_float2(v0, v1);
                *(float2*)(Cf + (size_t)(row + 8) * CS + col) = make_float2(v2, v3);
            } else if (mode == 4) {
                *(float2*)(Cf + (size_t)row * CS + col)       = make_float2(v0, v1);
                *(float2*)(Cf + (size_t)(row + 8) * CS + col) = make_float2(v2, v3);
            } else {
                uint32_t h0, l0, h1, l1;
                split2(v0, v1, h0, l0);
                split2(v2, v3, h1, l1);
                *(uint32_t*)((char*)Ch + ((size_t)row * CS + col) * 2)       = h0;
                *(uint32_t*)((char*)Cl + ((size_t)row * CS + col) * 2)       = l0;
                *(uint32_t*)((char*)Ch + ((size_t)(row + 8) * CS + col) * 2) = h1;
                *(uint32_t*)((char*)Cl + ((size_t)(row + 8) * CS + col) * 2) = l1;
            }
        }
    }
}

__global__ void __launch_bounds__(256) proj4_kernel(const float* __restrict__ bq)
{
    int which = blockIdx.z;
    const __nv_bfloat16* Ah = (which == 0 || which == 3) ? d_inh : d_inh + MROWS*CS;
    const __nv_bfloat16* Al = (which == 0 || which == 3) ? d_inl : d_inl + MROWS*CS;
    const __nv_bfloat16* Bh = d_Wh + (size_t)which * WSZ;
    const __nv_bfloat16* Bl = d_Wl + (size_t)which * WSZ;
    __nv_bfloat16* Ch = which == 0 ? d_qh : which == 1 ? d_kh : which == 2 ? d_vh : nullptr;
    __nv_bfloat16* Cl = which == 0 ? d_ql : which == 1 ? d_kl : which == 2 ? d_vl : nullptr;
    gemm_core(Ah, Al, Bh, Bl, bq, which == 3 ? 3 : which, d_g, Ch, Cl);
}

__global__ void __launch_bounds__(256) final_gemm(float* __restrict__ out)
{
    gemm_core(d_goh, d_gol, d_Wh + 4*(size_t)WSZ, d_Wl + 4*(size_t)WSZ,
              nullptr, 4, out, nullptr, nullptr);
}

// ---------------- fold LN affine into z-projection ----------------
__global__ void prep_kernel(const float* __restrict__ ln_g,
                            const float* __restrict__ ln_b,
                            const float* __restrict__ Wz)
{
    __shared__ float sB[CZ*NH];
    __shared__ float sG[CZ*NH];
    int c = threadIdx.x;
    float g = ln_g[c], bb = ln_b[c];
    #pragma unroll
    for (int h = 0; h < NH; h++) {
        float w = Wz[c*NH + h];
        float gz = g*w;
        d_Gz[c*NH + h] = gz;
        sG[c*NH + h] = gz;
        sB[c*NH + h] = bb*w;
    }
    __syncthreads();
    if (c < NH) {
        float sb = 0.f, sg = 0.f;
        for (int cc = 0; cc < CZ; cc++) { sb += sB[cc*NH + c]; sg += sG[cc*NH + c]; }
        d_Bh[c] = sb;
        d_GzSum[c] = sg;
    }
}

// ====== bias: LN+proj as tensor-core GEMM ======
#define ZROW 136
#define BZ_ZH 0
#define BZ_ZL 34816
#define BZ_GH 69632
#define BZ_GL 75776
#define BZ_ST 81920
#define BZ_SG 82944
#define BIAS_SMEM 91648

__global__ void __launch_bounds__(256) bias_mma(const float* __restrict__ z)
{
    extern __shared__ char smraw[];
    uint32_t sb = (uint32_t)__cvta_generic_to_shared(smraw);
    int tid = threadIdx.x, lane = tid & 31, wid = tid >> 5;

    for (int t = tid; t < CZ*NH; t += 256) {
        int c = t >> 4, h = t & 15;
        float w = d_Gz[t];
        __nv_bfloat16 hi = __float2bfloat16(w);
        __nv_bfloat16 lo = __float2bfloat16(w - __bfloat162float(hi));
        ((__nv_bfloat16*)(smraw + BZ_GH))[c*24 + h] = hi;
        ((__nv_bfloat16*)(smraw + BZ_GL))[c*24 + h] = lo;
    }

    int row = tid >> 1, half = tid & 1;
    {
        const float* zr = z + (size_t)(blockIdx.x*128 + row)*CZ + half*64;
        uint32_t* zh = (uint32_t*)(smraw + BZ_ZH);
        uint32_t* zl = (uint32_t*)(smraw + BZ_ZL);
        float s1 = 0.f, s2 = 0.f;
        #pragma unroll
        for (int f = 0; f < 16; f++) {
            float4 v = *(const float4*)(zr + f*4);
            s1 += (v.x + v.y) + (v.z + v.w);
            s2 = fmaf(v.x, v.x, s2); s2 = fmaf(v.y, v.y, s2);
            s2 = fmaf(v.z, v.z, s2); s2 = fmaf(v.w, v.w, s2);
            uint32_t h0, l0, h1, l1;
            split2(v.x, v.y, h0, l0);
            split2(v.z, v.w, h1, l1);
            int e0 = (row*ZROW + half*64 + f*4) >> 1;
            zh[e0] = h0; zh[e0+1] = h1;
            zl[e0] = l0; zl[e0+1] = l1;
        }
        s1 += __shfl_xor_sync(0xFFFFFFFFu, s1, 1);
        s2 += __shfl_xor_sync(0xFFFFFFFFu, s2, 1);
        if (half == 0) {
            float mu  = s1 * (1.f/128.f);
            float var = s2 * (1.f/128.f) - mu*mu;
            ((float2*)(smraw + BZ_ST))[row] = make_float2(mu, rsqrtf(var + 1e-5f));
        }
    }
    __syncthreads();

    int t8 = lane >> 3, r8 = lane & 7;
    int aRow = wid*16 + (t8 & 1)*8 + r8;
    int aCol = (t8 >> 1)*8;
    int gRow = (t8 & 1)*8 + r8;
    int gCol = (t8 >> 1)*8;

    float acc0[4] = {0.f,0.f,0.f,0.f}, acc1[4] = {0.f,0.f,0.f,0.f};
    #pragma unroll
    for (int kc = 0; kc < 8; kc++) {
        uint32_t Ahf[4], Alf[4], Gh[4], Gl[4];
        uint32_t aoff = (uint32_t)((aRow*ZROW + kc*16 + aCol) * 2);
        uint32_t goff = (uint32_t)(((gRow + kc*16)*24 + gCol) * 2);
        ldsm4(Ahf, sb + BZ_ZH + aoff);
        ldsm4(Alf, sb + BZ_ZL + aoff);
        ldsm4t(Gh, sb + BZ_GH + goff);
        ldsm4t(Gl, sb + BZ_GL + goff);
        mma_bf16(acc0, Ahf, &Gh[0]); mma_bf16(acc1, Ahf, &Gh[2]);
        mma_bf16(acc0, Alf, &Gh[0]); mma_bf16(acc1, Alf, &Gh[2]);
        mma_bf16(acc0, Ahf, &Gl[0]); mma_bf16(acc1, Ahf, &Gl[2]);
    }

    {
        int grp = lane >> 2, tL = lane & 3;
        int r0 = wid*16 + grp, r1 = r0 + 8;
        float2 st0 = ((float2*)(smraw + BZ_ST))[r0];
        float2 st1 = ((float2*)(smraw + BZ_ST))[r1];
        float* stage = (float*)(smraw + BZ_SG);
        #pragma unroll
        for (int n = 0; n < 2; n++) {
            float* a = n ? acc1 : acc0;
            int h = n*8 + tL*2;
            float gs0 = d_GzSum[h], gs1 = d_GzSum[h+1];
            float bh0 = d_Bh[h],    bh1 = d_Bh[h+1];
            stage[r0*17 + h]     = st0.y*(a[0] - st0.x*gs0) + bh0;
            stage[r0*17 + h + 1] = st0.y*(a[1] - st0.x*gs1) + bh1;
            stage[r1*17 + h]     = st1.y*(a[2] - st1.x*gs0) + bh0;
            stage[r1*17 + h + 1] = st1.y*(a[3] - st1.x*gs1) + bh1;
        }
    }
    __syncthreads();

    {
        int p0  = blockIdx.x * 128;
        int b   = p0 / (Nn*Nn);
        int rem = p0 % (Nn*Nn);
        int ii  = rem / Nn;
        int j0  = rem % Nn;
        float* stage = (float*)(smraw + BZ_SG);
        #pragma unroll
        for (int t = tid; t < 128*NH; t += 256) {
            int h = t >> 7, rr = t & 127;
            d_bias[((size_t)(b*NH + h)*Nn + ii)*Nn + j0 + rr] = stage[rr*17 + h];
        }
    }
}

// ========== flash attention v2: pre-split bf16 q/k/v, cp.async pipeline ==========
#define AT_STRIDE 72
#define AQ_H 0
#define AQ_L 9216
#define KV0 18432
#define KVSTAGE 36864        // kh(9216) kl vh vl
#define OSM_OFF 0
#define OSM_STRIDE 68
#define STAT_OFF 34816
#define ATT_SMEM 92160

__global__ void __launch_bounds__(256, 2) attn_mma(const float* __restrict__ mask)
{
    extern __shared__ char smraw[];
    uint32_t sb = (uint32_t)__cvta_generic_to_shared(smraw);
    int tid = threadIdx.x, lane = tid & 31, wid = tid >> 5;
    int warpM = wid >> 1, warpN = wid & 1;
    int b = blockIdx.z, h = blockIdx.y, i0 = blockIdx.x * 64;
    int grp = lane >> 2, tL = lane & 3;
    int t8 = lane >> 3, r8 = lane & 7;

    // ---- Q via cp.async (4 chunks/thread) + KV stage 0 (8 chunks/thread) ----
    {
        #pragma unroll
        for (int i = 0; i < 4; i++) {
            int g = tid + i*256;
            int mtx = g >> 9, r = (g >> 3) & 63, q = g & 7;
            const __nv_bfloat16* src = (mtx ? d_ql : d_qh) +
                (size_t)(b*Nn + i0 + r)*CS + h*HD + q*8;
            CPA(sb + mtx*9216 + r*144 + q*16, src);
        }
        #pragma unroll
        for (int i = 0; i < 8; i++) {
            int g = tid + i*256;
            int mtx = g >> 9, r = (g >> 3) & 63, q = g & 7;
            const __nv_bfloat16* src =
                (mtx == 0 ? d_kh : mtx == 1 ? d_kl : mtx == 2 ? d_vh : d_vl) +
                (size_t)(b*Nn + r)*CS + h*HD + q*8;
            CPA(sb + KV0 + mtx*9216 + r*144 + q*16, src);
        }
        CPCOMMIT();
    }

    float Oa[8][4];
    #pragma unroll
    for (int t = 0; t < 8; t++) { Oa[t][0]=0.f; Oa[t][1]=0.f; Oa[t][2]=0.f; Oa[t][3]=0.f; }
    float mrow0 = -1e30f, mrow1 = -1e30f, lsum0 = 0.f, lsum1 = 0.f;

    const float* maskp = mask + b*Nn;
    const float* biasbase = d_bias + ((size_t)(b*NH + h)*Nn + (i0 + warpM*16 + grp))*Nn;

    int aRow  = warpM*16 + (t8 & 1)*8 + r8;
    int aCol  = (t8 >> 1)*8;
    int kRowB = warpN*32 + (t8 >> 1)*8 + r8;
    int kColB = (t8 & 1)*8;
    int vRowB = (t8 & 1)*8 + r8;
    int vColB = (t8 >> 1)*8;

    #pragma unroll 1
    for (int jt = 0; jt < 12; jt++) {
        int j0c = jt * 64;
        __syncthreads();   // prior iter's consumers done with buffer (jt+1)&1
        if (jt + 1 < 12) {
            int st1 = (jt + 1) & 1;
            #pragma unroll
            for (int i = 0; i < 8; i++) {
                int g = tid + i*256;
                int mtx = g >> 9, r = (g >> 3) & 63, q = g & 7;
                const __nv_bfloat16* src =
                    (mtx == 0 ? d_kh : mtx == 1 ? d_kl : mtx == 2 ? d_vh : d_vl) +
                    (size_t)(b*Nn + j0c + 64 + r)*CS + h*HD + q*8;
                CPA(sb + KV0 + st1*KVSTAGE + mtx*9216 + r*144 + q*16, src);
            }
        }
        CPCOMMIT();
        CPWAIT1();
        __syncthreads();   // stage jt visible to all

        uint32_t ks = sb + KV0 + (jt & 1)*KVSTAGE;

        // ---- S = (Q/8) . K^T  (3-term) ----
        float S[4][4];
        #pragma unroll
        for (int nt = 0; nt < 4; nt++) { S[nt][0]=0.f; S[nt][1]=0.f; S[nt][2]=0.f; S[nt][3]=0.f; }
        #pragma unroll
        for (int kk = 0; kk < 4; kk++) {
            uint32_t qh_[4], ql_[4], khf[2][4], klf[2][4];
            uint32_t aoff = (uint32_t)((aRow*AT_STRIDE + kk*16 + aCol) * 2);
            ldsm4(qh_, sb + AQ_H + aoff);
            ldsm4(ql_, sb + AQ_L + aoff);
            uint32_t koff0 = (uint32_t)((kRowB*AT_STRIDE + kk*16 + kColB) * 2);
            uint32_t koff1 = (uint32_t)(((kRowB+16)*AT_STRIDE + kk*16 + kColB) * 2);
            ldsm4(khf[0], ks + koff0);
            ldsm4(khf[1], ks + koff1);
            #pragma unroll
            for (int nt = 0; nt < 4; nt++)
                mma_bf16(S[nt], qh_, &khf[nt >> 1][(nt & 1)*2]);
            #pragma unroll
            for (int nt = 0; nt < 4; nt++)
                mma_bf16(S[nt], ql_, &khf[nt >> 1][(nt & 1)*2]);
            ldsm4(klf[0], ks + 9216 + koff0);
            ldsm4(klf[1], ks + 9216 + koff1);
            #pragma unroll
            for (int nt = 0; nt < 4; nt++)
                mma_bf16(S[nt], qh_, &klf[nt >> 1][(nt & 1)*2]);
        }

        #pragma unroll
        for (int nt = 0; nt < 4; nt++) {
            int jc = j0c + warpN*32 + nt*8 + tL*2;
            float2 b0 = *(const float2*)(biasbase + jc);
            float2 b1 = *(const float2*)(biasbase + (size_t)8*Nn + jc);
            float2 mv = *(const float2*)(maskp + jc);
            float mk0 = (1.f - mv.x) * (-1000000.0f);
            float mk1 = (1.f - mv.y) * (-1000000.0f);
            S[nt][0] += b0.x + mk0; S[nt][1] += b0.y + mk1;
            S[nt][2] += b1.x + mk0; S[nt][3] += b1.y + mk1;
        }

        float cm0 = fmaxf(fmaxf(S[0][0], S[0][1]), fmaxf(S[1][0], S[1][1]));
        cm0 = fmaxf(cm0, fmaxf(fmaxf(S[2][0], S[2][1]), fmaxf(S[3][0], S[3][1])));
        float cm1 = fmaxf(fmaxf(S[0][2], S[0][3]), fmaxf(S[1][2], S[1][3]));
        cm1 = fmaxf(cm1, fmaxf(fmaxf(S[2][2], S[2][3]), fmaxf(S[3][2], S[3][3])));
        cm0 = fmaxf(cm0, __shfl_xor_sync(0xFFFFFFFFu, cm0, 1));
        cm0 = fmaxf(cm0, __shfl_xor_sync(0xFFFFFFFFu, cm0, 2));
        cm1 = fmaxf(cm1, __shfl_xor_sync(0xFFFFFFFFu, cm1, 1));
        cm1 = fmaxf(cm1, __shfl_xor_sync(0xFFFFFFFFu, cm1, 2));
        float mn0 = fmaxf(mrow0, cm0), mn1 = fmaxf(mrow1, cm1);
        float sc0 = __expf(mrow0 - mn0), sc1 = __expf(mrow1 - mn1);
        mrow0 = mn0; mrow1 = mn1;
        float rs0 = 0.f, rs1 = 0.f;
        #pragma unroll
        for (int nt = 0; nt < 4; nt++) {
            S[nt][0] = __expf(S[nt][0] - mn0);
            S[nt][1] = __expf(S[nt][1] - mn0);
            S[nt][2] = __expf(S[nt][2] - mn1);
            S[nt][3] = __expf(S[nt][3] - mn1);
            rs0 += S[nt][0] + S[nt][1];
            rs1 += S[nt][2] + S[nt][3];
        }
        rs0 += __shfl_xor_sync(0xFFFFFFFFu, rs0, 1);
        rs0 += __shfl_xor_sync(0xFFFFFFFFu, rs0, 2);
        rs1 += __shfl_xor_sync(0xFFFFFFFFu, rs1, 1);
        rs1 += __shfl_xor_sync(0xFFFFFFFFu, rs1, 2);
        lsum0 = lsum0*sc0 + rs0;
        lsum1 = lsum1*sc1 + rs1;
        #pragma unroll
        for (int t = 0; t < 8; t++) {
            Oa[t][0] *= sc0; Oa[t][1] *= sc0;
            Oa[t][2] *= sc1; Oa[t][3] *= sc1;
        }

        uint32_t Ph[2][4], Pl[2][4];
        #pragma unroll
        for (int kf = 0; kf < 2; kf++) {
            split2(S[2*kf][0],   S[2*kf][1],   Ph[kf][0], Pl[kf][0]);
            split2(S[2*kf][2],   S[2*kf][3],   Ph[kf][1], Pl[kf][1]);
            split2(S[2*kf+1][0], S[2*kf+1][1], Ph[kf][2], Pl[kf][2]);
            split2(S[2*kf+1][2], S[2*kf+1][3], Ph[kf][3], Pl[kf][3]);
        }

        #pragma unroll
        for (int kf = 0; kf < 2; kf++) {
            int kb = warpN*32 + kf*16;
            #pragma unroll
            for (int ntp = 0; ntp < 4; ntp++) {
                uint32_t vhf[4], vlf[4];
                uint32_t voff = (uint32_t)(((kb + vRowB)*AT_STRIDE + ntp*16 + vColB) * 2);
                ldsm4t(vhf, ks + 18432 + voff);
                ldsm4t(vlf, ks + 27648 + voff);
                mma_bf16(Oa[ntp*2],   Ph[kf], &vhf[0]);
                mma_bf16(Oa[ntp*2+1], Ph[kf], &vhf[2]);
                mma_bf16(Oa[ntp*2],   Pl[kf], &vhf[0]);
                mma_bf16(Oa[ntp*2+1], Pl[kf], &vhf[2]);
                mma_bf16(Oa[ntp*2],   Ph[kf], &vlf[0]);
                mma_bf16(Oa[ntp*2+1], Ph[kf], &vlf[2]);
            }
        }
    }

    // ---- combine partials (overlay smem), gate, write split bf16 go ----
    __syncthreads();
    float* Osm  = (float*)(smraw + OSM_OFF);
    float* stat = (float*)(smraw + STAT_OFF);
    #pragma unroll
    for (int t = 0; t < 8; t++) {
        int dcol = t*8 + tL*2;
        Osm[(wid*16 + grp)*OSM_STRIDE + dcol]       = Oa[t][0];
        Osm[(wid*16 + grp)*OSM_STRIDE + dcol + 1]   = Oa[t][1];
        Osm[(wid*16 + grp+8)*OSM_STRIDE + dcol]     = Oa[t][2];
        Osm[(wid*16 + grp+8)*OSM_STRIDE + dcol + 1] = Oa[t][3];
    }
    if (tL == 0) {
        stat[wid*32 + grp*2]       = mrow0;
        stat[wid*32 + grp*2 + 1]   = lsum0;
        stat[wid*32 + (grp+8)*2]     = mrow1;
        stat[wid*32 + (grp+8)*2 + 1] = lsum1;
    }
    __syncthreads();

    for (int t = tid; t < 64*32; t += 256) {
        int row = t >> 5, d2 = (t & 31)*2;
        int w0 = (row >> 4)*2, rl = row & 15;
        float m0 = stat[w0*32 + rl*2],     l0 = stat[w0*32 + rl*2 + 1];
        float m1 = stat[(w0+1)*32 + rl*2], l1 = stat[(w0+1)*32 + rl*2 + 1];
        float mm = fmaxf(m0, m1);
        float a0 = __expf(m0 - mm), a1 = __expf(m1 - mm);
        float inv = 1.f / (a0*l0 + a1*l1);
        float o0 = (a0*Osm[(w0*16 + rl)*OSM_STRIDE + d2] +
                    a1*Osm[((w0+1)*16 + rl)*OSM_STRIDE + d2]) * inv;
        float o1 = (a0*Osm[(w0*16 + rl)*OSM_STRIDE + d2 + 1] +
                    a1*Osm[((w0+1)*16 + rl)*OSM_STRIDE + d2 + 1]) * inv;
        size_t gi = (size_t)(b*Nn + i0 + row)*CS + h*HD + d2;
        float2 gg = *(const float2*)(d_g + gi);
        uint32_t hh, ll;
        split2(gg.x * o0, gg.y * o1, hh, ll);
        *(uint32_t*)((char*)d_goh + gi*2) = hh;
        *(uint32_t*)((char*)d_gol + gi*2) = ll;
    }
}

// ---------------- launch ----------------
extern "C" void kernel_launch(void* const* d_in, const int* in_sizes, int n_in,
                              void* d_out, int out_size)
{
    const float* s    = (const float*)d_in[0];
    const float* z    = (const float*)d_in[1];
    const float* mask = (const float*)d_in[2];
    const float* k_in = (const float*)d_in[3];
    const float* Wq   = (const float*)d_in[4];
    const float* bq   = (const float*)d_in[5];
    const float* Wk   = (const float*)d_in[6];
    const float* Wv   = (const float*)d_in[7];
    const float* Wg   = (const float*)d_in[8];
    const float* ln_g = (const float*)d_in[9];
    const float* ln_b = (const float*)d_in[10];
    const float* Wz   = (const float*)d_in[11];
    const float* Wo   = (const float*)d_in[12];
    float* out = (float*)d_out;

    cudaFuncSetAttribute(proj4_kernel, cudaFuncAttributeMaxDynamicSharedMemorySize, GEMM_SMEM);
    cudaFuncSetAttribute(final_gemm,   cudaFuncAttributeMaxDynamicSharedMemorySize, GEMM_SMEM);
    cudaFuncSetAttribute(attn_mma,     cudaFuncAttributeMaxDynamicSharedMemorySize, ATT_SMEM);
    cudaFuncSetAttribute(bias_mma,     cudaFuncAttributeMaxDynamicSharedMemorySize, BIAS_SMEM);

    wconv_kernel<<<dim3(WSZ/1024, 5), 256>>>(Wq, Wk, Wv, Wg, Wo);
    aconv_kernel<<<dim3(MROWS*CS/1024, 2), 256>>>(s, k_in);

    proj4_kernel<<<dim3(CS/64, MROWS/128, 4), 256, GEMM_SMEM>>>(bq);

    prep_kernel<<<1, 128>>>(ln_g, ln_b, Wz);
    bias_mma<<<NPAIR/128, 256, BIAS_SMEM>>>(z);

    attn_mma<<<dim3(Nn/64, NH, Bn), 256, ATT_SMEM>>>(mask);

    final_gemm<<<dim3(CS/64, MROWS/128), 256, GEMM_SMEM>>>(out);
}

// round 7
// speedup vs baseline: 2.4685x; 1.0145x over previous
#include <cuda_runtime.h>
#include <cuda_bf16.h>
#include <cstdint>
#include <cstddef>

#define Bn 2
#define Nn 768
#define CS 1024
#define CZ 128
#define NH 16
#define HD 64
#define MROWS (Bn*Nn)     // 1536
#define NPAIR (Bn*Nn*Nn)  // 1179648
#define WSZ (CS*CS)

// ---------------- scratch (device globals; no allocations allowed) ----------------
__device__ __nv_bfloat16 d_Wh[5*WSZ], d_Wl[5*WSZ];          // Wq,Wk,Wv,Wg,Wo split
__device__ __nv_bfloat16 d_inh[2*MROWS*CS], d_inl[2*MROWS*CS]; // s, k_in split
__device__ __nv_bfloat16 d_qh[MROWS*CS], d_ql[MROWS*CS];
__device__ __nv_bfloat16 d_kh[MROWS*CS], d_kl[MROWS*CS];
__device__ __nv_bfloat16 d_vh[MROWS*CS], d_vl[MROWS*CS];
__device__ __nv_bfloat16 d_goh[MROWS*CS], d_gol[MROWS*CS];
__device__ float d_g[MROWS*CS];
__device__ float d_bias[Bn*NH*Nn*Nn];     // 75.5 MB
__device__ float d_Gz[CZ*NH];
__device__ float d_Bh[NH];
__device__ float d_GzSum[NH];

// ================= helpers ====================
__device__ __forceinline__ void ldsm4(uint32_t* r, uint32_t a) {
    asm volatile("ldmatrix.sync.aligned.m8n8.x4.shared.b16 {%0,%1,%2,%3}, [%4];"
                 : "=r"(r[0]), "=r"(r[1]), "=r"(r[2]), "=r"(r[3]) : "r"(a));
}
__device__ __forceinline__ void ldsm4t(uint32_t* r, uint32_t a) {
    asm volatile("ldmatrix.sync.aligned.m8n8.x4.trans.shared.b16 {%0,%1,%2,%3}, [%4];"
                 : "=r"(r[0]), "=r"(r[1]), "=r"(r[2]), "=r"(r[3]) : "r"(a));
}
__device__ __forceinline__ void mma_bf16(float* c, const uint32_t* a, const uint32_t* b) {
    asm volatile("mma.sync.aligned.m16n8k16.row.col.f32.bf16.bf16.f32 "
                 "{%0,%1,%2,%3}, {%4,%5,%6,%7}, {%8,%9}, {%0,%1,%2,%3};"
                 : "+f"(c[0]), "+f"(c[1]), "+f"(c[2]), "+f"(c[3])
                 : "r"(a[0]), "r"(a[1]), "r"(a[2]), "r"(a[3]), "r"(b[0]), "r"(b[1]));
}
__device__ __forceinline__ void split2(float x, float y, uint32_t& hi, uint32_t& lo) {
    __nv_bfloat162 h = __float22bfloat162_rn(make_float2(x, y));
    float2 hf = __bfloat1622float2(h);
    __nv_bfloat162 l = __float22bfloat162_rn(make_float2(x - hf.x, y - hf.y));
    hi = *(uint32_t*)&h;
    lo = *(uint32_t*)&l;
}
#define CPA(dst, src) asm volatile("cp.async.cg.shared.global [%0], [%1], 16;" :: "r"(dst), "l"(src))
#define CPCOMMIT()    asm volatile("cp.async.commit_group;")
#define CPWAIT1()     asm volatile("cp.async.wait_group 1;")

// ---------------- pre-split converters ----------------
__global__ void __launch_bounds__(256) wconv_kernel(
    const float* __restrict__ W0, const float* __restrict__ W1,
    const float* __restrict__ W2, const float* __restrict__ W3,
    const float* __restrict__ W4)
{
    int which = blockIdx.y;
    const float* src = which == 0 ? W0 : which == 1 ? W1 : which == 2 ? W2 :
                       which == 3 ? W3 : W4;
    size_t idx = ((size_t)blockIdx.x * 256 + threadIdx.x) * 4;
    float4 v = *(const float4*)(src + idx);
    uint32_t h0, l0, h1, l1;
    split2(v.x, v.y, h0, l0);
    split2(v.z, v.w, h1, l1);
    size_t o = (size_t)which * WSZ + idx;
    *(uint2*)((char*)d_Wh + o*2) = make_uint2(h0, h1);
    *(uint2*)((char*)d_Wl + o*2) = make_uint2(l0, l1);
}
__global__ void __launch_bounds__(256) aconv_kernel(
    const float* __restrict__ A0, const float* __restrict__ A1)
{
    int which = blockIdx.y;
    const float* src = which == 0 ? A0 : A1;
    size_t idx = ((size_t)blockIdx.x * 256 + threadIdx.x) * 4;
    float4 v = *(const float4*)(src + idx);
    uint32_t h0, l0, h1, l1;
    split2(v.x, v.y, h0, l0);
    split2(v.z, v.w, h1, l1);
    size_t o = (size_t)which * MROWS * CS + idx;
    *(uint2*)((char*)d_inh + o*2) = make_uint2(h0, h1);
    *(uint2*)((char*)d_inl + o*2) = make_uint2(l0, l1);
}

// ================= GEMM v2: pre-split bf16 inputs, cp.async 3-stage =====
#define ASTRIDE 40
#define BSTRIDE 72
#define AHI_OFF 0
#define ALO_OFF 10240
#define BHI_OFF 20480
#define BLO_OFF 25088
#define BUFBYTES 29696
#define GEMM_SMEM (3*BUFBYTES)   // 89088

__device__ __forceinline__ void gemm_core(
    const __nv_bfloat16* __restrict__ Ah, const __nv_bfloat16* __restrict__ Al,
    const __nv_bfloat16* __restrict__ Bh, const __nv_bfloat16* __restrict__ Bl,
    const float* __restrict__ bq, int mode,
    float* __restrict__ Cf, __nv_bfloat16* __restrict__ Ch, __nv_bfloat16* __restrict__ Cl)
{
    extern __shared__ char sm_raw[];
    uint32_t sbase = (uint32_t)__cvta_generic_to_shared(sm_raw);

    int tid = threadIdx.x;
    int wid = tid >> 5, lane = tid & 31;
    int warpM = wid >> 1, warpN = wid & 1;
    int m0 = blockIdx.y * 128, n0 = blockIdx.x * 64;

    float acc[2][4][4];
    #pragma unroll
    for (int mt = 0; mt < 2; mt++)
        #pragma unroll
        for (int nt = 0; nt < 4; nt++)
            #pragma unroll
            for (int i = 0; i < 4; i++) acc[mt][nt][i] = 0.f;

    int matr = lane >> 3, rr = lane & 7;
    int aRowBase = warpM * 32 + (matr & 1) * 8 + rr;
    int aColBase = (matr >> 1) * 8;
    int bRowBase = (matr & 1) * 8 + rr;
    int bColBase = warpN * 32 + (matr >> 1) * 8;

    int arow = tid >> 2, aq = tid & 3;
    int brow = tid >> 3, bqc = tid & 7;

    auto issue = [&](int c, int buf) {
        uint32_t st = sbase + buf * BUFBYTES;
        #pragma unroll
        for (int r = 0; r < 2; r++) {
            int row = arow + r * 64;
            const __nv_bfloat16* sh = Ah + (size_t)(m0 + row) * CS + c * 32 + aq * 8;
            const __nv_bfloat16* sl = Al + (size_t)(m0 + row) * CS + c * 32 + aq * 8;
            uint32_t d = st + row * 80 + aq * 16;
            CPA(d + AHI_OFF, sh);
            CPA(d + ALO_OFF, sl);
        }
        {
            const __nv_bfloat16* sh = Bh + (size_t)(c * 32 + brow) * CS + n0 + bqc * 8;
            const __nv_bfloat16* sl = Bl + (size_t)(c * 32 + brow) * CS + n0 + bqc * 8;
            uint32_t d = st + brow * 144 + bqc * 16;
            CPA(d + BHI_OFF, sh);
            CPA(d + BLO_OFF, sl);
        }
    };

    issue(0, 0); CPCOMMIT();
    issue(1, 1); CPCOMMIT();

    const int CHUNKS = 32;
    for (int c = 0; c < CHUNKS; c++) {
        CPWAIT1();
        __syncthreads();
        if (c + 2 < CHUNKS) issue(c + 2, (c + 2) % 3);
        CPCOMMIT();

        uint32_t off = sbase + (c % 3) * BUFBYTES;
        #pragma unroll
        for (int ks = 0; ks < 32; ks += 16) {
            uint32_t Ahf[2][4], Alf[2][4], Bhf[2][4], Blf[2][4];
            #pragma unroll
            for (int mt = 0; mt < 2; mt++)
                ldsm4(Ahf[mt], off + AHI_OFF +
                      (((aRowBase + mt * 16) * ASTRIDE) + aColBase + ks) * 2);
            #pragma unroll
            for (int ntp = 0; ntp < 2; ntp++)
                ldsm4t(Bhf[ntp], off + BHI_OFF +
                       (((bRowBase + ks) * BSTRIDE) + bColBase + ntp * 16) * 2);
            #pragma unroll
            for (int mt = 0; mt < 2; mt++)
                #pragma unroll
                for (int nt = 0; nt < 4; nt++)
                    mma_bf16(acc[mt][nt], Ahf[mt], &Bhf[nt >> 1][(nt & 1) * 2]);
            #pragma unroll
            for (int mt = 0; mt < 2; mt++)
                ldsm4(Alf[mt], off + ALO_OFF +
                      (((aRowBase + mt * 16) * ASTRIDE) + aColBase + ks) * 2);
            #pragma unroll
            for (int mt = 0; mt < 2; mt++)
                #pragma unroll
                for (int nt = 0; nt < 4; nt++)
                    mma_bf16(acc[mt][nt], Alf[mt], &Bhf[nt >> 1][(nt & 1) * 2]);
            #pragma unroll
            for (int ntp = 0; ntp < 2; ntp++)
                ldsm4t(Blf[ntp], off + BLO_OFF +
                       (((bRowBase + ks) * BSTRIDE) + bColBase + ntp * 16) * 2);
            #pragma unroll
            for (int mt = 0; mt < 2; mt++)
                #pragma unroll
                for (int nt = 0; nt < 4; nt++)
                    mma_bf16(acc[mt][nt], Ahf[mt], &Blf[nt >> 1][(nt & 1) * 2]);
        }
    }

    int grp = lane >> 2, tL = lane & 3;
    #pragma unroll
    for (int mt = 0; mt < 2; mt++) {
        #pragma unroll
        for (int nt = 0; nt < 4; nt++) {
            int row = m0 + warpM * 32 + mt * 16 + grp;
            int col = n0 + warpN * 32 + nt * 8 + tL * 2;
            float v0 = acc[mt][nt][0], v1 = acc[mt][nt][1];
            float v2 = acc[mt][nt][2], v3 = acc[mt][nt][3];
            if (mode == 0) {
                float b0 = bq[col], b1 = bq[col + 1];
                v0 = (v0 + b0) * 0.125f; v1 = (v1 + b1) * 0.125f;
                v2 = (v2 + b0) * 0.125f; v3 = (v3 + b1) * 0.125f;
            }
            if (mode == 3) {
                v0 = 1.f/(1.f + __expf(-v0)); v1 = 1.f/(1.f + __expf(-v1));
                v2 = 1.f/(1.f + __expf(-v2)); v3 = 1.f/(1.f + __expf(-v3));
                *(float2*)(Cf + (size_t)row * CS + col)       = make_float2(v0, v1);
                *(float2*)(Cf + (size_t)(row + 8) * CS + col) = make_float2(v2, v3);
            } else if (mode == 4) {
                *(float2*)(Cf + (size_t)row * CS + col)       = make_float2(v0, v1);
                *(float2*)(Cf + (size_t)(row + 8) * CS + col) = make_float2(v2, v3);
            } else {
                uint32_t h0, l0, h1, l1;
                split2(v0, v1, h0, l0);
                split2(v2, v3, h1, l1);
                *(uint32_t*)((char*)Ch + ((size_t)row * CS + col) * 2)       = h0;
                *(uint32_t*)((char*)Cl + ((size_t)row * CS + col) * 2)       = l0;
                *(uint32_t*)((char*)Ch + ((size_t)(row + 8) * CS + col) * 2) = h1;
                *(uint32_t*)((char*)Cl + ((size_t)(row + 8) * CS + col) * 2) = l1;
            }
        }
    }
}

__global__ void __launch_bounds__(256) proj4_kernel(const float* __restrict__ bq)
{
    int which = blockIdx.z;
    const __nv_bfloat16* Ah = (which == 0 || which == 3) ? d_inh : d_inh + MROWS*CS;
    const __nv_bfloat16* Al = (which == 0 || which == 3) ? d_inl : d_inl + MROWS*CS;
    const __nv_bfloat16* Bh = d_Wh + (size_t)which * WSZ;
    const __nv_bfloat16* Bl = d_Wl + (size_t)which * WSZ;
    __nv_bfloat16* Ch = which == 0 ? d_qh : which == 1 ? d_kh : which == 2 ? d_vh : nullptr;
    __nv_bfloat16* Cl = which == 0 ? d_ql : which == 1 ? d_kl : which == 2 ? d_vl : nullptr;
    gemm_core(Ah, Al, Bh, Bl, bq, which == 3 ? 3 : which, d_g, Ch, Cl);
}

__global__ void __launch_bounds__(256) final_gemm(float* __restrict__ out)
{
    gemm_core(d_goh, d_gol, d_Wh + 4*(size_t)WSZ, d_Wl + 4*(size_t)WSZ,
              nullptr, 4, out, nullptr, nullptr);
}

// ---------------- fold LN affine into z-projection ----------------
__global__ void prep_kernel(const float* __restrict__ ln_g,
                            const float* __restrict__ ln_b,
                            const float* __restrict__ Wz)
{
    __shared__ float sB[CZ*NH];
    __shared__ float sG[CZ*NH];
    int c = threadIdx.x;
    float g = ln_g[c], bb = ln_b[c];
    #pragma unroll
    for (int h = 0; h < NH; h++) {
        float w = Wz[c*NH + h];
        float gz = g*w;
        d_Gz[c*NH + h] = gz;
        sG[c*NH + h] = gz;
        sB[c*NH + h] = bb*w;
    }
    __syncthreads();
    if (c < NH) {
        float sb = 0.f, sg = 0.f;
        for (int cc = 0; cc < CZ; cc++) { sb += sB[cc*NH + c]; sg += sG[cc*NH + c]; }
        d_Bh[c] = sb;
        d_GzSum[c] = sg;
    }
}

// ====== bias: LN+proj as tensor-core GEMM ======
#define ZROW 136
#define BZ_ZH 0
#define BZ_ZL 34816
#define BZ_GH 69632
#define BZ_GL 75776
#define BZ_ST 81920
#define BZ_SG 82944
#define BIAS_SMEM 91648

__global__ void __launch_bounds__(256) bias_mma(const float* __restrict__ z)
{
    extern __shared__ char smraw[];
    uint32_t sb = (uint32_t)__cvta_generic_to_shared(smraw);
    int tid = threadIdx.x, lane = tid & 31, wid = tid >> 5;

    for (int t = tid; t < CZ*NH; t += 256) {
        int c = t >> 4, h = t & 15;
        float w = d_Gz[t];
        __nv_bfloat16 hi = __float2bfloat16(w);
        __nv_bfloat16 lo = __float2bfloat16(w - __bfloat162float(hi));
        ((__nv_bfloat16*)(smraw + BZ_GH))[c*24 + h] = hi;
        ((__nv_bfloat16*)(smraw + BZ_GL))[c*24 + h] = lo;
    }

    int row = tid >> 1, half = tid & 1;
    {
        const float* zr = z + (size_t)(blockIdx.x*128 + row)*CZ + half*64;
        uint32_t* zh = (uint32_t*)(smraw + BZ_ZH);
        uint32_t* zl = (uint32_t*)(smraw + BZ_ZL);
        float s1 = 0.f, s2 = 0.f;
        #pragma unroll
        for (int f = 0; f < 16; f++) {
            float4 v = *(const float4*)(zr + f*4);
            s1 += (v.x + v.y) + (v.z + v.w);
            s2 = fmaf(v.x, v.x, s2); s2 = fmaf(v.y, v.y, s2);
            s2 = fmaf(v.z, v.z, s2); s2 = fmaf(v.w, v.w, s2);
            uint32_t h0, l0, h1, l1;
            split2(v.x, v.y, h0, l0);
            split2(v.z, v.w, h1, l1);
            int e0 = (row*ZROW + half*64 + f*4) >> 1;
            zh[e0] = h0; zh[e0+1] = h1;
            zl[e0] = l0; zl[e0+1] = l1;
        }
        s1 += __shfl_xor_sync(0xFFFFFFFFu, s1, 1);
        s2 += __shfl_xor_sync(0xFFFFFFFFu, s2, 1);
        if (half == 0) {
            float mu  = s1 * (1.f/128.f);
            float var = s2 * (1.f/128.f) - mu*mu;
            ((float2*)(smraw + BZ_ST))[row] = make_float2(mu, rsqrtf(var + 1e-5f));
        }
    }
    __syncthreads();

    int t8 = lane >> 3, r8 = lane & 7;
    int aRow = wid*16 + (t8 & 1)*8 + r8;
    int aCol = (t8 >> 1)*8;
    int gRow = (t8 & 1)*8 + r8;
    int gCol = (t8 >> 1)*8;

    float acc0[4] = {0.f,0.f,0.f,0.f}, acc1[4] = {0.f,0.f,0.f,0.f};
    #pragma unroll
    for (int kc = 0; kc < 8; kc++) {
        uint32_t Ahf[4], Alf[4], Gh[4], Gl[4];
        uint32_t aoff = (uint32_t)((aRow*ZROW + kc*16 + aCol) * 2);
        uint32_t goff = (uint32_t)(((gRow + kc*16)*24 + gCol) * 2);
        ldsm4(Ahf, sb + BZ_ZH + aoff);
        ldsm4(Alf, sb + BZ_ZL + aoff);
        ldsm4t(Gh, sb + BZ_GH + goff);
        ldsm4t(Gl, sb + BZ_GL + goff);
        mma_bf16(acc0, Ahf, &Gh[0]); mma_bf16(acc1, Ahf, &Gh[2]);
        mma_bf16(acc0, Alf, &Gh[0]); mma_bf16(acc1, Alf, &Gh[2]);
        mma_bf16(acc0, Ahf, &Gl[0]); mma_bf16(acc1, Ahf, &Gl[2]);
    }

    {
        int grp = lane >> 2, tL = lane & 3;
        int r0 = wid*16 + grp, r1 = r0 + 8;
        float2 st0 = ((float2*)(smraw + BZ_ST))[r0];
        float2 st1 = ((float2*)(smraw + BZ_ST))[r1];
        float* stage = (float*)(smraw + BZ_SG);
        #pragma unroll
        for (int n = 0; n < 2; n++) {
            float* a = n ? acc1 : acc0;
            int h = n*8 + tL*2;
            float gs0 = d_GzSum[h], gs1 = d_GzSum[h+1];
            float bh0 = d_Bh[h],    bh1 = d_Bh[h+1];
            stage[r0*17 + h]     = st0.y*(a[0] - st0.x*gs0) + bh0;
            stage[r0*17 + h + 1] = st0.y*(a[1] - st0.x*gs1) + bh1;
            stage[r1*17 + h]     = st1.y*(a[2] - st1.x*gs0) + bh0;
            stage[r1*17 + h + 1] = st1.y*(a[3] - st1.x*gs1) + bh1;
        }
    }
    __syncthreads();

    {
        int p0  = blockIdx.x * 128;
        int b   = p0 / (Nn*Nn);
        int rem = p0 % (Nn*Nn);
        int ii  = rem / Nn;
        int j0  = rem % Nn;
        float* stage = (float*)(smraw + BZ_SG);
        #pragma unroll
        for (int t = tid; t < 128*NH; t += 256) {
            int h = t >> 7, rr = t & 127;
            d_bias[((size_t)(b*NH + h)*Nn + ii)*Nn + j0 + rr] = stage[rr*17 + h];
        }
    }
}

// ========== flash attention v2: pre-split bf16 q/k/v, cp.async pipeline ==========
#define AT_STRIDE 72
#define AQ_H 0
#define AQ_L 9216
#define KV0 18432
#define KVSTAGE 36864
#define OSM_OFF 0
#define OSM_STRIDE 68
#define STAT_OFF 34816
#define ATT_SMEM 92160

__global__ void __launch_bounds__(256, 2) attn_mma(const float* __restrict__ mask)
{
    extern __shared__ char smraw[];
    uint32_t sb = (uint32_t)__cvta_generic_to_shared(smraw);
    int tid = threadIdx.x, lane = tid & 31, wid = tid >> 5;
    int warpM = wid >> 1, warpN = wid & 1;
    int b = blockIdx.z, h = blockIdx.y, i0 = blockIdx.x * 64;
    int grp = lane >> 2, tL = lane & 3;
    int t8 = lane >> 3, r8 = lane & 7;

    {
        #pragma unroll
        for (int i = 0; i < 4; i++) {
            int g = tid + i*256;
            int mtx = g >> 9, r = (g >> 3) & 63, q = g & 7;
            const __nv_bfloat16* src = (mtx ? d_ql : d_qh) +
                (size_t)(b*Nn + i0 + r)*CS + h*HD + q*8;
            CPA(sb + mtx*9216 + r*144 + q*16, src);
        }
        #pragma unroll
        for (int i = 0; i < 8; i++) {
            int g = tid + i*256;
            int mtx = g >> 9, r = (g >> 3) & 63, q = g & 7;
            const __nv_bfloat16* src =
                (mtx == 0 ? d_kh : mtx == 1 ? d_kl : mtx == 2 ? d_vh : d_vl) +
                (size_t)(b*Nn + r)*CS + h*HD + q*8;
            CPA(sb + KV0 + mtx*9216 + r*144 + q*16, src);
        }
        CPCOMMIT();
    }

    float Oa[8][4];
    #pragma unroll
    for (int t = 0; t < 8; t++) { Oa[t][0]=0.f; Oa[t][1]=0.f; Oa[t][2]=0.f; Oa[t][3]=0.f; }
    float mrow0 = -1e30f, mrow1 = -1e30f, lsum0 = 0.f, lsum1 = 0.f;

    const float* maskp = mask + b*Nn;
    const float* biasbase = d_bias + ((size_t)(b*NH + h)*Nn + (i0 + warpM*16 + grp))*Nn;

    int aRow  = warpM*16 + (t8 & 1)*8 + r8;
    int aCol  = (t8 >> 1)*8;
    int kRowB = warpN*32 + (t8 >> 1)*8 + r8;
    int kColB = (t8 & 1)*8;
    int vRowB = (t8 & 1)*8 + r8;
    int vColB = (t8 >> 1)*8;

    #pragma unroll 1
    for (int jt = 0; jt < 12; jt++) {
        int j0c = jt * 64;
        __syncthreads();
        if (jt + 1 < 12) {
            int st1 = (jt + 1) & 1;
            #pragma unroll
            for (int i = 0; i < 8; i++) {
                int g = tid + i*256;
                int mtx = g >> 9, r = (g >> 3) & 63, q = g & 7;
                const __nv_bfloat16* src =
                    (mtx == 0 ? d_kh : mtx == 1 ? d_kl : mtx == 2 ? d_vh : d_vl) +
                    (size_t)(b*Nn + j0c + 64 + r)*CS + h*HD + q*8;
                CPA(sb + KV0 + st1*KVSTAGE + mtx*9216 + r*144 + q*16, src);
            }
        }
        CPCOMMIT();
        CPWAIT1();
        __syncthreads();

        uint32_t ks = sb + KV0 + (jt & 1)*KVSTAGE;

        float S[4][4];
        #pragma unroll
        for (int nt = 0; nt < 4; nt++) { S[nt][0]=0.f; S[nt][1]=0.f; S[nt][2]=0.f; S[nt][3]=0.f; }
        #pragma unroll
        for (int kk = 0; kk < 4; kk++) {
            uint32_t qh_[4], ql_[4], khf[2][4], klf[2][4];
            uint32_t aoff = (uint32_t)((aRow*AT_STRIDE + kk*16 + aCol) * 2);
            ldsm4(qh_, sb + AQ_H + aoff);
            ldsm4(ql_, sb + AQ_L + aoff);
            uint32_t koff0 = (uint32_t)((kRowB*AT_STRIDE + kk*16 + kColB) * 2);
            uint32_t koff1 = (uint32_t)(((kRowB+16)*AT_STRIDE + kk*16 + kColB) * 2);
            ldsm4(khf[0], ks + koff0);
            ldsm4(khf[1], ks + koff1);
            #pragma unroll
            for (int nt = 0; nt < 4; nt++)
                mma_bf16(S[nt], qh_, &khf[nt >> 1][(nt & 1)*2]);
            #pragma unroll
            for (int nt = 0; nt < 4; nt++)
                mma_bf16(S[nt], ql_, &khf[nt >> 1][(nt & 1)*2]);
            ldsm4(klf[0], ks + 9216 + koff0);
            ldsm4(klf[1], ks + 9216 + koff1);
            #pragma unroll
            for (int nt = 0; nt < 4; nt++)
                mma_bf16(S[nt], qh_, &klf[nt >> 1][(nt & 1)*2]);
        }

        #pragma unroll
        for (int nt = 0; nt < 4; nt++) {
            int jc = j0c + warpN*32 + nt*8 + tL*2;
            float2 b0 = *(const float2*)(biasbase + jc);
            float2 b1 = *(const float2*)(biasbase + (size_t)8*Nn + jc);
            float2 mv = *(const float2*)(maskp + jc);
            float mk0 = (1.f - mv.x) * (-1000000.0f);
            float mk1 = (1.f - mv.y) * (-1000000.0f);
            S[nt][0] += b0.x + mk0; S[nt][1] += b0.y + mk1;
            S[nt][2] += b1.x + mk0; S[nt][3] += b1.y + mk1;
        }

        float cm0 = fmaxf(fmaxf(S[0][0], S[0][1]), fmaxf(S[1][0], S[1][1]));
        cm0 = fmaxf(cm0, fmaxf(fmaxf(S[2][0], S[2][1]), fmaxf(S[3][0], S[3][1])));
        float cm1 = fmaxf(fmaxf(S[0][2], S[0][3]), fmaxf(S[1][2], S[1][3]));
        cm1 = fmaxf(cm1, fmaxf(fmaxf(S[2][2], S[2][3]), fmaxf(S[3][2], S[3][3])));
        cm0 = fmaxf(cm0, __shfl_xor_sync(0xFFFFFFFFu, cm0, 1));
        cm0 = fmaxf(cm0, __shfl_xor_sync(0xFFFFFFFFu, cm0, 2));
        cm1 = fmaxf(cm1, __shfl_xor_sync(0xFFFFFFFFu, cm1, 1));
        cm1 = fmaxf(cm1, __shfl_xor_sync(0xFFFFFFFFu, cm1, 2));
        float mn0 = fmaxf(mrow0, cm0), mn1 = fmaxf(mrow1, cm1);
        float sc0 = __expf(mrow0 - mn0), sc1 = __expf(mrow1 - mn1);
        mrow0 = mn0; mrow1 = mn1;
        float rs0 = 0.f, rs1 = 0.f;
        #pragma unroll
        for (int nt = 0; nt < 4; nt++) {
            S[nt][0] = __expf(S[nt][0] - mn0);
            S[nt][1] = __expf(S[nt][1] - mn0);
            S[nt][2] = __expf(S[nt][2] - mn1);
            S[nt][3] = __expf(S[nt][3] - mn1);
            rs0 += S[nt][0] + S[nt][1];
            rs1 += S[nt][2] + S[nt][3];
        }
        rs0 += __shfl_xor_sync(0xFFFFFFFFu, rs0, 1);
        rs0 += __shfl_xor_sync(0xFFFFFFFFu, rs0, 2);
        rs1 += __shfl_xor_sync(0xFFFFFFFFu, rs1, 1);
        rs1 += __shfl_xor_sync(0xFFFFFFFFu, rs1, 2);
        lsum0 = lsum0*sc0 + rs0;
        lsum1 = lsum1*sc1 + rs1;
        #pragma unroll
        for (int t = 0; t < 8; t++) {
            Oa[t][0] *= sc0; Oa[t][1] *= sc0;
            Oa[t][2] *= sc1; Oa[t][3] *= sc1;
        }

        uint32_t Ph[2][4], Pl[2][4];
        #pragma unroll
        for (int kf = 0; kf < 2; kf++) {
            split2(S[2*kf][0],   S[2*kf][1],   Ph[kf][0], Pl[kf][0]);
            split2(S[2*kf][2],   S[2*kf][3],   Ph[kf][1], Pl[kf][1]);
            split2(S[2*kf+1][0], S[2*kf+1][1], Ph[kf][2], Pl[kf][2]);
            split2(S[2*kf+1][2], S[2*kf+1][3], Ph[kf][3], Pl[kf][3]);
        }

        #pragma unroll
        for (int kf = 0; kf < 2; kf++) {
            int kb = warpN*32 + kf*16;
            #pragma unroll
            for (int ntp = 0; ntp < 4; ntp++) {
                uint32_t vhf[4], vlf[4];
                uint32_t voff = (uint32_t)(((kb + vRowB)*AT_STRIDE + ntp*16 + vColB) * 2);
                ldsm4t(vhf, ks + 18432 + voff);
                ldsm4t(vlf, ks + 27648 + voff);
                mma_bf16(Oa[ntp*2],   Ph[kf], &vhf[0]);
                mma_bf16(Oa[ntp*2+1], Ph[kf], &vhf[2]);
                mma_bf16(Oa[ntp*2],   Pl[kf], &vhf[0]);
                mma_bf16(Oa[ntp*2+1], Pl[kf], &vhf[2]);
                mma_bf16(Oa[ntp*2],   Ph[kf], &vlf[0]);
                mma_bf16(Oa[ntp*2+1], Ph[kf], &vlf[2]);
            }
        }
    }

    __syncthreads();
    float* Osm  = (float*)(smraw + OSM_OFF);
    float* stat = (float*)(smraw + STAT_OFF);
    #pragma unroll
    for (int t = 0; t < 8; t++) {
        int dcol = t*8 + tL*2;
        Osm[(wid*16 + grp)*OSM_STRIDE + dcol]       = Oa[t][0];
        Osm[(wid*16 + grp)*OSM_STRIDE + dcol + 1]   = Oa[t][1];
        Osm[(wid*16 + grp+8)*OSM_STRIDE + dcol]     = Oa[t][2];
        Osm[(wid*16 + grp+8)*OSM_STRIDE + dcol + 1] = Oa[t][3];
    }
    if (tL == 0) {
        stat[wid*32 + grp*2]       = mrow0;
        stat[wid*32 + grp*2 + 1]   = lsum0;
        stat[wid*32 + (grp+8)*2]     = mrow1;
        stat[wid*32 + (grp+8)*2 + 1] = lsum1;
    }
    __syncthreads();

    for (int t = tid; t < 64*32; t += 256) {
        int row = t >> 5, d2 = (t & 31)*2;
        int w0 = (row >> 4)*2, rl = row & 15;
        float m0 = stat[w0*32 + rl*2],     l0 = stat[w0*32 + rl*2 + 1];
        float m1 = stat[(w0+1)*32 + rl*2], l1 = stat[(w0+1)*32 + rl*2 + 1];
        float mm = fmaxf(m0, m1);
        float a0 = __expf(m0 - mm), a1 = __expf(m1 - mm);
        float inv = 1.f / (a0*l0 + a1*l1);
        float o0 = (a0*Osm[(w0*16 + rl)*OSM_STRIDE + d2] +
                    a1*Osm[((w0+1)*16 + rl)*OSM_STRIDE + d2]) * inv;
        float o1 = (a0*Osm[(w0*16 + rl)*OSM_STRIDE + d2 + 1] +
                    a1*Osm[((w0+1)*16 + rl)*OSM_STRIDE + d2 + 1]) * inv;
        size_t gi = (size_t)(b*Nn + i0 + row)*CS + h*HD + d2;
        float2 gg = *(const float2*)(d_g + gi);
        uint32_t hh, ll;
        split2(gg.x * o0, gg.y * o1, hh, ll);
        *(uint32_t*)((char*)d_goh + gi*2) = hh;
        *(uint32_t*)((char*)d_gol + gi*2) = ll;
    }
}

// ---------------- launch: fork bias chain onto a second stream ----------------
extern "C" void kernel_launch(void* const* d_in, const int* in_sizes, int n_in,
                              void* d_out, int out_size)
{
    const float* s    = (const float*)d_in[0];
    const float* z    = (const float*)d_in[1];
    const float* mask = (const float*)d_in[2];
    const float* k_in = (const float*)d_in[3];
    const float* Wq   = (const float*)d_in[4];
    const float* bq   = (const float*)d_in[5];
    const float* Wk   = (const float*)d_in[6];
    const float* Wv   = (const float*)d_in[7];
    const float* Wg   = (const float*)d_in[8];
    const float* ln_g = (const float*)d_in[9];
    const float* ln_b = (const float*)d_in[10];
    const float* Wz   = (const float*)d_in[11];
    const float* Wo   = (const float*)d_in[12];
    float* out = (float*)d_out;

    static cudaStream_t s2 = nullptr;
    static cudaEvent_t evF = nullptr, evJ = nullptr;
    if (s2 == nullptr) {
        cudaStreamCreateWithFlags(&s2, cudaStreamNonBlocking);
        cudaEventCreateWithFlags(&evF, cudaEventDisableTiming);
        cudaEventCreateWithFlags(&evJ, cudaEventDisableTiming);
        cudaFuncSetAttribute(proj4_kernel, cudaFuncAttributeMaxDynamicSharedMemorySize, GEMM_SMEM);
        cudaFuncSetAttribute(final_gemm,   cudaFuncAttributeMaxDynamicSharedMemorySize, GEMM_SMEM);
        cudaFuncSetAttribute(attn_mma,     cudaFuncAttributeMaxDynamicSharedMemorySize, ATT_SMEM);
        cudaFuncSetAttribute(bias_mma,     cudaFuncAttributeMaxDynamicSharedMemorySize, BIAS_SMEM);
    }

    // fork: stream B = prep + bias_mma (DRAM/scalar bound)
    cudaEventRecord(evF, 0);
    cudaStreamWaitEvent(s2, evF, 0);
    prep_kernel<<<1, 128, 0, s2>>>(ln_g, ln_b, Wz);
    bias_mma<<<NPAIR/128, 256, BIAS_SMEM, s2>>>(z);
    cudaEventRecord(evJ, s2);

    // stream A (capture stream) = conversions + projections (tensor bound)
    wconv_kernel<<<dim3(WSZ/1024, 5), 256>>>(Wq, Wk, Wv, Wg, Wo);
    aconv_kernel<<<dim3(MROWS*CS/1024, 2), 256>>>(s, k_in);
    proj4_kernel<<<dim3(CS/64, MROWS/128, 4), 256, GEMM_SMEM>>>(bq);

    // join, then attention + output projection
    cudaStreamWaitEvent(0, evJ, 0);
    attn_mma<<<dim3(Nn/64, NH, Bn), 256, ATT_SMEM>>>(mask);
    final_gemm<<<dim3(CS/64, MROWS/128), 256, GEMM_SMEM>>>(out);
}

// round 9
// speedup vs baseline: 2.4914x; 1.0093x over previous
#include <cuda_runtime.h>
#include <cuda_bf16.h>
#include <cstdint>
#include <cstddef>

#define Bn 2
#define Nn 768
#define CS 1024
#define CZ 128
#define NH 16
#define HD 64
#define MROWS (Bn*Nn)     // 1536
#define NPAIR (Bn*Nn*Nn)  // 1179648
#define WSZ (CS*CS)

// ---------------- scratch (device globals; no allocations allowed) ----------------
__device__ __nv_bfloat16 d_Wh[5*WSZ], d_Wl[5*WSZ];          // Wq,Wk,Wv,Wg,Wo split
__device__ __nv_bfloat16 d_inh[2*MROWS*CS], d_inl[2*MROWS*CS]; // s, k_in split
__device__ __nv_bfloat16 d_qh[MROWS*CS], d_ql[MROWS*CS];
__device__ __nv_bfloat16 d_kh[MROWS*CS], d_kl[MROWS*CS];
__device__ __nv_bfloat16 d_vh[MROWS*CS], d_vl[MROWS*CS];
__device__ __nv_bfloat16 d_goh[MROWS*CS], d_gol[MROWS*CS];
__device__ float d_g[MROWS*CS];
__device__ float d_bias[Bn*NH*Nn*Nn];     // 75.5 MB
__device__ float d_Gz[CZ*NH];
__device__ float d_Bh[NH];
__device__ float d_GzSum[NH];

// ================= helpers ====================
__device__ __forceinline__ void ldsm4(uint32_t* r, uint32_t a) {
    asm volatile("ldmatrix.sync.aligned.m8n8.x4.shared.b16 {%0,%1,%2,%3}, [%4];"
                 : "=r"(r[0]), "=r"(r[1]), "=r"(r[2]), "=r"(r[3]) : "r"(a));
}
__device__ __forceinline__ void ldsm4t(uint32_t* r, uint32_t a) {
    asm volatile("ldmatrix.sync.aligned.m8n8.x4.trans.shared.b16 {%0,%1,%2,%3}, [%4];"
                 : "=r"(r[0]), "=r"(r[1]), "=r"(r[2]), "=r"(r[3]) : "r"(a));
}
__device__ __forceinline__ void mma_bf16(float* c, const uint32_t* a, const uint32_t* b) {
    asm volatile("mma.sync.aligned.m16n8k16.row.col.f32.bf16.bf16.f32 "
                 "{%0,%1,%2,%3}, {%4,%5,%6,%7}, {%8,%9}, {%0,%1,%2,%3};"
                 : "+f"(c[0]), "+f"(c[1]), "+f"(c[2]), "+f"(c[3])
                 : "r"(a[0]), "r"(a[1]), "r"(a[2]), "r"(a[3]), "r"(b[0]), "r"(b[1]));
}
__device__ __forceinline__ void split2(float x, float y, uint32_t& hi, uint32_t& lo) {
    __nv_bfloat162 h = __float22bfloat162_rn(make_float2(x, y));
    float2 hf = __bfloat1622float2(h);
    __nv_bfloat162 l = __float22bfloat162_rn(make_float2(x - hf.x, y - hf.y));
    hi = *(uint32_t*)&h;
    lo = *(uint32_t*)&l;
}
#define CPA(dst, src) asm volatile("cp.async.cg.shared.global [%0], [%1], 16;" :: "r"(dst), "l"(src))
#define CPCOMMIT()    asm volatile("cp.async.commit_group;")
#define CPWAIT1()     asm volatile("cp.async.wait_group 1;")

// ---------------- pre-split converters ----------------
__global__ void __launch_bounds__(256) wconv_kernel(
    const float* __restrict__ W0, const float* __restrict__ W1,
    const float* __restrict__ W2, const float* __restrict__ W3,
    const float* __restrict__ W4)
{
    int which = blockIdx.y;
    const float* src = which == 0 ? W0 : which == 1 ? W1 : which == 2 ? W2 :
                       which == 3 ? W3 : W4;
    size_t idx = ((size_t)blockIdx.x * 256 + threadIdx.x) * 4;
    float4 v = *(const float4*)(src + idx);
    uint32_t h0, l0, h1, l1;
    split2(v.x, v.y, h0, l0);
    split2(v.z, v.w, h1, l1);
    size_t o = (size_t)which * WSZ + idx;
    *(uint2*)((char*)d_Wh + o*2) = make_uint2(h0, h1);
    *(uint2*)((char*)d_Wl + o*2) = make_uint2(l0, l1);
}
__global__ void __launch_bounds__(256) aconv_kernel(
    const float* __restrict__ A0, const float* __restrict__ A1)
{
    int which = blockIdx.y;
    const float* src = which == 0 ? A0 : A1;
    size_t idx = ((size_t)blockIdx.x * 256 + threadIdx.x) * 4;
    float4 v = *(const float4*)(src + idx);
    uint32_t h0, l0, h1, l1;
    split2(v.x, v.y, h0, l0);
    split2(v.z, v.w, h1, l1);
    size_t o = (size_t)which * MROWS * CS + idx;
    *(uint2*)((char*)d_inh + o*2) = make_uint2(h0, h1);
    *(uint2*)((char*)d_inl + o*2) = make_uint2(l0, l1);
}

// ================= GEMM: pre-split bf16 inputs, cp.async 3-stage =====
#define ASTRIDE 40
#define BSTRIDE 72
#define AHI_OFF 0
#define ALO_OFF 10240
#define BHI_OFF 20480
#define BLO_OFF 25088
#define BUFBYTES 29696
#define GEMM_SMEM (3*BUFBYTES)   // 89088

__device__ __forceinline__ void gemm_core(
    const __nv_bfloat16* __restrict__ Ah, const __nv_bfloat16* __restrict__ Al,
    const __nv_bfloat16* __restrict__ Bh, const __nv_bfloat16* __restrict__ Bl,
    const float* __restrict__ bq, int mode,
    float* __restrict__ Cf, __nv_bfloat16* __restrict__ Ch, __nv_bfloat16* __restrict__ Cl)
{
    extern __shared__ char sm_raw[];
    uint32_t sbase = (uint32_t)__cvta_generic_to_shared(sm_raw);

    int tid = threadIdx.x;
    int wid = tid >> 5, lane = tid & 31;
    int warpM = wid >> 1, warpN = wid & 1;
    int m0 = blockIdx.y * 128, n0 = blockIdx.x * 64;

    float acc[2][4][4];
    #pragma unroll
    for (int mt = 0; mt < 2; mt++)
        #pragma unroll
        for (int nt = 0; nt < 4; nt++)
            #pragma unroll
            for (int i = 0; i < 4; i++) acc[mt][nt][i] = 0.f;

    int matr = lane >> 3, rr = lane & 7;
    int aRowBase = warpM * 32 + (matr & 1) * 8 + rr;
    int aColBase = (matr >> 1) * 8;
    int bRowBase = (matr & 1) * 8 + rr;
    int bColBase = warpN * 32 + (matr >> 1) * 8;

    int arow = tid >> 2, aq = tid & 3;
    int brow = tid >> 3, bqc = tid & 7;

    auto issue = [&](int c, int buf) {
        uint32_t st = sbase + buf * BUFBYTES;
        #pragma unroll
        for (int r = 0; r < 2; r++) {
            int row = arow + r * 64;
            const __nv_bfloat16* sh = Ah + (size_t)(m0 + row) * CS + c * 32 + aq * 8;
            const __nv_bfloat16* sl = Al + (size_t)(m0 + row) * CS + c * 32 + aq * 8;
            uint32_t d = st + row * 80 + aq * 16;
            CPA(d + AHI_OFF, sh);
            CPA(d + ALO_OFF, sl);
        }
        {
            const __nv_bfloat16* sh = Bh + (size_t)(c * 32 + brow) * CS + n0 + bqc * 8;
            const __nv_bfloat16* sl = Bl + (size_t)(c * 32 + brow) * CS + n0 + bqc * 8;
            uint32_t d = st + brow * 144 + bqc * 16;
            CPA(d + BHI_OFF, sh);
            CPA(d + BLO_OFF, sl);
        }
    };

    issue(0, 0); CPCOMMIT();
    issue(1, 1); CPCOMMIT();

    const int CHUNKS = 32;
    for (int c = 0; c < CHUNKS; c++) {
        CPWAIT1();
        __syncthreads();
        if (c + 2 < CHUNKS) issue(c + 2, (c + 2) % 3);
        CPCOMMIT();

        uint32_t off = sbase + (c % 3) * BUFBYTES;
        #pragma unroll
        for (int ks = 0; ks < 32; ks += 16) {
            uint32_t Ahf[2][4], Alf[2][4], Bhf[2][4], Blf[2][4];
            #pragma unroll
            for (int mt = 0; mt < 2; mt++)
                ldsm4(Ahf[mt], off + AHI_OFF +
                      (((aRowBase + mt * 16) * ASTRIDE) + aColBase + ks) * 2);
            #pragma unroll
            for (int ntp = 0; ntp < 2; ntp++)
                ldsm4t(Bhf[ntp], off + BHI_OFF +
                       (((bRowBase + ks) * BSTRIDE) + bColBase + ntp * 16) * 2);
            #pragma unroll
            for (int mt = 0; mt < 2; mt++)
                #pragma unroll
                for (int nt = 0; nt < 4; nt++)
                    mma_bf16(acc[mt][nt], Ahf[mt], &Bhf[nt >> 1][(nt & 1) * 2]);
            #pragma unroll
            for (int mt = 0; mt < 2; mt++)
                ldsm4(Alf[mt], off + ALO_OFF +
                      (((aRowBase + mt * 16) * ASTRIDE) + aColBase + ks) * 2);
            #pragma unroll
            for (int mt = 0; mt < 2; mt++)
                #pragma unroll
                for (int nt = 0; nt < 4; nt++)
                    mma_bf16(acc[mt][nt], Alf[mt], &Bhf[nt >> 1][(nt & 1) * 2]);
            #pragma unroll
            for (int ntp = 0; ntp < 2; ntp++)
                ldsm4t(Blf[ntp], off + BLO_OFF +
                       (((bRowBase + ks) * BSTRIDE) + bColBase + ntp * 16) * 2);
            #pragma unroll
            for (int mt = 0; mt < 2; mt++)
                #pragma unroll
                for (int nt = 0; nt < 4; nt++)
                    mma_bf16(acc[mt][nt], Ahf[mt], &Blf[nt >> 1][(nt & 1) * 2]);
        }
    }

    int grp = lane >> 2, tL = lane & 3;
    #pragma unroll
    for (int mt = 0; mt < 2; mt++) {
        #pragma unroll
        for (int nt = 0; nt < 4; nt++) {
            int row = m0 + warpM * 32 + mt * 16 + grp;
            int col = n0 + warpN * 32 + nt * 8 + tL * 2;
            float v0 = acc[mt][nt][0], v1 = acc[mt][nt][1];
            float v2 = acc[mt][nt][2], v3 = acc[mt][nt][3];
            if (mode == 0) {
                float b0 = bq[col], b1 = bq[col + 1];
                v0 = (v0 + b0) * 0.125f; v1 = (v1 + b1) * 0.125f;
                v2 = (v2 + b0) * 0.125f; v3 = (v3 + b1) * 0.125f;
            }
            if (mode == 3) {
                v0 = 1.f/(1.f + __expf(-v0)); v1 = 1.f/(1.f + __expf(-v1));
                v2 = 1.f/(1.f + __expf(-v2)); v3 = 1.f/(1.f + __expf(-v3));
                *(float2*)(Cf + (size_t)row * CS + col)       = make_float2(v0, v1);
                *(float2*)(Cf + (size_t)(row + 8) * CS + col) = make_float2(v2, v3);
            } else if (mode == 4) {
                *(float2*)(Cf + (size_t)row * CS + col)       = make_float2(v0, v1);
                *(float2*)(Cf + (size_t)(row + 8) * CS + col) = make_float2(v2, v3);
            } else {
                uint32_t h0, l0, h1, l1;
                split2(v0, v1, h0, l0);
                split2(v2, v3, h1, l1);
                *(uint32_t*)((char*)Ch + ((size_t)row * CS + col) * 2)       = h0;
                *(uint32_t*)((char*)Cl + ((size_t)row * CS + col) * 2)       = l0;
                *(uint32_t*)((char*)Ch + ((size_t)(row + 8) * CS + col) * 2) = h1;
                *(uint32_t*)((char*)Cl + ((size_t)(row + 8) * CS + col) * 2) = l1;
            }
        }
    }
}

__global__ void __launch_bounds__(256) proj4_kernel(const float* __restrict__ bq)
{
    int which = blockIdx.z;
    const __nv_bfloat16* Ah = (which == 0 || which == 3) ? d_inh : d_inh + MROWS*CS;
    const __nv_bfloat16* Al = (which == 0 || which == 3) ? d_inl : d_inl + MROWS*CS;
    const __nv_bfloat16* Bh = d_Wh + (size_t)which * WSZ;
    const __nv_bfloat16* Bl = d_Wl + (size_t)which * WSZ;
    __nv_bfloat16* Ch = which == 0 ? d_qh : which == 1 ? d_kh : which == 2 ? d_vh : nullptr;
    __nv_bfloat16* Cl = which == 0 ? d_ql : which == 1 ? d_kl : which == 2 ? d_vl : nullptr;
    gemm_core(Ah, Al, Bh, Bl, bq, which == 3 ? 3 : which, d_g, Ch, Cl);
}

__global__ void __launch_bounds__(256) final_gemm(float* __restrict__ out)
{
    gemm_core(d_goh, d_gol, d_Wh + 4*(size_t)WSZ, d_Wl + 4*(size_t)WSZ,
              nullptr, 4, out, nullptr, nullptr);
}

// ---------------- fold LN affine into z-projection ----------------
__global__ void prep_kernel(const float* __restrict__ ln_g,
                            const float* __restrict__ ln_b,
                            const float* __restrict__ Wz)
{
    __shared__ float sB[CZ*NH];
    __shared__ float sG[CZ*NH];
    int c = threadIdx.x;
    float g = ln_g[c], bb = ln_b[c];
    #pragma unroll
    for (int h = 0; h < NH; h++) {
        float w = Wz[c*NH + h];
        float gz = g*w;
        d_Gz[c*NH + h] = gz;
        sG[c*NH + h] = gz;
        sB[c*NH + h] = bb*w;
    }
    __syncthreads();
    if (c < NH) {
        float sb = 0.f, sg = 0.f;
        for (int cc = 0; cc < CZ; cc++) { sb += sB[cc*NH + c]; sg += sG[cc*NH + c]; }
        d_Bh[c] = sb;
        d_GzSum[c] = sg;
    }
}

// ====== bias: LN+proj as tensor-core GEMM ======
#define ZROW 136
#define BZ_ZH 0
#define BZ_ZL 34816
#define BZ_GH 69632
#define BZ_GL 75776
#define BZ_ST 81920
#define BZ_SG 82944
#define BIAS_SMEM 91648

__global__ void __launch_bounds__(256) bias_mma(const float* __restrict__ z)
{
    extern __shared__ char smraw[];
    uint32_t sb = (uint32_t)__cvta_generic_to_shared(smraw);
    int tid = threadIdx.x, lane = tid & 31, wid = tid >> 5;

    for (int t = tid; t < CZ*NH; t += 256) {
        int c = t >> 4, h = t & 15;
        float w = d_Gz[t];
        __nv_bfloat16 hi = __float2bfloat16(w);
        __nv_bfloat16 lo = __float2bfloat16(w - __bfloat162float(hi));
        ((__nv_bfloat16*)(smraw + BZ_GH))[c*24 + h] = hi;
        ((__nv_bfloat16*)(smraw + BZ_GL))[c*24 + h] = lo;
    }

    int row = tid >> 1, half = tid & 1;
    {
        const float* zr = z + (size_t)(blockIdx.x*128 + row)*CZ + half*64;
        uint32_t* zh = (uint32_t*)(smraw + BZ_ZH);
        uint32_t* zl = (uint32_t*)(smraw + BZ_ZL);
        float s1 = 0.f, s2 = 0.f;
        #pragma unroll
        for (int f = 0; f < 16; f++) {
            float4 v = *(const float4*)(zr + f*4);
            s1 += (v.x + v.y) + (v.z + v.w);
            s2 = fmaf(v.x, v.x, s2); s2 = fmaf(v.y, v.y, s2);
            s2 = fmaf(v.z, v.z, s2); s2 = fmaf(v.w, v.w, s2);
            uint32_t h0, l0, h1, l1;
            split2(v.x, v.y, h0, l0);
            split2(v.z, v.w, h1, l1);
            int e0 = (row*ZROW + half*64 + f*4) >> 1;
            zh[e0] = h0; zh[e0+1] = h1;
            zl[e0] = l0; zl[e0+1] = l1;
        }
        s1 += __shfl_xor_sync(0xFFFFFFFFu, s1, 1);
        s2 += __shfl_xor_sync(0xFFFFFFFFu, s2, 1);
        if (half == 0) {
            float mu  = s1 * (1.f/128.f);
            float var = s2 * (1.f/128.f) - mu*mu;
            ((float2*)(smraw + BZ_ST))[row] = make_float2(mu, rsqrtf(var + 1e-5f));
        }
    }
    __syncthreads();

    int t8 = lane >> 3, r8 = lane & 7;
    int aRow = wid*16 + (t8 & 1)*8 + r8;
    int aCol = (t8 >> 1)*8;
    int gRow = (t8 & 1)*8 + r8;
    int gCol = (t8 >> 1)*8;

    float acc0[4] = {0.f,0.f,0.f,0.f}, acc1[4] = {0.f,0.f,0.f,0.f};
    #pragma unroll
    for (int kc = 0; kc < 8; kc++) {
        uint32_t Ahf[4], Alf[4], Gh[4], Gl[4];
        uint32_t aoff = (uint32_t)((aRow*ZROW + kc*16 + aCol) * 2);
        uint32_t goff = (uint32_t)(((gRow + kc*16)*24 + gCol) * 2);
        ldsm4(Ahf, sb + BZ_ZH + aoff);
        ldsm4(Alf, sb + BZ_ZL + aoff);
        ldsm4t(Gh, sb + BZ_GH + goff);
        ldsm4t(Gl, sb + BZ_GL + goff);
        mma_bf16(acc0, Ahf, &Gh[0]); mma_bf16(acc1, Ahf, &Gh[2]);
        mma_bf16(acc0, Alf, &Gh[0]); mma_bf16(acc1, Alf, &Gh[2]);
        mma_bf16(acc0, Ahf, &Gl[0]); mma_bf16(acc1, Ahf, &Gl[2]);
    }

    {
        int grp = lane >> 2, tL = lane & 3;
        int r0 = wid*16 + grp, r1 = r0 + 8;
        float2 st0 = ((float2*)(smraw + BZ_ST))[r0];
        float2 st1 = ((float2*)(smraw + BZ_ST))[r1];
        float* stage = (float*)(smraw + BZ_SG);
        #pragma unroll
        for (int n = 0; n < 2; n++) {
            float* a = n ? acc1 : acc0;
            int h = n*8 + tL*2;
            float gs0 = d_GzSum[h], gs1 = d_GzSum[h+1];
            float bh0 = d_Bh[h],    bh1 = d_Bh[h+1];
            stage[r0*17 + h]     = st0.y*(a[0] - st0.x*gs0) + bh0;
            stage[r0*17 + h + 1] = st0.y*(a[1] - st0.x*gs1) + bh1;
            stage[r1*17 + h]     = st1.y*(a[2] - st1.x*gs0) + bh0;
            stage[r1*17 + h + 1] = st1.y*(a[3] - st1.x*gs1) + bh1;
        }
    }
    __syncthreads();

    {
        int p0  = blockIdx.x * 128;
        int b   = p0 / (Nn*Nn);
        int rem = p0 % (Nn*Nn);
        int ii  = rem / Nn;
        int j0  = rem % Nn;
        float* stage = (float*)(smraw + BZ_SG);
        #pragma unroll
        for (int t = tid; t < 128*NH; t += 256) {
            int h = t >> 7, rr = t & 127;
            d_bias[((size_t)(b*NH + h)*Nn + ii)*Nn + j0 + rr] = stage[rr*17 + h];
        }
    }
}

// ========== flash attention: pre-split bf16 q/k/v, cp.async pipeline ==========
#define AT_STRIDE 72
#define AQ_H 0
#define AQ_L 9216
#define KV0 18432
#define KVSTAGE 36864
#define OSM_OFF 0
#define OSM_STRIDE 68
#define STAT_OFF 34816
#define ATT_SMEM 92160

__global__ void __launch_bounds__(256, 2) attn_mma(const float* __restrict__ mask)
{
    extern __shared__ char smraw[];
    uint32_t sb = (uint32_t)__cvta_generic_to_shared(smraw);
    int tid = threadIdx.x, lane = tid & 31, wid = tid >> 5;
    int warpM = wid >> 1, warpN = wid & 1;
    int b = blockIdx.z, h = blockIdx.y, i0 = blockIdx.x * 64;
    int grp = lane >> 2, tL = lane & 3;
    int t8 = lane >> 3, r8 = lane & 7;

    {
        #pragma unroll
        for (int i = 0; i < 4; i++) {
            int g = tid + i*256;
            int mtx = g >> 9, r = (g >> 3) & 63, q = g & 7;
            const __nv_bfloat16* src = (mtx ? d_ql : d_qh) +
                (size_t)(b*Nn + i0 + r)*CS + h*HD + q*8;
            CPA(sb + mtx*9216 + r*144 + q*16, src);
        }
        #pragma unroll
        for (int i = 0; i < 8; i++) {
            int g = tid + i*256;
            int mtx = g >> 9, r = (g >> 3) & 63, q = g & 7;
            const __nv_bfloat16* src =
                (mtx == 0 ? d_kh : mtx == 1 ? d_kl : mtx == 2 ? d_vh : d_vl) +
                (size_t)(b*Nn + r)*CS + h*HD + q*8;
            CPA(sb + KV0 + mtx*9216 + r*144 + q*16, src);
        }
        CPCOMMIT();
    }

    float Oa[8][4];
    #pragma unroll
    for (int t = 0; t < 8; t++) { Oa[t][0]=0.f; Oa[t][1]=0.f; Oa[t][2]=0.f; Oa[t][3]=0.f; }
    float mrow0 = -1e30f, mrow1 = -1e30f, lsum0 = 0.f, lsum1 = 0.f;

    const float* maskp = mask + b*Nn;
    const float* biasbase = d_bias + ((size_t)(b*NH + h)*Nn + (i0 + warpM*16 + grp))*Nn;

    int aRow  = warpM*16 + (t8 & 1)*8 + r8;
    int aCol  = (t8 >> 1)*8;
    int kRowB = warpN*32 + (t8 >> 1)*8 + r8;
    int kColB = (t8 & 1)*8;
    int vRowB = (t8 & 1)*8 + r8;
    int vColB = (t8 >> 1)*8;

    #pragma unroll 1
    for (int jt = 0; jt < 12; jt++) {
        int j0c = jt * 64;
        __syncthreads();
        if (jt + 1 < 12) {
            int st1 = (jt + 1) & 1;
            #pragma unroll
            for (int i = 0; i < 8; i++) {
                int g = tid + i*256;
                int mtx = g >> 9, r = (g >> 3) & 63, q = g & 7;
                const __nv_bfloat16* src =
                    (mtx == 0 ? d_kh : mtx == 1 ? d_kl : mtx == 2 ? d_vh : d_vl) +
                    (size_t)(b*Nn + j0c + 64 + r)*CS + h*HD + q*8;
                CPA(sb + KV0 + st1*KVSTAGE + mtx*9216 + r*144 + q*16, src);
            }
        }
        CPCOMMIT();
        CPWAIT1();
        __syncthreads();

        uint32_t ks = sb + KV0 + (jt & 1)*KVSTAGE;

        float S[4][4];
        #pragma unroll
        for (int nt = 0; nt < 4; nt++) { S[nt][0]=0.f; S[nt][1]=0.f; S[nt][2]=0.f; S[nt][3]=0.f; }
        #pragma unroll
        for (int kk = 0; kk < 4; kk++) {
            uint32_t qh_[4], ql_[4], khf[2][4], klf[2][4];
            uint32_t aoff = (uint32_t)((aRow*AT_STRIDE + kk*16 + aCol) * 2);
            ldsm4(qh_, sb + AQ_H + aoff);
            ldsm4(ql_, sb + AQ_L + aoff);
            uint32_t koff0 = (uint32_t)((kRowB*AT_STRIDE + kk*16 + kColB) * 2);
            uint32_t koff1 = (uint32_t)(((kRowB+16)*AT_STRIDE + kk*16 + kColB) * 2);
            ldsm4(khf[0], ks + koff0);
            ldsm4(khf[1], ks + koff1);
            #pragma unroll
            for (int nt = 0; nt < 4; nt++)
                mma_bf16(S[nt], qh_, &khf[nt >> 1][(nt & 1)*2]);
            #pragma unroll
            for (int nt = 0; nt < 4; nt++)
                mma_bf16(S[nt], ql_, &khf[nt >> 1][(nt & 1)*2]);
            ldsm4(klf[0], ks + 9216 + koff0);
            ldsm4(klf[1], ks + 9216 + koff1);
            #pragma unroll
            for (int nt = 0; nt < 4; nt++)
                mma_bf16(S[nt], qh_, &klf[nt >> 1][(nt & 1)*2]);
        }

        #pragma unroll
        for (int nt = 0; nt < 4; nt++) {
            int jc = j0c + warpN*32 + nt*8 + tL*2;
            float2 b0 = *(const float2*)(biasbase + jc);
            float2 b1 = *(const float2*)(biasbase + (size_t)8*Nn + jc);
            float2 mv = *(const float2*)(maskp + jc);
            float mk0 = (1.f - mv.x) * (-1000000.0f);
            float mk1 = (1.f - mv.y) * (-1000000.0f);
            S[nt][0] += b0.x + mk0; S[nt][1] += b0.y + mk1;
            S[nt][2] += b1.x + mk0; S[nt][3] += b1.y + mk1;
        }

        float cm0 = fmaxf(fmaxf(S[0][0], S[0][1]), fmaxf(S[1][0], S[1][1]));
        cm0 = fmaxf(cm0, fmaxf(fmaxf(S[2][0], S[2][1]), fmaxf(S[3][0], S[3][1])));
        float cm1 = fmaxf(fmaxf(S[0][2], S[0][3]), fmaxf(S[1][2], S[1][3]));
        cm1 = fmaxf(cm1, fmaxf(fmaxf(S[2][2], S[2][3]), fmaxf(S[3][2], S[3][3])));
        cm0 = fmaxf(cm0, __shfl_xor_sync(0xFFFFFFFFu, cm0, 1));
        cm0 = fmaxf(cm0, __shfl_xor_sync(0xFFFFFFFFu, cm0, 2));
        cm1 = fmaxf(cm1, __shfl_xor_sync(0xFFFFFFFFu, cm1, 1));
        cm1 = fmaxf(cm1, __shfl_xor_sync(0xFFFFFFFFu, cm1, 2));
        float mn0 = fmaxf(mrow0, cm0), mn1 = fmaxf(mrow1, cm1);
        float sc0 = __expf(mrow0 - mn0), sc1 = __expf(mrow1 - mn1);
        mrow0 = mn0; mrow1 = mn1;
        float rs0 = 0.f, rs1 = 0.f;
        #pragma unroll
        for (int nt = 0; nt < 4; nt++) {
            S[nt][0] = __expf(S[nt][0] - mn0);
            S[nt][1] = __expf(S[nt][1] - mn0);
            S[nt][2] = __expf(S[nt][2] - mn1);
            S[nt][3] = __expf(S[nt][3] - mn1);
            rs0 += S[nt][0] + S[nt][1];
            rs1 += S[nt][2] + S[nt][3];
        }
        rs0 += __shfl_xor_sync(0xFFFFFFFFu, rs0, 1);
        rs0 += __shfl_xor_sync(0xFFFFFFFFu, rs0, 2);
        rs1 += __shfl_xor_sync(0xFFFFFFFFu, rs1, 1);
        rs1 += __shfl_xor_sync(0xFFFFFFFFu, rs1, 2);
        lsum0 = lsum0*sc0 + rs0;
        lsum1 = lsum1*sc1 + rs1;
        #pragma unroll
        for (int t = 0; t < 8; t++) {
            Oa[t][0] *= sc0; Oa[t][1] *= sc0;
            Oa[t][2] *= sc1; Oa[t][3] *= sc1;
        }

        uint32_t Ph[2][4], Pl[2][4];
        #pragma unroll
        for (int kf = 0; kf < 2; kf++) {
            split2(S[2*kf][0],   S[2*kf][1],   Ph[kf][0], Pl[kf][0]);
            split2(S[2*kf][2],   S[2*kf][3],   Ph[kf][1], Pl[kf][1]);
            split2(S[2*kf+1][0], S[2*kf+1][1], Ph[kf][2], Pl[kf][2]);
            split2(S[2*kf+1][2], S[2*kf+1][3], Ph[kf][3], Pl[kf][3]);
        }

        #pragma unroll
        for (int kf = 0; kf < 2; kf++) {
            int kb = warpN*32 + kf*16;
            #pragma unroll
            for (int ntp = 0; ntp < 4; ntp++) {
                uint32_t vhf[4], vlf[4];
                uint32_t voff = (uint32_t)(((kb + vRowB)*AT_STRIDE + ntp*16 + vColB) * 2);
                ldsm4t(vhf, ks + 18432 + voff);
                ldsm4t(vlf, ks + 27648 + voff);
                mma_bf16(Oa[ntp*2],   Ph[kf], &vhf[0]);
                mma_bf16(Oa[ntp*2+1], Ph[kf], &vhf[2]);
                mma_bf16(Oa[ntp*2],   Pl[kf], &vhf[0]);
                mma_bf16(Oa[ntp*2+1], Pl[kf], &vhf[2]);
                mma_bf16(Oa[ntp*2],   Ph[kf], &vlf[0]);
                mma_bf16(Oa[ntp*2+1], Ph[kf], &vlf[2]);
            }
        }
    }

    __syncthreads();
    float* Osm  = (float*)(smraw + OSM_OFF);
    float* stat = (float*)(smraw + STAT_OFF);
    #pragma unroll
    for (int t = 0; t < 8; t++) {
        int dcol = t*8 + tL*2;
        Osm[(wid*16 + grp)*OSM_STRIDE + dcol]       = Oa[t][0];
        Osm[(wid*16 + grp)*OSM_STRIDE + dcol + 1]   = Oa[t][1];
        Osm[(wid*16 + grp+8)*OSM_STRIDE + dcol]     = Oa[t][2];
        Osm[(wid*16 + grp+8)*OSM_STRIDE + dcol + 1] = Oa[t][3];
    }
    if (tL == 0) {
        stat[wid*32 + grp*2]       = mrow0;
        stat[wid*32 + grp*2 + 1]   = lsum0;
        stat[wid*32 + (grp+8)*2]     = mrow1;
        stat[wid*32 + (grp+8)*2 + 1] = lsum1;
    }
    __syncthreads();

    for (int t = tid; t < 64*32; t += 256) {
        int row = t >> 5, d2 = (t & 31)*2;
        int w0 = (row >> 4)*2, rl = row & 15;
        float m0 = stat[w0*32 + rl*2],     l0 = stat[w0*32 + rl*2 + 1];
        float m1 = stat[(w0+1)*32 + rl*2], l1 = stat[(w0+1)*32 + rl*2 + 1];
        float mm = fmaxf(m0, m1);
        float a0 = __expf(m0 - mm), a1 = __expf(m1 - mm);
        float inv = 1.f / (a0*l0 + a1*l1);
        float o0 = (a0*Osm[(w0*16 + rl)*OSM_STRIDE + d2] +
                    a1*Osm[((w0+1)*16 + rl)*OSM_STRIDE + d2]) * inv;
        float o1 = (a0*Osm[(w0*16 + rl)*OSM_STRIDE + d2 + 1] +
                    a1*Osm[((w0+1)*16 + rl)*OSM_STRIDE + d2 + 1]) * inv;
        size_t gi = (size_t)(b*Nn + i0 + row)*CS + h*HD + d2;
        float2 gg = *(const float2*)(d_g + gi);
        uint32_t hh, ll;
        split2(gg.x * o0, gg.y * o1, hh, ll);
        *(uint32_t*)((char*)d_goh + gi*2) = hh;
        *(uint32_t*)((char*)d_gol + gi*2) = ll;
    }
}

// ---------------- launch: fork bias chain; submission order aims ncu at bias_mma ----------------
extern "C" void kernel_launch(void* const* d_in, const int* in_sizes, int n_in,
                              void* d_out, int out_size)
{
    const float* s    = (const float*)d_in[0];
    const float* z    = (const float*)d_in[1];
    const float* mask = (const float*)d_in[2];
    const float* k_in = (const float*)d_in[3];
    const float* Wq   = (const float*)d_in[4];
    const float* bq   = (const float*)d_in[5];
    const float* Wk   = (const float*)d_in[6];
    const float* Wv   = (const float*)d_in[7];
    const float* Wg   = (const float*)d_in[8];
    const float* ln_g = (const float*)d_in[9];
    const float* ln_b = (const float*)d_in[10];
    const float* Wz   = (const float*)d_in[11];
    const float* Wo   = (const float*)d_in[12];
    float* out = (float*)d_out;

    static cudaStream_t s2 = nullptr;
    static cudaEvent_t evF = nullptr, evJ = nullptr;
    if (s2 == nullptr) {
        cudaStreamCreateWithFlags(&s2, cudaStreamNonBlocking);
        cudaEventCreateWithFlags(&evF, cudaEventDisableTiming);
        cudaEventCreateWithFlags(&evJ, cudaEventDisableTiming);
        cudaFuncSetAttribute(proj4_kernel, cudaFuncAttributeMaxDynamicSharedMemorySize, GEMM_SMEM);
        cudaFuncSetAttribute(final_gemm,   cudaFuncAttributeMaxDynamicSharedMemorySize, GEMM_SMEM);
        cudaFuncSetAttribute(attn_mma,     cudaFuncAttributeMaxDynamicSharedMemorySize, ATT_SMEM);
        cudaFuncSetAttribute(bias_mma,     cudaFuncAttributeMaxDynamicSharedMemorySize, BIAS_SMEM);
    }

    // stream A first two launches (submission #1, #2)
    cudaEventRecord(evF, 0);
    cudaStreamWaitEvent(s2, evF, 0);
    wconv_kernel<<<dim3(WSZ/1024, 5), 256>>>(Wq, Wk, Wv, Wg, Wo);
    aconv_kernel<<<dim3(MROWS*CS/1024, 2), 256>>>(s, k_in);

    // stream B: prep (#3) + bias_mma (#4 — profiler target)
    prep_kernel<<<1, 128, 0, s2>>>(ln_g, ln_b, Wz);
    bias_mma<<<NPAIR/128, 256, BIAS_SMEM, s2>>>(z);
    cudaEventRecord(evJ, s2);

    // stream A: projections (#5)
    proj4_kernel<<<dim3(CS/64, MROWS/128, 4), 256, GEMM_SMEM>>>(bq);

    // join, then attention (#6) + output projection (#7)
    cudaStreamWaitEvent(0, evJ, 0);
    attn_mma<<<dim3(Nn/64, NH, Bn), 256, ATT_SMEM>>>(mask);
    final_gemm<<<dim3(CS/64, MROWS/128), 256, GEMM_SMEM>>>(out);
}

// round 10
// speedup vs baseline: 3.4853x; 1.3989x over previous
#include <cuda_runtime.h>
#include <cuda_bf16.h>
#include <cstdint>
#include <cstddef>

#define Bn 2
#define Nn 768
#define CS 1024
#define CZ 128
#define NH 16
#define HD 64
#define MROWS (Bn*Nn)     // 1536
#define NPAIR (Bn*Nn*Nn)  // 1179648
#define WSZ (CS*CS)

// ---------------- scratch (device globals; no allocations allowed) ----------------
__device__ __nv_bfloat16 d_Wh[5*WSZ], d_Wl[5*WSZ];          // Wq,Wk,Wv,Wg,Wo split
__device__ __nv_bfloat16 d_inh[2*MROWS*CS], d_inl[2*MROWS*CS]; // s, k_in split
__device__ __nv_bfloat16 d_qh[MROWS*CS], d_ql[MROWS*CS];
__device__ __nv_bfloat16 d_kh[MROWS*CS], d_kl[MROWS*CS];
__device__ __nv_bfloat16 d_vh[MROWS*CS], d_vl[MROWS*CS];
__device__ __nv_bfloat16 d_goh[MROWS*CS], d_gol[MROWS*CS];
__device__ float d_g[MROWS*CS];
__device__ float d_bias[Bn*NH*Nn*Nn];     // 75.5 MB
__device__ float d_Gz[CZ*NH];
__device__ float d_Bh[NH];
__device__ float d_GzSum[NH];

// ================= helpers ====================
__device__ __forceinline__ void ldsm4(uint32_t* r, uint32_t a) {
    asm volatile("ldmatrix.sync.aligned.m8n8.x4.shared.b16 {%0,%1,%2,%3}, [%4];"
                 : "=r"(r[0]), "=r"(r[1]), "=r"(r[2]), "=r"(r[3]) : "r"(a));
}
__device__ __forceinline__ void ldsm4t(uint32_t* r, uint32_t a) {
    asm volatile("ldmatrix.sync.aligned.m8n8.x4.trans.shared.b16 {%0,%1,%2,%3}, [%4];"
                 : "=r"(r[0]), "=r"(r[1]), "=r"(r[2]), "=r"(r[3]) : "r"(a));
}
__device__ __forceinline__ void mma_bf16(float* c, const uint32_t* a, const uint32_t* b) {
    asm volatile("mma.sync.aligned.m16n8k16.row.col.f32.bf16.bf16.f32 "
                 "{%0,%1,%2,%3}, {%4,%5,%6,%7}, {%8,%9}, {%0,%1,%2,%3};"
                 : "+f"(c[0]), "+f"(c[1]), "+f"(c[2]), "+f"(c[3])
                 : "r"(a[0]), "r"(a[1]), "r"(a[2]), "r"(a[3]), "r"(b[0]), "r"(b[1]));
}
__device__ __forceinline__ void split2(float x, float y, uint32_t& hi, uint32_t& lo) {
    __nv_bfloat162 h = __float22bfloat162_rn(make_float2(x, y));
    float2 hf = __bfloat1622float2(h);
    __nv_bfloat162 l = __float22bfloat162_rn(make_float2(x - hf.x, y - hf.y));
    hi = *(uint32_t*)&h;
    lo = *(uint32_t*)&l;
}
#define CPA(dst, src) asm volatile("cp.async.cg.shared.global [%0], [%1], 16;" :: "r"(dst), "l"(src))
#define CPCOMMIT()    asm volatile("cp.async.commit_group;")
#define CPWAIT1()     asm volatile("cp.async.wait_group 1;")

// ---------------- pre-split converters ----------------
__global__ void __launch_bounds__(256) wconv_kernel(
    const float* __restrict__ W0, const float* __restrict__ W1,
    const float* __restrict__ W2, const float* __restrict__ W3,
    const float* __restrict__ W4)
{
    int which = blockIdx.y;
    const float* src = which == 0 ? W0 : which == 1 ? W1 : which == 2 ? W2 :
                       which == 3 ? W3 : W4;
    size_t idx = ((size_t)blockIdx.x * 256 + threadIdx.x) * 4;
    float4 v = *(const float4*)(src + idx);
    uint32_t h0, l0, h1, l1;
    split2(v.x, v.y, h0, l0);
    split2(v.z, v.w, h1, l1);
    size_t o = (size_t)which * WSZ + idx;
    *(uint2*)((char*)d_Wh + o*2) = make_uint2(h0, h1);
    *(uint2*)((char*)d_Wl + o*2) = make_uint2(l0, l1);
}
__global__ void __launch_bounds__(256) aconv_kernel(
    const float* __restrict__ A0, const float* __restrict__ A1)
{
    int which = blockIdx.y;
    const float* src = which == 0 ? A0 : A1;
    size_t idx = ((size_t)blockIdx.x * 256 + threadIdx.x) * 4;
    float4 v = *(const float4*)(src + idx);
    uint32_t h0, l0, h1, l1;
    split2(v.x, v.y, h0, l0);
    split2(v.z, v.w, h1, l1);
    size_t o = (size_t)which * MROWS * CS + idx;
    *(uint2*)((char*)d_inh + o*2) = make_uint2(h0, h1);
    *(uint2*)((char*)d_inl + o*2) = make_uint2(l0, l1);
}

// ================= GEMM: pre-split bf16 inputs, cp.async 3-stage =====
#define ASTRIDE 40
#define BSTRIDE 72
#define AHI_OFF 0
#define ALO_OFF 10240
#define BHI_OFF 20480
#define BLO_OFF 25088
#define BUFBYTES 29696
#define GEMM_SMEM (3*BUFBYTES)   // 89088

__device__ __forceinline__ void gemm_core(
    const __nv_bfloat16* __restrict__ Ah, const __nv_bfloat16* __restrict__ Al,
    const __nv_bfloat16* __restrict__ Bh, const __nv_bfloat16* __restrict__ Bl,
    const float* __restrict__ bq, int mode,
    float* __restrict__ Cf, __nv_bfloat16* __restrict__ Ch, __nv_bfloat16* __restrict__ Cl)
{
    extern __shared__ char sm_raw[];
    uint32_t sbase = (uint32_t)__cvta_generic_to_shared(sm_raw);

    int tid = threadIdx.x;
    int wid = tid >> 5, lane = tid & 31;
    int warpM = wid >> 1, warpN = wid & 1;
    int m0 = blockIdx.y * 128, n0 = blockIdx.x * 64;

    float acc[2][4][4];
    #pragma unroll
    for (int mt = 0; mt < 2; mt++)
        #pragma unroll
        for (int nt = 0; nt < 4; nt++)
            #pragma unroll
            for (int i = 0; i < 4; i++) acc[mt][nt][i] = 0.f;

    int matr = lane >> 3, rr = lane & 7;
    int aRowBase = warpM * 32 + (matr & 1) * 8 + rr;
    int aColBase = (matr >> 1) * 8;
    int bRowBase = (matr & 1) * 8 + rr;
    int bColBase = warpN * 32 + (matr >> 1) * 8;

    int arow = tid >> 2, aq = tid & 3;
    int brow = tid >> 3, bqc = tid & 7;

    auto issue = [&](int c, int buf) {
        uint32_t st = sbase + buf * BUFBYTES;
        #pragma unroll
        for (int r = 0; r < 2; r++) {
            int row = arow + r * 64;
            const __nv_bfloat16* sh = Ah + (size_t)(m0 + row) * CS + c * 32 + aq * 8;
            const __nv_bfloat16* sl = Al + (size_t)(m0 + row) * CS + c * 32 + aq * 8;
            uint32_t d = st + row * 80 + aq * 16;
            CPA(d + AHI_OFF, sh);
            CPA(d + ALO_OFF, sl);
        }
        {
            const __nv_bfloat16* sh = Bh + (size_t)(c * 32 + brow) * CS + n0 + bqc * 8;
            const __nv_bfloat16* sl = Bl + (size_t)(c * 32 + brow) * CS + n0 + bqc * 8;
            uint32_t d = st + brow * 144 + bqc * 16;
            CPA(d + BHI_OFF, sh);
            CPA(d + BLO_OFF, sl);
        }
    };

    issue(0, 0); CPCOMMIT();
    issue(1, 1); CPCOMMIT();

    const int CHUNKS = 32;
    for (int c = 0; c < CHUNKS; c++) {
        CPWAIT1();
        __syncthreads();
        if (c + 2 < CHUNKS) issue(c + 2, (c + 2) % 3);
        CPCOMMIT();

        uint32_t off = sbase + (c % 3) * BUFBYTES;
        #pragma unroll
        for (int ks = 0; ks < 32; ks += 16) {
            uint32_t Ahf[2][4], Alf[2][4], Bhf[2][4], Blf[2][4];
            #pragma unroll
            for (int mt = 0; mt < 2; mt++)
                ldsm4(Ahf[mt], off + AHI_OFF +
                      (((aRowBase + mt * 16) * ASTRIDE) + aColBase + ks) * 2);
            #pragma unroll
            for (int ntp = 0; ntp < 2; ntp++)
                ldsm4t(Bhf[ntp], off + BHI_OFF +
                       (((bRowBase + ks) * BSTRIDE) + bColBase + ntp * 16) * 2);
            #pragma unroll
            for (int mt = 0; mt < 2; mt++)
                #pragma unroll
                for (int nt = 0; nt < 4; nt++)
                    mma_bf16(acc[mt][nt], Ahf[mt], &Bhf[nt >> 1][(nt & 1) * 2]);
            #pragma unroll
            for (int mt = 0; mt < 2; mt++)
                ldsm4(Alf[mt], off + ALO_OFF +
                      (((aRowBase + mt * 16) * ASTRIDE) + aColBase + ks) * 2);
            #pragma unroll
            for (int mt = 0; mt < 2; mt++)
                #pragma unroll
                for (int nt = 0; nt < 4; nt++)
                    mma_bf16(acc[mt][nt], Alf[mt], &Bhf[nt >> 1][(nt & 1) * 2]);
            #pragma unroll
            for (int ntp = 0; ntp < 2; ntp++)
                ldsm4t(Blf[ntp], off + BLO_OFF +
                       (((bRowBase + ks) * BSTRIDE) + bColBase + ntp * 16) * 2);
            #pragma unroll
            for (int mt = 0; mt < 2; mt++)
                #pragma unroll
                for (int nt = 0; nt < 4; nt++)
                    mma_bf16(acc[mt][nt], Ahf[mt], &Blf[nt >> 1][(nt & 1) * 2]);
        }
    }

    int grp = lane >> 2, tL = lane & 3;
    #pragma unroll
    for (int mt = 0; mt < 2; mt++) {
        #pragma unroll
        for (int nt = 0; nt < 4; nt++) {
            int row = m0 + warpM * 32 + mt * 16 + grp;
            int col = n0 + warpN * 32 + nt * 8 + tL * 2;
            float v0 = acc[mt][nt][0], v1 = acc[mt][nt][1];
            float v2 = acc[mt][nt][2], v3 = acc[mt][nt][3];
            if (mode == 0) {
                float b0 = bq[col], b1 = bq[col + 1];
                v0 = (v0 + b0) * 0.125f; v1 = (v1 + b1) * 0.125f;
                v2 = (v2 + b0) * 0.125f; v3 = (v3 + b1) * 0.125f;
            }
            if (mode == 3) {
                v0 = 1.f/(1.f + __expf(-v0)); v1 = 1.f/(1.f + __expf(-v1));
                v2 = 1.f/(1.f + __expf(-v2)); v3 = 1.f/(1.f + __expf(-v3));
                *(float2*)(Cf + (size_t)row * CS + col)       = make_float2(v0, v1);
                *(float2*)(Cf + (size_t)(row + 8) * CS + col) = make_float2(v2, v3);
            } else if (mode == 4) {
                *(float2*)(Cf + (size_t)row * CS + col)       = make_float2(v0, v1);
                *(float2*)(Cf + (size_t)(row + 8) * CS + col) = make_float2(v2, v3);
            } else {
                uint32_t h0, l0, h1, l1;
                split2(v0, v1, h0, l0);
                split2(v2, v3, h1, l1);
                *(uint32_t*)((char*)Ch + ((size_t)row * CS + col) * 2)       = h0;
                *(uint32_t*)((char*)Cl + ((size_t)row * CS + col) * 2)       = l0;
                *(uint32_t*)((char*)Ch + ((size_t)(row + 8) * CS + col) * 2) = h1;
                *(uint32_t*)((char*)Cl + ((size_t)(row + 8) * CS + col) * 2) = l1;
            }
        }
    }
}

__global__ void __launch_bounds__(256) proj4_kernel(const float* __restrict__ bq)
{
    int which = blockIdx.z;
    const __nv_bfloat16* Ah = (which == 0 || which == 3) ? d_inh : d_inh + MROWS*CS;
    const __nv_bfloat16* Al = (which == 0 || which == 3) ? d_inl : d_inl + MROWS*CS;
    const __nv_bfloat16* Bh = d_Wh + (size_t)which * WSZ;
    const __nv_bfloat16* Bl = d_Wl + (size_t)which * WSZ;
    __nv_bfloat16* Ch = which == 0 ? d_qh : which == 1 ? d_kh : which == 2 ? d_vh : nullptr;
    __nv_bfloat16* Cl = which == 0 ? d_ql : which == 1 ? d_kl : which == 2 ? d_vl : nullptr;
    gemm_core(Ah, Al, Bh, Bl, bq, which == 3 ? 3 : which, d_g, Ch, Cl);
}

__global__ void __launch_bounds__(256) final_gemm(float* __restrict__ out)
{
    gemm_core(d_goh, d_gol, d_Wh + 4*(size_t)WSZ, d_Wl + 4*(size_t)WSZ,
              nullptr, 4, out, nullptr, nullptr);
}

// ---------------- fold LN affine into z-projection ----------------
__global__ void prep_kernel(const float* __restrict__ ln_g,
                            const float* __restrict__ ln_b,
                            const float* __restrict__ Wz)
{
    __shared__ float sB[CZ*NH];
    __shared__ float sG[CZ*NH];
    int c = threadIdx.x;
    float g = ln_g[c], bb = ln_b[c];
    #pragma unroll
    for (int h = 0; h < NH; h++) {
        float w = Wz[c*NH + h];
        float gz = g*w;
        d_Gz[c*NH + h] = gz;
        sG[c*NH + h] = gz;
        sB[c*NH + h] = bb*w;
    }
    __syncthreads();
    if (c < NH) {
        float sb = 0.f, sg = 0.f;
        for (int cc = 0; cc < CZ; cc++) { sb += sB[cc*NH + c]; sg += sG[cc*NH + c]; }
        d_Bh[c] = sb;
        d_GzSum[c] = sg;
    }
}

// ====== bias v3: LN+proj, A fragments loaded DIRECTLY from gmem (no z smem) ======
// Block: 128 pair-rows, 256 threads, 8 warps x 16 rows. 3-term split bf16 MMA.
#define BM_GH 0            // Gz hi: 128 c-rows x 24 stride bf16 = 6144 B
#define BM_GL 6144
#define BM_SG 12288        // stage float[128*17] = 8704 B
#define BIAS_SMEM 21504

__global__ void __launch_bounds__(256) bias_mma(const float* __restrict__ z)
{
    extern __shared__ char smraw[];
    uint32_t sb = (uint32_t)__cvta_generic_to_shared(smraw);
    int tid = threadIdx.x, lane = tid & 31, wid = tid >> 5;
    int grp = lane >> 2, tL = lane & 3;
    int t8 = lane >> 3, r8 = lane & 7;

    // stage Gz (fp32 -> split bf16): rows c, cols h, stride 24 (ldsm-conflict-free)
    for (int t = tid; t < CZ*NH; t += 256) {
        int c = t >> 4, h = t & 15;
        float w = d_Gz[t];
        __nv_bfloat16 hi = __float2bfloat16(w);
        __nv_bfloat16 lo = __float2bfloat16(w - __bfloat162float(hi));
        ((__nv_bfloat16*)(smraw + BM_GH))[c*24 + h] = hi;
        ((__nv_bfloat16*)(smraw + BM_GL))[c*24 + h] = lo;
    }
    __syncthreads();

    // this thread's two rows (mma A layout: rows grp and grp+8 of warp's 16)
    const float* z0 = z + (size_t)(blockIdx.x*128 + wid*16 + grp)*CZ;
    const float* z1 = z0 + 8*CZ;

    int gRow = (t8 & 1)*8 + r8;
    int gCol = (t8 >> 1)*8;

    float acc0[4] = {0.f,0.f,0.f,0.f}, acc1[4] = {0.f,0.f,0.f,0.f};
    float s1_0 = 0.f, s2_0 = 0.f, s1_1 = 0.f, s2_1 = 0.f;

    #pragma unroll
    for (int kc = 0; kc < 8; kc++) {
        int c0 = kc*16 + tL*2;
        float2 f0 = *(const float2*)(z0 + c0);        // reg0: (grp, k0-7 pair)
        float2 f1 = *(const float2*)(z1 + c0);        // reg1: (grp+8)
        float2 f2 = *(const float2*)(z0 + c0 + 8);    // reg2: (grp, k8-15 pair)
        float2 f3 = *(const float2*)(z1 + c0 + 8);    // reg3: (grp+8)

        s1_0 += (f0.x + f0.y) + (f2.x + f2.y);
        s2_0 = fmaf(f0.x,f0.x, fmaf(f0.y,f0.y, fmaf(f2.x,f2.x, fmaf(f2.y,f2.y, s2_0))));
        s1_1 += (f1.x + f1.y) + (f3.x + f3.y);
        s2_1 = fmaf(f1.x,f1.x, fmaf(f1.y,f1.y, fmaf(f3.x,f3.x, fmaf(f3.y,f3.y, s2_1))));

        uint32_t Ahf[4], Alf[4];
        split2(f0.x, f0.y, Ahf[0], Alf[0]);
        split2(f1.x, f1.y, Ahf[1], Alf[1]);
        split2(f2.x, f2.y, Ahf[2], Alf[2]);
        split2(f3.x, f3.y, Ahf[3], Alf[3]);

        uint32_t Gh[4], Gl[4];
        uint32_t goff = (uint32_t)(((gRow + kc*16)*24 + gCol) * 2);
        ldsm4t(Gh, sb + BM_GH + goff);
        ldsm4t(Gl, sb + BM_GL + goff);

        mma_bf16(acc0, Ahf, &Gh[0]); mma_bf16(acc1, Ahf, &Gh[2]);
        mma_bf16(acc0, Alf, &Gh[0]); mma_bf16(acc1, Alf, &Gh[2]);
        mma_bf16(acc0, Ahf, &Gl[0]); mma_bf16(acc1, Ahf, &Gl[2]);
    }

    // row stats: reduce over the 4 tL lanes of each quad
    s1_0 += __shfl_xor_sync(0xFFFFFFFFu, s1_0, 1);
    s1_0 += __shfl_xor_sync(0xFFFFFFFFu, s1_0, 2);
    s2_0 += __shfl_xor_sync(0xFFFFFFFFu, s2_0, 1);
    s2_0 += __shfl_xor_sync(0xFFFFFFFFu, s2_0, 2);
    s1_1 += __shfl_xor_sync(0xFFFFFFFFu, s1_1, 1);
    s1_1 += __shfl_xor_sync(0xFFFFFFFFu, s1_1, 2);
    s2_1 += __shfl_xor_sync(0xFFFFFFFFu, s2_1, 1);
    s2_1 += __shfl_xor_sync(0xFFFFFFFFu, s2_1, 2);
    float mu0 = s1_0 * (1.f/128.f);
    float rstd0 = rsqrtf(s2_0 * (1.f/128.f) - mu0*mu0 + 1e-5f);
    float mu1 = s1_1 * (1.f/128.f);
    float rstd1 = rsqrtf(s2_1 * (1.f/128.f) - mu1*mu1 + 1e-5f);

    // affine epilogue into stage[row][h]
    {
        int r0 = wid*16 + grp, r1 = r0 + 8;
        float* stage = (float*)(smraw + BM_SG);
        #pragma unroll
        for (int n = 0; n < 2; n++) {
            float* a = n ? acc1 : acc0;
            int h = n*8 + tL*2;
            float gs0 = d_GzSum[h], gs1 = d_GzSum[h+1];
            float bh0 = d_Bh[h],    bh1 = d_Bh[h+1];
            stage[r0*17 + h]     = rstd0*(a[0] - mu0*gs0) + bh0;
            stage[r0*17 + h + 1] = rstd0*(a[1] - mu0*gs1) + bh1;
            stage[r1*17 + h]     = rstd1*(a[2] - mu1*gs0) + bh0;
            stage[r1*17 + h + 1] = rstd1*(a[3] - mu1*gs1) + bh1;
        }
    }
    __syncthreads();

    // transposed coalesced write: all 128 rows share (b, i)
    {
        int p0  = blockIdx.x * 128;
        int b   = p0 / (Nn*Nn);
        int rem = p0 % (Nn*Nn);
        int ii  = rem / Nn;
        int j0  = rem % Nn;
        float* stage = (float*)(smraw + BM_SG);
        #pragma unroll
        for (int t = tid; t < 128*NH; t += 256) {
            int h = t >> 7, rr = t & 127;
            d_bias[((size_t)(b*NH + h)*Nn + ii)*Nn + j0 + rr] = stage[rr*17 + h];
        }
    }
}

// ========== flash attention: pre-split bf16 q/k/v, cp.async pipeline ==========
#define AT_STRIDE 72
#define AQ_H 0
#define AQ_L 9216
#define KV0 18432
#define KVSTAGE 36864
#define OSM_OFF 0
#define OSM_STRIDE 68
#define STAT_OFF 34816
#define ATT_SMEM 92160

__global__ void __launch_bounds__(256, 2) attn_mma(const float* __restrict__ mask)
{
    extern __shared__ char smraw[];
    uint32_t sb = (uint32_t)__cvta_generic_to_shared(smraw);
    int tid = threadIdx.x, lane = tid & 31, wid = tid >> 5;
    int warpM = wid >> 1, warpN = wid & 1;
    int b = blockIdx.z, h = blockIdx.y, i0 = blockIdx.x * 64;
    int grp = lane >> 2, tL = lane & 3;
    int t8 = lane >> 3, r8 = lane & 7;

    {
        #pragma unroll
        for (int i = 0; i < 4; i++) {
            int g = tid + i*256;
            int mtx = g >> 9, r = (g >> 3) & 63, q = g & 7;
            const __nv_bfloat16* src = (mtx ? d_ql : d_qh) +
                (size_t)(b*Nn + i0 + r)*CS + h*HD + q*8;
            CPA(sb + mtx*9216 + r*144 + q*16, src);
        }
        #pragma unroll
        for (int i = 0; i < 8; i++) {
            int g = tid + i*256;
            int mtx = g >> 9, r = (g >> 3) & 63, q = g & 7;
            const __nv_bfloat16* src =
                (mtx == 0 ? d_kh : mtx == 1 ? d_kl : mtx == 2 ? d_vh : d_vl) +
                (size_t)(b*Nn + r)*CS + h*HD + q*8;
            CPA(sb + KV0 + mtx*9216 + r*144 + q*16, src);
        }
        CPCOMMIT();
    }

    float Oa[8][4];
    #pragma unroll
    for (int t = 0; t < 8; t++) { Oa[t][0]=0.f; Oa[t][1]=0.f; Oa[t][2]=0.f; Oa[t][3]=0.f; }
    float mrow0 = -1e30f, mrow1 = -1e30f, lsum0 = 0.f, lsum1 = 0.f;

    const float* maskp = mask + b*Nn;
    const float* biasbase = d_bias + ((size_t)(b*NH + h)*Nn + (i0 + warpM*16 + grp))*Nn;

    int aRow  = warpM*16 + (t8 & 1)*8 + r8;
    int aCol  = (t8 >> 1)*8;
    int kRowB = warpN*32 + (t8 >> 1)*8 + r8;
    int kColB = (t8 & 1)*8;
    int vRowB = (t8 & 1)*8 + r8;
    int vColB = (t8 >> 1)*8;

    #pragma unroll 1
    for (int jt = 0; jt < 12; jt++) {
        int j0c = jt * 64;
        __syncthreads();
        if (jt + 1 < 12) {
            int st1 = (jt + 1) & 1;
            #pragma unroll
            for (int i = 0; i < 8; i++) {
                int g = tid + i*256;
                int mtx = g >> 9, r = (g >> 3) & 63, q = g & 7;
                const __nv_bfloat16* src =
                    (mtx == 0 ? d_kh : mtx == 1 ? d_kl : mtx == 2 ? d_vh : d_vl) +
                    (size_t)(b*Nn + j0c + 64 + r)*CS + h*HD + q*8;
                CPA(sb + KV0 + st1*KVSTAGE + mtx*9216 + r*144 + q*16, src);
            }
        }
        CPCOMMIT();
        CPWAIT1();
        __syncthreads();

        uint32_t ks = sb + KV0 + (jt & 1)*KVSTAGE;

        float S[4][4];
        #pragma unroll
        for (int nt = 0; nt < 4; nt++) { S[nt][0]=0.f; S[nt][1]=0.f; S[nt][2]=0.f; S[nt][3]=0.f; }
        #pragma unroll
        for (int kk = 0; kk < 4; kk++) {
            uint32_t qh_[4], ql_[4], khf[2][4], klf[2][4];
            uint32_t aoff = (uint32_t)((aRow*AT_STRIDE + kk*16 + aCol) * 2);
            ldsm4(qh_, sb + AQ_H + aoff);
            ldsm4(ql_, sb + AQ_L + aoff);
            uint32_t koff0 = (uint32_t)((kRowB*AT_STRIDE + kk*16 + kColB) * 2);
            uint32_t koff1 = (uint32_t)(((kRowB+16)*AT_STRIDE + kk*16 + kColB) * 2);
            ldsm4(khf[0], ks + koff0);
            ldsm4(khf[1], ks + koff1);
            #pragma unroll
            for (int nt = 0; nt < 4; nt++)
                mma_bf16(S[nt], qh_, &khf[nt >> 1][(nt & 1)*2]);
            #pragma unroll
            for (int nt = 0; nt < 4; nt++)
                mma_bf16(S[nt], ql_, &khf[nt >> 1][(nt & 1)*2]);
            ldsm4(klf[0], ks + 9216 + koff0);
            ldsm4(klf[1], ks + 9216 + koff1);
            #pragma unroll
            for (int nt = 0; nt < 4; nt++)
                mma_bf16(S[nt], qh_, &klf[nt >> 1][(nt & 1)*2]);
        }

        #pragma unroll
        for (int nt = 0; nt < 4; nt++) {
            int jc = j0c + warpN*32 + nt*8 + tL*2;
            float2 b0 = *(const float2*)(biasbase + jc);
            float2 b1 = *(const float2*)(biasbase + (size_t)8*Nn + jc);
            float2 mv = *(const float2*)(maskp + jc);
            float mk0 = (1.f - mv.x) * (-1000000.0f);
            float mk1 = (1.f - mv.y) * (-1000000.0f);
            S[nt][0] += b0.x + mk0; S[nt][1] += b0.y + mk1;
            S[nt][2] += b1.x + mk0; S[nt][3] += b1.y + mk1;
        }

        float cm0 = fmaxf(fmaxf(S[0][0], S[0][1]), fmaxf(S[1][0], S[1][1]));
        cm0 = fmaxf(cm0, fmaxf(fmaxf(S[2][0], S[2][1]), fmaxf(S[3][0], S[3][1])));
        float cm1 = fmaxf(fmaxf(S[0][2], S[0][3]), fmaxf(S[1][2], S[1][3]));
        cm1 = fmaxf(cm1, fmaxf(fmaxf(S[2][2], S[2][3]), fmaxf(S[3][2], S[3][3])));
        cm0 = fmaxf(cm0, __shfl_xor_sync(0xFFFFFFFFu, cm0, 1));
        cm0 = fmaxf(cm0, __shfl_xor_sync(0xFFFFFFFFu, cm0, 2));
        cm1 = fmaxf(cm1, __shfl_xor_sync(0xFFFFFFFFu, cm1, 1));
        cm1 = fmaxf(cm1, __shfl_xor_sync(0xFFFFFFFFu, cm1, 2));
        float mn0 = fmaxf(mrow0, cm0), mn1 = fmaxf(mrow1, cm1);
        float sc0 = __expf(mrow0 - mn0), sc1 = __expf(mrow1 - mn1);
        mrow0 = mn0; mrow1 = mn1;
        float rs0 = 0.f, rs1 = 0.f;
        #pragma unroll
        for (int nt = 0; nt < 4; nt++) {
            S[nt][0] = __expf(S[nt][0] - mn0);
            S[nt][1] = __expf(S[nt][1] - mn0);
            S[nt][2] = __expf(S[nt][2] - mn1);
            S[nt][3] = __expf(S[nt][3] - mn1);
            rs0 += S[nt][0] + S[nt][1];
            rs1 += S[nt][2] + S[nt][3];
        }
        rs0 += __shfl_xor_sync(0xFFFFFFFFu, rs0, 1);
        rs0 += __shfl_xor_sync(0xFFFFFFFFu, rs0, 2);
        rs1 += __shfl_xor_sync(0xFFFFFFFFu, rs1, 1);
        rs1 += __shfl_xor_sync(0xFFFFFFFFu, rs1, 2);
        lsum0 = lsum0*sc0 + rs0;
        lsum1 = lsum1*sc1 + rs1;
        #pragma unroll
        for (int t = 0; t < 8; t++) {
            Oa[t][0] *= sc0; Oa[t][1] *= sc0;
            Oa[t][2] *= sc1; Oa[t][3] *= sc1;
        }

        uint32_t Ph[2][4], Pl[2][4];
        #pragma unroll
        for (int kf = 0; kf < 2; kf++) {
            split2(S[2*kf][0],   S[2*kf][1],   Ph[kf][0], Pl[kf][0]);
            split2(S[2*kf][2],   S[2*kf][3],   Ph[kf][1], Pl[kf][1]);
            split2(S[2*kf+1][0], S[2*kf+1][1], Ph[kf][2], Pl[kf][2]);
            split2(S[2*kf+1][2], S[2*kf+1][3], Ph[kf][3], Pl[kf][3]);
        }

        #pragma unroll
        for (int kf = 0; kf < 2; kf++) {
            int kb = warpN*32 + kf*16;
            #pragma unroll
            for (int ntp = 0; ntp < 4; ntp++) {
                uint32_t vhf[4], vlf[4];
                uint32_t voff = (uint32_t)(((kb + vRowB)*AT_STRIDE + ntp*16 + vColB) * 2);
                ldsm4t(vhf, ks + 18432 + voff);
                ldsm4t(vlf, ks + 27648 + voff);
                mma_bf16(Oa[ntp*2],   Ph[kf], &vhf[0]);
                mma_bf16(Oa[ntp*2+1], Ph[kf], &vhf[2]);
                mma_bf16(Oa[ntp*2],   Pl[kf], &vhf[0]);
                mma_bf16(Oa[ntp*2+1], Pl[kf], &vhf[2]);
                mma_bf16(Oa[ntp*2],   Ph[kf], &vlf[0]);
                mma_bf16(Oa[ntp*2+1], Ph[kf], &vlf[2]);
            }
        }
    }

    __syncthreads();
    float* Osm  = (float*)(smraw + OSM_OFF);
    float* stat = (float*)(smraw + STAT_OFF);
    #pragma unroll
    for (int t = 0; t < 8; t++) {
        int dcol = t*8 + tL*2;
        Osm[(wid*16 + grp)*OSM_STRIDE + dcol]       = Oa[t][0];
        Osm[(wid*16 + grp)*OSM_STRIDE + dcol + 1]   = Oa[t][1];
        Osm[(wid*16 + grp+8)*OSM_STRIDE + dcol]     = Oa[t][2];
        Osm[(wid*16 + grp+8)*OSM_STRIDE + dcol + 1] = Oa[t][3];
    }
    if (tL == 0) {
        stat[wid*32 + grp*2]       = mrow0;
        stat[wid*32 + grp*2 + 1]   = lsum0;
        stat[wid*32 + (grp+8)*2]     = mrow1;
        stat[wid*32 + (grp+8)*2 + 1] = lsum1;
    }
    __syncthreads();

    for (int t = tid; t < 64*32; t += 256) {
        int row = t >> 5, d2 = (t & 31)*2;
        int w0 = (row >> 4)*2, rl = row & 15;
        float m0 = stat[w0*32 + rl*2],     l0 = stat[w0*32 + rl*2 + 1];
        float m1 = stat[(w0+1)*32 + rl*2], l1 = stat[(w0+1)*32 + rl*2 + 1];
        float mm = fmaxf(m0, m1);
        float a0 = __expf(m0 - mm), a1 = __expf(m1 - mm);
        float inv = 1.f / (a0*l0 + a1*l1);
        float o0 = (a0*Osm[(w0*16 + rl)*OSM_STRIDE + d2] +
                    a1*Osm[((w0+1)*16 + rl)*OSM_STRIDE + d2]) * inv;
        float o1 = (a0*Osm[(w0*16 + rl)*OSM_STRIDE + d2 + 1] +
                    a1*Osm[((w0+1)*16 + rl)*OSM_STRIDE + d2 + 1]) * inv;
        size_t gi = (size_t)(b*Nn + i0 + row)*CS + h*HD + d2;
        float2 gg = *(const float2*)(d_g + gi);
        uint32_t hh, ll;
        split2(gg.x * o0, gg.y * o1, hh, ll);
        *(uint32_t*)((char*)d_goh + gi*2) = hh;
        *(uint32_t*)((char*)d_gol + gi*2) = ll;
    }
}

// ---------------- launch: fork bias chain; bias stays launch #4 for ncu ----------------
extern "C" void kernel_launch(void* const* d_in, const int* in_sizes, int n_in,
                              void* d_out, int out_size)
{
    const float* s    = (const float*)d_in[0];
    const float* z    = (const float*)d_in[1];
    const float* mask = (const float*)d_in[2];
    const float* k_in = (const float*)d_in[3];
    const float* Wq   = (const float*)d_in[4];
    const float* bq   = (const float*)d_in[5];
    const float* Wk   = (const float*)d_in[6];
    const float* Wv   = (const float*)d_in[7];
    const float* Wg   = (const float*)d_in[8];
    const float* ln_g = (const float*)d_in[9];
    const float* ln_b = (const float*)d_in[10];
    const float* Wz   = (const float*)d_in[11];
    const float* Wo   = (const float*)d_in[12];
    float* out = (float*)d_out;

    static cudaStream_t s2 = nullptr;
    static cudaEvent_t evF = nullptr, evJ = nullptr;
    if (s2 == nullptr) {
        cudaStreamCreateWithFlags(&s2, cudaStreamNonBlocking);
        cudaEventCreateWithFlags(&evF, cudaEventDisableTiming);
        cudaEventCreateWithFlags(&evJ, cudaEventDisableTiming);
        cudaFuncSetAttribute(proj4_kernel, cudaFuncAttributeMaxDynamicSharedMemorySize, GEMM_SMEM);
        cudaFuncSetAttribute(final_gemm,   cudaFuncAttributeMaxDynamicSharedMemorySize, GEMM_SMEM);
        cudaFuncSetAttribute(attn_mma,     cudaFuncAttributeMaxDynamicSharedMemorySize, ATT_SMEM);
        cudaFuncSetAttribute(bias_mma,     cudaFuncAttributeMaxDynamicSharedMemorySize, BIAS_SMEM);
    }

    // stream A first two launches (submission #1, #2)
    cudaEventRecord(evF, 0);
    cudaStreamWaitEvent(s2, evF, 0);
    wconv_kernel<<<dim3(WSZ/1024, 5), 256>>>(Wq, Wk, Wv, Wg, Wo);
    aconv_kernel<<<dim3(MROWS*CS/1024, 2), 256>>>(s, k_in);

    // stream B: prep (#3) + bias_mma (#4 — profiler target)
    prep_kernel<<<1, 128, 0, s2>>>(ln_g, ln_b, Wz);
    bias_mma<<<NPAIR/128, 256, BIAS_SMEM, s2>>>(z);
    cudaEventRecord(evJ, s2);

    // stream A: projections (#5)
    proj4_kernel<<<dim3(CS/64, MROWS/128, 4), 256, GEMM_SMEM>>>(bq);

    // join, then attention (#6) + output projection (#7)
    cudaStreamWaitEvent(0, evJ, 0);
    attn_mma<<<dim3(Nn/64, NH, Bn), 256, ATT_SMEM>>>(mask);
    final_gemm<<<dim3(CS/64, MROWS/128), 256, GEMM_SMEM>>>(out);
}

// round 11
// speedup vs baseline: 3.8157x; 1.0948x over previous
#include <cuda_runtime.h>
#include <cuda_bf16.h>
#include <cuda_fp16.h>
#include <cstdint>
#include <cstddef>

#define Bn 2
#define Nn 768
#define CS 1024
#define CZ 128
#define NH 16
#define HD 64
#define MROWS (Bn*Nn)     // 1536
#define NPAIR (Bn*Nn*Nn)  // 1179648
#define WSZ (CS*CS)

// ---------------- scratch (device globals; no allocations allowed) ----------------
__device__ __nv_bfloat16 d_Wh[5*WSZ], d_Wl[5*WSZ];          // Wq,Wk,Wv,Wg,Wo split (bf16)
__device__ __nv_bfloat16 d_inh[2*MROWS*CS], d_inl[2*MROWS*CS]; // s, k_in split (bf16)
__device__ __nv_bfloat16 d_qh[MROWS*CS], d_ql[MROWS*CS];    // fp16 content (raw 16-bit)
__device__ __nv_bfloat16 d_kh[MROWS*CS], d_kl[MROWS*CS];    // kh used (fp16), kl unused
__device__ __nv_bfloat16 d_vh[MROWS*CS], d_vl[MROWS*CS];    // vh used (fp16), vl unused
__device__ __nv_bfloat16 d_goh[MROWS*CS], d_gol[MROWS*CS];  // bf16 split
__device__ float d_g[MROWS*CS];
__device__ __half d_bias[Bn*NH*Nn*Nn];    // fp16 bias (37.7 MB)
__device__ float d_Gz[CZ*NH];
__device__ float d_Bh[NH];
__device__ float d_GzSum[NH];

// ================= helpers ====================
__device__ __forceinline__ void ldsm4(uint32_t* r, uint32_t a) {
    asm volatile("ldmatrix.sync.aligned.m8n8.x4.shared.b16 {%0,%1,%2,%3}, [%4];"
                 : "=r"(r[0]), "=r"(r[1]), "=r"(r[2]), "=r"(r[3]) : "r"(a));
}
__device__ __forceinline__ void ldsm4t(uint32_t* r, uint32_t a) {
    asm volatile("ldmatrix.sync.aligned.m8n8.x4.trans.shared.b16 {%0,%1,%2,%3}, [%4];"
                 : "=r"(r[0]), "=r"(r[1]), "=r"(r[2]), "=r"(r[3]) : "r"(a));
}
__device__ __forceinline__ void mma_bf16(float* c, const uint32_t* a, const uint32_t* b) {
    asm volatile("mma.sync.aligned.m16n8k16.row.col.f32.bf16.bf16.f32 "
                 "{%0,%1,%2,%3}, {%4,%5,%6,%7}, {%8,%9}, {%0,%1,%2,%3};"
                 : "+f"(c[0]), "+f"(c[1]), "+f"(c[2]), "+f"(c[3])
                 : "r"(a[0]), "r"(a[1]), "r"(a[2]), "r"(a[3]), "r"(b[0]), "r"(b[1]));
}
__device__ __forceinline__ void mma_f16(float* c, const uint32_t* a, const uint32_t* b) {
    asm volatile("mma.sync.aligned.m16n8k16.row.col.f32.f16.f16.f32 "
                 "{%0,%1,%2,%3}, {%4,%5,%6,%7}, {%8,%9}, {%0,%1,%2,%3};"
                 : "+f"(c[0]), "+f"(c[1]), "+f"(c[2]), "+f"(c[3])
                 : "r"(a[0]), "r"(a[1]), "r"(a[2]), "r"(a[3]), "r"(b[0]), "r"(b[1]));
}
__device__ __forceinline__ void split2(float x, float y, uint32_t& hi, uint32_t& lo) {
    __nv_bfloat162 h = __float22bfloat162_rn(make_float2(x, y));
    float2 hf = __bfloat1622float2(h);
    __nv_bfloat162 l = __float22bfloat162_rn(make_float2(x - hf.x, y - hf.y));
    hi = *(uint32_t*)&h;
    lo = *(uint32_t*)&l;
}
__device__ __forceinline__ void split2h(float x, float y, uint32_t& hi, uint32_t& lo) {
    __half2 h = __floats2half2_rn(x, y);
    float2 hf = __half22float2(h);
    __half2 l = __floats2half2_rn(x - hf.x, y - hf.y);
    hi = *(uint32_t*)&h;
    lo = *(uint32_t*)&l;
}
#define CPA(dst, src) asm volatile("cp.async.cg.shared.global [%0], [%1], 16;" :: "r"(dst), "l"(src))
#define CPCOMMIT()    asm volatile("cp.async.commit_group;")
#define CPWAIT1()     asm volatile("cp.async.wait_group 1;")

// ---------------- pre-split converters ----------------
__global__ void __launch_bounds__(256) wconv_kernel(
    const float* __restrict__ W0, const float* __restrict__ W1,
    const float* __restrict__ W2, const float* __restrict__ W3,
    const float* __restrict__ W4)
{
    int which = blockIdx.y;
    const float* src = which == 0 ? W0 : which == 1 ? W1 : which == 2 ? W2 :
                       which == 3 ? W3 : W4;
    size_t idx = ((size_t)blockIdx.x * 256 + threadIdx.x) * 4;
    float4 v = *(const float4*)(src + idx);
    uint32_t h0, l0, h1, l1;
    split2(v.x, v.y, h0, l0);
    split2(v.z, v.w, h1, l1);
    size_t o = (size_t)which * WSZ + idx;
    *(uint2*)((char*)d_Wh + o*2) = make_uint2(h0, h1);
    *(uint2*)((char*)d_Wl + o*2) = make_uint2(l0, l1);
}
__global__ void __launch_bounds__(256) aconv_kernel(
    const float* __restrict__ A0, const float* __restrict__ A1)
{
    int which = blockIdx.y;
    const float* src = which == 0 ? A0 : A1;
    size_t idx = ((size_t)blockIdx.x * 256 + threadIdx.x) * 4;
    float4 v = *(const float4*)(src + idx);
    uint32_t h0, l0, h1, l1;
    split2(v.x, v.y, h0, l0);
    split2(v.z, v.w, h1, l1);
    size_t o = (size_t)which * MROWS * CS + idx;
    *(uint2*)((char*)d_inh + o*2) = make_uint2(h0, h1);
    *(uint2*)((char*)d_inl + o*2) = make_uint2(l0, l1);
}

// ================= GEMM: pre-split bf16 inputs, cp.async 3-stage =====
// modes: 0=q (bias, *0.125, fp16 split out), 1=k, 2=v (fp16 hi out),
//        3=g (sigmoid, f32 out), 4=final (f32 out)
#define ASTRIDE 40
#define BSTRIDE 72
#define AHI_OFF 0
#define ALO_OFF 10240
#define BHI_OFF 20480
#define BLO_OFF 25088
#define BUFBYTES 29696
#define GEMM_SMEM (3*BUFBYTES)   // 89088

__device__ __forceinline__ void gemm_core(
    const __nv_bfloat16* __restrict__ Ah, const __nv_bfloat16* __restrict__ Al,
    const __nv_bfloat16* __restrict__ Bh, const __nv_bfloat16* __restrict__ Bl,
    const float* __restrict__ bq, int mode,
    float* __restrict__ Cf, __nv_bfloat16* __restrict__ Ch, __nv_bfloat16* __restrict__ Cl)
{
    extern __shared__ char sm_raw[];
    uint32_t sbase = (uint32_t)__cvta_generic_to_shared(sm_raw);

    int tid = threadIdx.x;
    int wid = tid >> 5, lane = tid & 31;
    int warpM = wid >> 1, warpN = wid & 1;
    int m0 = blockIdx.y * 128, n0 = blockIdx.x * 64;

    float acc[2][4][4];
    #pragma unroll
    for (int mt = 0; mt < 2; mt++)
        #pragma unroll
        for (int nt = 0; nt < 4; nt++)
            #pragma unroll
            for (int i = 0; i < 4; i++) acc[mt][nt][i] = 0.f;

    int matr = lane >> 3, rr = lane & 7;
    int aRowBase = warpM * 32 + (matr & 1) * 8 + rr;
    int aColBase = (matr >> 1) * 8;
    int bRowBase = (matr & 1) * 8 + rr;
    int bColBase = warpN * 32 + (matr >> 1) * 8;

    int arow = tid >> 2, aq = tid & 3;
    int brow = tid >> 3, bqc = tid & 7;

    auto issue = [&](int c, int buf) {
        uint32_t st = sbase + buf * BUFBYTES;
        #pragma unroll
        for (int r = 0; r < 2; r++) {
            int row = arow + r * 64;
            const __nv_bfloat16* sh = Ah + (size_t)(m0 + row) * CS + c * 32 + aq * 8;
            const __nv_bfloat16* sl = Al + (size_t)(m0 + row) * CS + c * 32 + aq * 8;
            uint32_t d = st + row * 80 + aq * 16;
            CPA(d + AHI_OFF, sh);
            CPA(d + ALO_OFF, sl);
        }
        {
            const __nv_bfloat16* sh = Bh + (size_t)(c * 32 + brow) * CS + n0 + bqc * 8;
            const __nv_bfloat16* sl = Bl + (size_t)(c * 32 + brow) * CS + n0 + bqc * 8;
            uint32_t d = st + brow * 144 + bqc * 16;
            CPA(d + BHI_OFF, sh);
            CPA(d + BLO_OFF, sl);
        }
    };

    issue(0, 0); CPCOMMIT();
    issue(1, 1); CPCOMMIT();

    const int CHUNKS = 32;
    for (int c = 0; c < CHUNKS; c++) {
        CPWAIT1();
        __syncthreads();
        if (c + 2 < CHUNKS) issue(c + 2, (c + 2) % 3);
        CPCOMMIT();

        uint32_t off = sbase + (c % 3) * BUFBYTES;
        #pragma unroll
        for (int ks = 0; ks < 32; ks += 16) {
            uint32_t Ahf[2][4], Alf[2][4], Bhf[2][4], Blf[2][4];
            #pragma unroll
            for (int mt = 0; mt < 2; mt++)
                ldsm4(Ahf[mt], off + AHI_OFF +
                      (((aRowBase + mt * 16) * ASTRIDE) + aColBase + ks) * 2);
            #pragma unroll
            for (int ntp = 0; ntp < 2; ntp++)
                ldsm4t(Bhf[ntp], off + BHI_OFF +
                       (((bRowBase + ks) * BSTRIDE) + bColBase + ntp * 16) * 2);
            #pragma unroll
            for (int mt = 0; mt < 2; mt++)
                #pragma unroll
                for (int nt = 0; nt < 4; nt++)
                    mma_bf16(acc[mt][nt], Ahf[mt], &Bhf[nt >> 1][(nt & 1) * 2]);
            #pragma unroll
            for (int mt = 0; mt < 2; mt++)
                ldsm4(Alf[mt], off + ALO_OFF +
                      (((aRowBase + mt * 16) * ASTRIDE) + aColBase + ks) * 2);
            #pragma unroll
            for (int mt = 0; mt < 2; mt++)
                #pragma unroll
                for (int nt = 0; nt < 4; nt++)
                    mma_bf16(acc[mt][nt], Alf[mt], &Bhf[nt >> 1][(nt & 1) * 2]);
            #pragma unroll
            for (int ntp = 0; ntp < 2; ntp++)
                ldsm4t(Blf[ntp], off + BLO_OFF +
                       (((bRowBase + ks) * BSTRIDE) + bColBase + ntp * 16) * 2);
            #pragma unroll
            for (int mt = 0; mt < 2; mt++)
                #pragma unroll
                for (int nt = 0; nt < 4; nt++)
                    mma_bf16(acc[mt][nt], Ahf[mt], &Blf[nt >> 1][(nt & 1) * 2]);
        }
    }

    int grp = lane >> 2, tL = lane & 3;
    #pragma unroll
    for (int mt = 0; mt < 2; mt++) {
        #pragma unroll
        for (int nt = 0; nt < 4; nt++) {
            int row = m0 + warpM * 32 + mt * 16 + grp;
            int col = n0 + warpN * 32 + nt * 8 + tL * 2;
            float v0 = acc[mt][nt][0], v1 = acc[mt][nt][1];
            float v2 = acc[mt][nt][2], v3 = acc[mt][nt][3];
            if (mode == 0) {
                float b0 = bq[col], b1 = bq[col + 1];
                v0 = (v0 + b0) * 0.125f; v1 = (v1 + b1) * 0.125f;
                v2 = (v2 + b0) * 0.125f; v3 = (v3 + b1) * 0.125f;
                uint32_t h0, l0, h1, l1;
                split2h(v0, v1, h0, l0);
                split2h(v2, v3, h1, l1);
                *(uint32_t*)((char*)Ch + ((size_t)row * CS + col) * 2)       = h0;
                *(uint32_t*)((char*)Cl + ((size_t)row * CS + col) * 2)       = l0;
                *(uint32_t*)((char*)Ch + ((size_t)(row + 8) * CS + col) * 2) = h1;
                *(uint32_t*)((char*)Cl + ((size_t)(row + 8) * CS + col) * 2) = l1;
            } else if (mode == 1 || mode == 2) {
                __half2 a = __floats2half2_rn(v0, v1);
                __half2 b2 = __floats2half2_rn(v2, v3);
                *(uint32_t*)((char*)Ch + ((size_t)row * CS + col) * 2)       = *(uint32_t*)&a;
                *(uint32_t*)((char*)Ch + ((size_t)(row + 8) * CS + col) * 2) = *(uint32_t*)&b2;
            } else if (mode == 3) {
                v0 = 1.f/(1.f + __expf(-v0)); v1 = 1.f/(1.f + __expf(-v1));
                v2 = 1.f/(1.f + __expf(-v2)); v3 = 1.f/(1.f + __expf(-v3));
                *(float2*)(Cf + (size_t)row * CS + col)       = make_float2(v0, v1);
                *(float2*)(Cf + (size_t)(row + 8) * CS + col) = make_float2(v2, v3);
            } else {
                *(float2*)(Cf + (size_t)row * CS + col)       = make_float2(v0, v1);
                *(float2*)(Cf + (size_t)(row + 8) * CS + col) = make_float2(v2, v3);
            }
        }
    }
}

__global__ void __launch_bounds__(256) proj4_kernel(const float* __restrict__ bq)
{
    int which = blockIdx.z;
    const __nv_bfloat16* Ah = (which == 0 || which == 3) ? d_inh : d_inh + MROWS*CS;
    const __nv_bfloat16* Al = (which == 0 || which == 3) ? d_inl : d_inl + MROWS*CS;
    const __nv_bfloat16* Bh = d_Wh + (size_t)which * WSZ;
    const __nv_bfloat16* Bl = d_Wl + (size_t)which * WSZ;
    __nv_bfloat16* Ch = which == 0 ? d_qh : which == 1 ? d_kh : which == 2 ? d_vh : nullptr;
    __nv_bfloat16* Cl = which == 0 ? d_ql : nullptr;
    gemm_core(Ah, Al, Bh, Bl, bq, which, d_g, Ch, Cl);
}

__global__ void __launch_bounds__(256) final_gemm(float* __restrict__ out)
{
    gemm_core(d_goh, d_gol, d_Wh + 4*(size_t)WSZ, d_Wl + 4*(size_t)WSZ,
              nullptr, 4, out, nullptr, nullptr);
}

// ---------------- fold LN affine into z-projection ----------------
__global__ void prep_kernel(const float* __restrict__ ln_g,
                            const float* __restrict__ ln_b,
                            const float* __restrict__ Wz)
{
    __shared__ float sB[CZ*NH];
    __shared__ float sG[CZ*NH];
    int c = threadIdx.x;
    float g = ln_g[c], bb = ln_b[c];
    #pragma unroll
    for (int h = 0; h < NH; h++) {
        float w = Wz[c*NH + h];
        float gz = g*w;
        d_Gz[c*NH + h] = gz;
        sG[c*NH + h] = gz;
        sB[c*NH + h] = bb*w;
    }
    __syncthreads();
    if (c < NH) {
        float sb = 0.f, sg = 0.f;
        for (int cc = 0; cc < CZ; cc++) { sb += sB[cc*NH + c]; sg += sG[cc*NH + c]; }
        d_Bh[c] = sb;
        d_GzSum[c] = sg;
    }
}

// ====== bias v4: direct gmem fragments with k-permutation (float4 loads), fp16 out ======
#define BM_GH 0            // Gz hi: 128 rows x 24 stride bf16 = 6144 B
#define BM_GL 6144
#define BM_SG 12288        // stage float[128*17] = 8704 B
#define BIAS_SMEM 21504

__global__ void __launch_bounds__(256) bias_mma(const float* __restrict__ z)
{
    extern __shared__ char smraw[];
    uint32_t sb = (uint32_t)__cvta_generic_to_shared(smraw);
    int tid = threadIdx.x, lane = tid & 31, wid = tid >> 5;
    int grp = lane >> 2, tL = lane & 3;
    int t8 = lane >> 3, r8 = lane & 7;

    // stage Gz with k-permutation matching the float4 fragment order:
    // mem col 4t+j (within 16-block) -> logical row 2t+j (j<2) or 8+2t+j-2 (j>=2)
    for (int t = tid; t < CZ*NH; t += 256) {
        int c = t >> 4, hh = t & 15;
        int cb = c & 15, tq = cb >> 2, j = cb & 3;
        int lr = (j < 2) ? (2*tq + j) : (8 + 2*tq + (j - 2));
        int row = (c & 0x70) | lr;
        float w = d_Gz[t];
        __nv_bfloat16 hi = __float2bfloat16(w);
        __nv_bfloat16 lo = __float2bfloat16(w - __bfloat162float(hi));
        ((__nv_bfloat16*)(smraw + BM_GH))[row*24 + hh] = hi;
        ((__nv_bfloat16*)(smraw + BM_GL))[row*24 + hh] = lo;
    }
    __syncthreads();

    const float* z0 = z + (size_t)(blockIdx.x*128 + wid*16 + grp)*CZ;
    const float* z1 = z0 + 8*CZ;

    int gRow = (t8 & 1)*8 + r8;
    int gCol = (t8 >> 1)*8;

    float acc0[4] = {0.f,0.f,0.f,0.f}, acc1[4] = {0.f,0.f,0.f,0.f};
    float s1_0 = 0.f, s2_0 = 0.f, s1_1 = 0.f, s2_1 = 0.f;

    #pragma unroll
    for (int kc = 0; kc < 8; kc++) {
        float4 f = *(const float4*)(z0 + kc*16 + tL*4);
        float4 g = *(const float4*)(z1 + kc*16 + tL*4);

        s1_0 += (f.x + f.y) + (f.z + f.w);
        s2_0 = fmaf(f.x,f.x, fmaf(f.y,f.y, fmaf(f.z,f.z, fmaf(f.w,f.w, s2_0))));
        s1_1 += (g.x + g.y) + (g.z + g.w);
        s2_1 = fmaf(g.x,g.x, fmaf(g.y,g.y, fmaf(g.z,g.z, fmaf(g.w,g.w, s2_1))));

        uint32_t Ahf[4], Alf[4];
        split2(f.x, f.y, Ahf[0], Alf[0]);   // logical k (2tL, 2tL+1), row grp
        split2(g.x, g.y, Ahf[1], Alf[1]);   // row grp+8
        split2(f.z, f.w, Ahf[2], Alf[2]);   // logical k (2tL+8, 2tL+9)
        split2(g.z, g.w, Ahf[3], Alf[3]);

        uint32_t Gh[4], Gl[4];
        uint32_t goff = (uint32_t)(((gRow + kc*16)*24 + gCol) * 2);
        ldsm4t(Gh, sb + BM_GH + goff);
        ldsm4t(Gl, sb + BM_GL + goff);

        mma_bf16(acc0, Ahf, &Gh[0]); mma_bf16(acc1, Ahf, &Gh[2]);
        mma_bf16(acc0, Alf, &Gh[0]); mma_bf16(acc1, Alf, &Gh[2]);
        mma_bf16(acc0, Ahf, &Gl[0]); mma_bf16(acc1, Ahf, &Gl[2]);
    }

    s1_0 += __shfl_xor_sync(0xFFFFFFFFu, s1_0, 1);
    s1_0 += __shfl_xor_sync(0xFFFFFFFFu, s1_0, 2);
    s2_0 += __shfl_xor_sync(0xFFFFFFFFu, s2_0, 1);
    s2_0 += __shfl_xor_sync(0xFFFFFFFFu, s2_0, 2);
    s1_1 += __shfl_xor_sync(0xFFFFFFFFu, s1_1, 1);
    s1_1 += __shfl_xor_sync(0xFFFFFFFFu, s1_1, 2);
    s2_1 += __shfl_xor_sync(0xFFFFFFFFu, s2_1, 1);
    s2_1 += __shfl_xor_sync(0xFFFFFFFFu, s2_1, 2);
    float mu0 = s1_0 * (1.f/128.f);
    float rstd0 = rsqrtf(s2_0 * (1.f/128.f) - mu0*mu0 + 1e-5f);
    float mu1 = s1_1 * (1.f/128.f);
    float rstd1 = rsqrtf(s2_1 * (1.f/128.f) - mu1*mu1 + 1e-5f);

    {
        int r0 = wid*16 + grp, r1 = r0 + 8;
        float* stage = (float*)(smraw + BM_SG);
        #pragma unroll
        for (int n = 0; n < 2; n++) {
            float* a = n ? acc1 : acc0;
            int h = n*8 + tL*2;
            float gs0 = d_GzSum[h], gs1 = d_GzSum[h+1];
            float bh0 = d_Bh[h],    bh1 = d_Bh[h+1];
            stage[r0*17 + h]     = rstd0*(a[0] - mu0*gs0) + bh0;
            stage[r0*17 + h + 1] = rstd0*(a[1] - mu0*gs1) + bh1;
            stage[r1*17 + h]     = rstd1*(a[2] - mu1*gs0) + bh0;
            stage[r1*17 + h + 1] = rstd1*(a[3] - mu1*gs1) + bh1;
        }
    }
    __syncthreads();

    // transposed write as fp16 (half2)
    {
        int p0  = blockIdx.x * 128;
        int b   = p0 / (Nn*Nn);
        int rem = p0 % (Nn*Nn);
        int ii  = rem / Nn;
        int j0  = rem % Nn;
        float* stage = (float*)(smraw + BM_SG);
        #pragma unroll
        for (int t = tid; t < 128*8; t += 256) {
            int h = t >> 6, rr2 = (t & 63) * 2;
            __half2 val = __floats2half2_rn(stage[rr2*17 + h], stage[(rr2+1)*17 + h]);
            *(__half2*)(d_bias + ((size_t)(b*NH + h)*Nn + ii)*Nn + j0 + rr2) = val;
        }
    }
}

// ========== flash attention v3: fp16 q(2-term)/k(1)/v(1), cp.async pipeline ==========
#define AT_STRIDE 72
#define AQ_H 0
#define AQ_L 9216
#define KV0 18432
#define KVSTAGE 18432        // Kh(9216) + Vh(9216)
#define OSM_OFF 0
#define OSM_STRIDE 68
#define STAT_OFF 34816
#define ATT_SMEM 55296

__global__ void __launch_bounds__(256, 2) attn_mma(const float* __restrict__ mask)
{
    extern __shared__ char smraw[];
    uint32_t sb = (uint32_t)__cvta_generic_to_shared(smraw);
    int tid = threadIdx.x, lane = tid & 31, wid = tid >> 5;
    int warpM = wid >> 1, warpN = wid & 1;
    int b = blockIdx.z, h = blockIdx.y, i0 = blockIdx.x * 64;
    int grp = lane >> 2, tL = lane & 3;
    int t8 = lane >> 3, r8 = lane & 7;

    {
        #pragma unroll
        for (int i = 0; i < 4; i++) {
            int g = tid + i*256;
            int mtx = g >> 9, r = (g >> 3) & 63, q = g & 7;
            const __nv_bfloat16* src = (mtx ? d_ql : d_qh) +
                (size_t)(b*Nn + i0 + r)*CS + h*HD + q*8;
            CPA(sb + mtx*9216 + r*144 + q*16, src);
        }
        #pragma unroll
        for (int i = 0; i < 4; i++) {
            int g = tid + i*256;
            int mtx = g >> 9, r = (g >> 3) & 63, q = g & 7;
            const __nv_bfloat16* src = (mtx ? d_vh : d_kh) +
                (size_t)(b*Nn + r)*CS + h*HD + q*8;
            CPA(sb + KV0 + mtx*9216 + r*144 + q*16, src);
        }
        CPCOMMIT();
    }

    float Oa[8][4];
    #pragma unroll
    for (int t = 0; t < 8; t++) { Oa[t][0]=0.f; Oa[t][1]=0.f; Oa[t][2]=0.f; Oa[t][3]=0.f; }
    float mrow0 = -1e30f, mrow1 = -1e30f, lsum0 = 0.f, lsum1 = 0.f;

    const float* maskp = mask + b*Nn;
    const __half* biasbase = d_bias + ((size_t)(b*NH + h)*Nn + (i0 + warpM*16 + grp))*Nn;

    int aRow  = warpM*16 + (t8 & 1)*8 + r8;
    int aCol  = (t8 >> 1)*8;
    int kRowB = warpN*32 + (t8 >> 1)*8 + r8;
    int kColB = (t8 & 1)*8;
    int vRowB = (t8 & 1)*8 + r8;
    int vColB = (t8 >> 1)*8;

    #pragma unroll 1
    for (int jt = 0; jt < 12; jt++) {
        int j0c = jt * 64;
        __syncthreads();
        if (jt + 1 < 12) {
            int st1 = (jt + 1) & 1;
            #pragma unroll
            for (int i = 0; i < 4; i++) {
                int g = tid + i*256;
                int mtx = g >> 9, r = (g >> 3) & 63, q = g & 7;
                const __nv_bfloat16* src = (mtx ? d_vh : d_kh) +
                    (size_t)(b*Nn + j0c + 64 + r)*CS + h*HD + q*8;
                CPA(sb + KV0 + st1*KVSTAGE + mtx*9216 + r*144 + q*16, src);
            }
        }
        CPCOMMIT();
        CPWAIT1();
        __syncthreads();

        uint32_t ks = sb + KV0 + (jt & 1)*KVSTAGE;

        // ---- S = (Qh+Ql) . Kh  (2 terms, fp16) ----
        float S[4][4];
        #pragma unroll
        for (int nt = 0; nt < 4; nt++) { S[nt][0]=0.f; S[nt][1]=0.f; S[nt][2]=0.f; S[nt][3]=0.f; }
        #pragma unroll
        for (int kk = 0; kk < 4; kk++) {
            uint32_t qh_[4], ql_[4], khf[2][4];
            uint32_t aoff = (uint32_t)((aRow*AT_STRIDE + kk*16 + aCol) * 2);
            ldsm4(qh_, sb + AQ_H + aoff);
            ldsm4(ql_, sb + AQ_L + aoff);
            uint32_t koff0 = (uint32_t)((kRowB*AT_STRIDE + kk*16 + kColB) * 2);
            uint32_t koff1 = (uint32_t)(((kRowB+16)*AT_STRIDE + kk*16 + kColB) * 2);
            ldsm4(khf[0], ks + koff0);
            ldsm4(khf[1], ks + koff1);
            #pragma unroll
            for (int nt = 0; nt < 4; nt++)
                mma_f16(S[nt], qh_, &khf[nt >> 1][(nt & 1)*2]);
            #pragma unroll
            for (int nt = 0; nt < 4; nt++)
                mma_f16(S[nt], ql_, &khf[nt >> 1][(nt & 1)*2]);
        }

        #pragma unroll
        for (int nt = 0; nt < 4; nt++) {
            int jc = j0c + warpN*32 + nt*8 + tL*2;
            float2 b0 = __half22float2(*(const __half2*)(biasbase + jc));
            float2 b1 = __half22float2(*(const __half2*)(biasbase + (size_t)8*Nn + jc));
            float2 mv = *(const float2*)(maskp + jc);
            float mk0 = (1.f - mv.x) * (-1000000.0f);
            float mk1 = (1.f - mv.y) * (-1000000.0f);
            S[nt][0] += b0.x + mk0; S[nt][1] += b0.y + mk1;
            S[nt][2] += b1.x + mk0; S[nt][3] += b1.y + mk1;
        }

        float cm0 = fmaxf(fmaxf(S[0][0], S[0][1]), fmaxf(S[1][0], S[1][1]));
        cm0 = fmaxf(cm0, fmaxf(fmaxf(S[2][0], S[2][1]), fmaxf(S[3][0], S[3][1])));
        float cm1 = fmaxf(fmaxf(S[0][2], S[0][3]), fmaxf(S[1][2], S[1][3]));
        cm1 = fmaxf(cm1, fmaxf(fmaxf(S[2][2], S[2][3]), fmaxf(S[3][2], S[3][3])));
        cm0 = fmaxf(cm0, __shfl_xor_sync(0xFFFFFFFFu, cm0, 1));
        cm0 = fmaxf(cm0, __shfl_xor_sync(0xFFFFFFFFu, cm0, 2));
        cm1 = fmaxf(cm1, __shfl_xor_sync(0xFFFFFFFFu, cm1, 1));
        cm1 = fmaxf(cm1, __shfl_xor_sync(0xFFFFFFFFu, cm1, 2));
        float mn0 = fmaxf(mrow0, cm0), mn1 = fmaxf(mrow1, cm1);
        float sc0 = __expf(mrow0 - mn0), sc1 = __expf(mrow1 - mn1);
        mrow0 = mn0; mrow1 = mn1;
        float rs0 = 0.f, rs1 = 0.f;
        #pragma unroll
        for (int nt = 0; nt < 4; nt++) {
            S[nt][0] = __expf(S[nt][0] - mn0);
            S[nt][1] = __expf(S[nt][1] - mn0);
            S[nt][2] = __expf(S[nt][2] - mn1);
            S[nt][3] = __expf(S[nt][3] - mn1);
            rs0 += S[nt][0] + S[nt][1];
            rs1 += S[nt][2] + S[nt][3];
        }
        rs0 += __shfl_xor_sync(0xFFFFFFFFu, rs0, 1);
        rs0 += __shfl_xor_sync(0xFFFFFFFFu, rs0, 2);
        rs1 += __shfl_xor_sync(0xFFFFFFFFu, rs1, 1);
        rs1 += __shfl_xor_sync(0xFFFFFFFFu, rs1, 2);
        lsum0 = lsum0*sc0 + rs0;
        lsum1 = lsum1*sc1 + rs1;
        #pragma unroll
        for (int t = 0; t < 8; t++) {
            Oa[t][0] *= sc0; Oa[t][1] *= sc0;
            Oa[t][2] *= sc1; Oa[t][3] *= sc1;
        }

        // ---- P fragments (fp16 2-term split) ----
        uint32_t Ph[2][4], Pl[2][4];
        #pragma unroll
        for (int kf = 0; kf < 2; kf++) {
            split2h(S[2*kf][0],   S[2*kf][1],   Ph[kf][0], Pl[kf][0]);
            split2h(S[2*kf][2],   S[2*kf][3],   Ph[kf][1], Pl[kf][1]);
            split2h(S[2*kf+1][0], S[2*kf+1][1], Ph[kf][2], Pl[kf][2]);
            split2h(S[2*kf+1][2], S[2*kf+1][3], Ph[kf][3], Pl[kf][3]);
        }

        // ---- O += (Ph+Pl) . Vh ----
        #pragma unroll
        for (int kf = 0; kf < 2; kf++) {
            int kb = warpN*32 + kf*16;
            #pragma unroll
            for (int ntp = 0; ntp < 4; ntp++) {
                uint32_t vhf[4];
                uint32_t voff = (uint32_t)(((kb + vRowB)*AT_STRIDE + ntp*16 + vColB) * 2);
                ldsm4t(vhf, ks + 9216 + voff);
                mma_f16(Oa[ntp*2],   Ph[kf], &vhf[0]);
                mma_f16(Oa[ntp*2+1], Ph[kf], &vhf[2]);
                mma_f16(Oa[ntp*2],   Pl[kf], &vhf[0]);
                mma_f16(Oa[ntp*2+1], Pl[kf], &vhf[2]);
            }
        }
    }

    __syncthreads();
    float* Osm  = (float*)(smraw + OSM_OFF);
    float* stat = (float*)(smraw + STAT_OFF);
    #pragma unroll
    for (int t = 0; t < 8; t++) {
        int dcol = t*8 + tL*2;
        Osm[(wid*16 + grp)*OSM_STRIDE + dcol]       = Oa[t][0];
        Osm[(wid*16 + grp)*OSM_STRIDE + dcol + 1]   = Oa[t][1];
        Osm[(wid*16 + grp+8)*OSM_STRIDE + dcol]     = Oa[t][2];
        Osm[(wid*16 + grp+8)*OSM_STRIDE + dcol + 1] = Oa[t][3];
    }
    if (tL == 0) {
        stat[wid*32 + grp*2]       = mrow0;
        stat[wid*32 + grp*2 + 1]   = lsum0;
        stat[wid*32 + (grp+8)*2]     = mrow1;
        stat[wid*32 + (grp+8)*2 + 1] = lsum1;
    }
    __syncthreads();

    for (int t = tid; t < 64*32; t += 256) {
        int row = t >> 5, d2 = (t & 31)*2;
        int w0 = (row >> 4)*2, rl = row & 15;
        float m0 = stat[w0*32 + rl*2],     l0 = stat[w0*32 + rl*2 + 1];
        float m1 = stat[(w0+1)*32 + rl*2], l1 = stat[(w0+1)*32 + rl*2 + 1];
        float mm = fmaxf(m0, m1);
        float a0 = __expf(m0 - mm), a1 = __expf(m1 - mm);
        float inv = 1.f / (a0*l0 + a1*l1);
        float o0 = (a0*Osm[(w0*16 + rl)*OSM_STRIDE + d2] +
                    a1*Osm[((w0+1)*16 + rl)*OSM_STRIDE + d2]) * inv;
        float o1 = (a0*Osm[(w0*16 + rl)*OSM_STRIDE + d2 + 1] +
                    a1*Osm[((w0+1)*16 + rl)*OSM_STRIDE + d2 + 1]) * inv;
        size_t gi = (size_t)(b*Nn + i0 + row)*CS + h*HD + d2;
        float2 gg = *(const float2*)(d_g + gi);
        uint32_t hh, ll;
        split2(gg.x * o0, gg.y * o1, hh, ll);
        *(uint32_t*)((char*)d_goh + gi*2) = hh;
        *(uint32_t*)((char*)d_gol + gi*2) = ll;
    }
}

// ---------------- launch: fork bias chain; bias stays launch #4 for ncu ----------------
extern "C" void kernel_launch(void* const* d_in, const int* in_sizes, int n_in,
                              void* d_out, int out_size)
{
    const float* s    = (const float*)d_in[0];
    const float* z    = (const float*)d_in[1];
    const float* mask = (const float*)d_in[2];
    const float* k_in = (const float*)d_in[3];
    const float* Wq   = (const float*)d_in[4];
    const float* bq   = (const float*)d_in[5];
    const float* Wk   = (const float*)d_in[6];
    const float* Wv   = (const float*)d_in[7];
    const float* Wg   = (const float*)d_in[8];
    const float* ln_g = (const float*)d_in[9];
    const float* ln_b = (const float*)d_in[10];
    const float* Wz   = (const float*)d_in[11];
    const float* Wo   = (const float*)d_in[12];
    float* out = (float*)d_out;

    static cudaStream_t s2 = nullptr;
    static cudaEvent_t evF = nullptr, evJ = nullptr;
    if (s2 == nullptr) {
        cudaStreamCreateWithFlags(&s2, cudaStreamNonBlocking);
        cudaEventCreateWithFlags(&evF, cudaEventDisableTiming);
        cudaEventCreateWithFlags(&evJ, cudaEventDisableTiming);
        cudaFuncSetAttribute(proj4_kernel, cudaFuncAttributeMaxDynamicSharedMemorySize, GEMM_SMEM);
        cudaFuncSetAttribute(final_gemm,   cudaFuncAttributeMaxDynamicSharedMemorySize, GEMM_SMEM);
        cudaFuncSetAttribute(attn_mma,     cudaFuncAttributeMaxDynamicSharedMemorySize, ATT_SMEM);
        cudaFuncSetAttribute(bias_mma,     cudaFuncAttributeMaxDynamicSharedMemorySize, BIAS_SMEM);
    }

    // stream A first two launches (submission #1, #2)
    cudaEventRecord(evF, 0);
    cudaStreamWaitEvent(s2, evF, 0);
    wconv_kernel<<<dim3(WSZ/1024, 5), 256>>>(Wq, Wk, Wv, Wg, Wo);
    aconv_kernel<<<dim3(MROWS*CS/1024, 2), 256>>>(s, k_in);

    // stream B: prep (#3) + bias_mma (#4 — profiler target)
    prep_kernel<<<1, 128, 0, s2>>>(ln_g, ln_b, Wz);
    bias_mma<<<NPAIR/128, 256, BIAS_SMEM, s2>>>(z);
    cudaEventRecord(evJ, s2);

    // stream A: projections (#5)
    proj4_kernel<<<dim3(CS/64, MROWS/128, 4), 256, GEMM_SMEM>>>(bq);

    // join, then attention (#6) + output projection (#7)
    cudaStreamWaitEvent(0, evJ, 0);
    attn_mma<<<dim3(Nn/64, NH, Bn), 256, ATT_SMEM>>>(mask);
    final_gemm<<<dim3(CS/64, MROWS/128), 256, GEMM_SMEM>>>(out);
}

// round 12
// speedup vs baseline: 3.8377x; 1.0058x over previous
#include <cuda_runtime.h>
#include <cuda_bf16.h>
#include <cuda_fp16.h>
#include <cstdint>
#include <cstddef>

#define Bn 2
#define Nn 768
#define CS 1024
#define CZ 128
#define NH 16
#define HD 64
#define MROWS (Bn*Nn)     // 1536
#define NPAIR (Bn*Nn*Nn)  // 1179648
#define WSZ (CS*CS)

// ---------------- scratch (device globals; no allocations allowed) ----------------
__device__ __nv_bfloat16 d_Wh[5*WSZ], d_Wl[5*WSZ];          // Wq,Wk,Wv,Wg,Wo split (bf16)
__device__ __nv_bfloat16 d_inh[2*MROWS*CS], d_inl[2*MROWS*CS]; // s, k_in split (bf16)
__device__ __nv_bfloat16 d_qh[MROWS*CS], d_ql[MROWS*CS];    // fp16 content (raw 16-bit)
__device__ __nv_bfloat16 d_kh[MROWS*CS], d_kl[MROWS*CS];    // kh used (fp16), kl unused
__device__ __nv_bfloat16 d_vh[MROWS*CS], d_vl[MROWS*CS];    // vh used (fp16), vl unused
__device__ __nv_bfloat16 d_goh[MROWS*CS], d_gol[MROWS*CS];  // bf16 split
__device__ float d_g[MROWS*CS];
__device__ __half d_bias[Bn*NH*Nn*Nn];    // fp16 bias (37.7 MB)
__device__ float d_Gz[CZ*NH];
__device__ float d_Bh[NH];
__device__ float d_GzSum[NH];

// ================= helpers ====================
__device__ __forceinline__ void ldsm4(uint32_t* r, uint32_t a) {
    asm volatile("ldmatrix.sync.aligned.m8n8.x4.shared.b16 {%0,%1,%2,%3}, [%4];"
                 : "=r"(r[0]), "=r"(r[1]), "=r"(r[2]), "=r"(r[3]) : "r"(a));
}
__device__ __forceinline__ void ldsm4t(uint32_t* r, uint32_t a) {
    asm volatile("ldmatrix.sync.aligned.m8n8.x4.trans.shared.b16 {%0,%1,%2,%3}, [%4];"
                 : "=r"(r[0]), "=r"(r[1]), "=r"(r[2]), "=r"(r[3]) : "r"(a));
}
__device__ __forceinline__ void mma_bf16(float* c, const uint32_t* a, const uint32_t* b) {
    asm volatile("mma.sync.aligned.m16n8k16.row.col.f32.bf16.bf16.f32 "
                 "{%0,%1,%2,%3}, {%4,%5,%6,%7}, {%8,%9}, {%0,%1,%2,%3};"
                 : "+f"(c[0]), "+f"(c[1]), "+f"(c[2]), "+f"(c[3])
                 : "r"(a[0]), "r"(a[1]), "r"(a[2]), "r"(a[3]), "r"(b[0]), "r"(b[1]));
}
__device__ __forceinline__ void mma_f16(float* c, const uint32_t* a, const uint32_t* b) {
    asm volatile("mma.sync.aligned.m16n8k16.row.col.f32.f16.f16.f32 "
                 "{%0,%1,%2,%3}, {%4,%5,%6,%7}, {%8,%9}, {%0,%1,%2,%3};"
                 : "+f"(c[0]), "+f"(c[1]), "+f"(c[2]), "+f"(c[3])
                 : "r"(a[0]), "r"(a[1]), "r"(a[2]), "r"(a[3]), "r"(b[0]), "r"(b[1]));
}
__device__ __forceinline__ void split2(float x, float y, uint32_t& hi, uint32_t& lo) {
    __nv_bfloat162 h = __float22bfloat162_rn(make_float2(x, y));
    float2 hf = __bfloat1622float2(h);
    __nv_bfloat162 l = __float22bfloat162_rn(make_float2(x - hf.x, y - hf.y));
    hi = *(uint32_t*)&h;
    lo = *(uint32_t*)&l;
}
__device__ __forceinline__ void split2h(float x, float y, uint32_t& hi, uint32_t& lo) {
    __half2 h = __floats2half2_rn(x, y);
    float2 hf = __half22float2(h);
    __half2 l = __floats2half2_rn(x - hf.x, y - hf.y);
    hi = *(uint32_t*)&h;
    lo = *(uint32_t*)&l;
}
#define CPA(dst, src) asm volatile("cp.async.cg.shared.global [%0], [%1], 16;" :: "r"(dst), "l"(src))
#define CPCOMMIT()    asm volatile("cp.async.commit_group;")
#define CPWAIT1()     asm volatile("cp.async.wait_group 1;")

// ---------------- pre-split converters ----------------
__global__ void __launch_bounds__(256) wconv_kernel(
    const float* __restrict__ W0, const float* __restrict__ W1,
    const float* __restrict__ W2, const float* __restrict__ W3,
    const float* __restrict__ W4)
{
    int which = blockIdx.y;
    const float* src = which == 0 ? W0 : which == 1 ? W1 : which == 2 ? W2 :
                       which == 3 ? W3 : W4;
    size_t idx = ((size_t)blockIdx.x * 256 + threadIdx.x) * 4;
    float4 v = *(const float4*)(src + idx);
    uint32_t h0, l0, h1, l1;
    split2(v.x, v.y, h0, l0);
    split2(v.z, v.w, h1, l1);
    size_t o = (size_t)which * WSZ + idx;
    *(uint2*)((char*)d_Wh + o*2) = make_uint2(h0, h1);
    *(uint2*)((char*)d_Wl + o*2) = make_uint2(l0, l1);
}
__global__ void __launch_bounds__(256) aconv_kernel(
    const float* __restrict__ A0, const float* __restrict__ A1)
{
    int which = blockIdx.y;
    const float* src = which == 0 ? A0 : A1;
    size_t idx = ((size_t)blockIdx.x * 256 + threadIdx.x) * 4;
    float4 v = *(const float4*)(src + idx);
    uint32_t h0, l0, h1, l1;
    split2(v.x, v.y, h0, l0);
    split2(v.z, v.w, h1, l1);
    size_t o = (size_t)which * MROWS * CS + idx;
    *(uint2*)((char*)d_inh + o*2) = make_uint2(h0, h1);
    *(uint2*)((char*)d_inl + o*2) = make_uint2(l0, l1);
}

// ================= GEMM: pre-split bf16 inputs, cp.async 3-stage =====
#define ASTRIDE 40
#define BSTRIDE 72
#define AHI_OFF 0
#define ALO_OFF 10240
#define BHI_OFF 20480
#define BLO_OFF 25088
#define BUFBYTES 29696
#define GEMM_SMEM (3*BUFBYTES)   // 89088

__device__ __forceinline__ void gemm_core(
    const __nv_bfloat16* __restrict__ Ah, const __nv_bfloat16* __restrict__ Al,
    const __nv_bfloat16* __restrict__ Bh, const __nv_bfloat16* __restrict__ Bl,
    const float* __restrict__ bq, int mode,
    float* __restrict__ Cf, __nv_bfloat16* __restrict__ Ch, __nv_bfloat16* __restrict__ Cl)
{
    extern __shared__ char sm_raw[];
    uint32_t sbase = (uint32_t)__cvta_generic_to_shared(sm_raw);

    int tid = threadIdx.x;
    int wid = tid >> 5, lane = tid & 31;
    int warpM = wid >> 1, warpN = wid & 1;
    int m0 = blockIdx.y * 128, n0 = blockIdx.x * 64;

    float acc[2][4][4];
    #pragma unroll
    for (int mt = 0; mt < 2; mt++)
        #pragma unroll
        for (int nt = 0; nt < 4; nt++)
            #pragma unroll
            for (int i = 0; i < 4; i++) acc[mt][nt][i] = 0.f;

    int matr = lane >> 3, rr = lane & 7;
    int aRowBase = warpM * 32 + (matr & 1) * 8 + rr;
    int aColBase = (matr >> 1) * 8;
    int bRowBase = (matr & 1) * 8 + rr;
    int bColBase = warpN * 32 + (matr >> 1) * 8;

    int arow = tid >> 2, aq = tid & 3;
    int brow = tid >> 3, bqc = tid & 7;

    auto issue = [&](int c, int buf) {
        uint32_t st = sbase + buf * BUFBYTES;
        #pragma unroll
        for (int r = 0; r < 2; r++) {
            int row = arow + r * 64;
            const __nv_bfloat16* sh = Ah + (size_t)(m0 + row) * CS + c * 32 + aq * 8;
            const __nv_bfloat16* sl = Al + (size_t)(m0 + row) * CS + c * 32 + aq * 8;
            uint32_t d = st + row * 80 + aq * 16;
            CPA(d + AHI_OFF, sh);
            CPA(d + ALO_OFF, sl);
        }
        {
            const __nv_bfloat16* sh = Bh + (size_t)(c * 32 + brow) * CS + n0 + bqc * 8;
            const __nv_bfloat16* sl = Bl + (size_t)(c * 32 + brow) * CS + n0 + bqc * 8;
            uint32_t d = st + brow * 144 + bqc * 16;
            CPA(d + BHI_OFF, sh);
            CPA(d + BLO_OFF, sl);
        }
    };

    issue(0, 0); CPCOMMIT();
    issue(1, 1); CPCOMMIT();

    const int CHUNKS = 32;
    for (int c = 0; c < CHUNKS; c++) {
        CPWAIT1();
        __syncthreads();
        if (c + 2 < CHUNKS) issue(c + 2, (c + 2) % 3);
        CPCOMMIT();

        uint32_t off = sbase + (c % 3) * BUFBYTES;
        #pragma unroll
        for (int ks = 0; ks < 32; ks += 16) {
            uint32_t Ahf[2][4], Alf[2][4], Bhf[2][4], Blf[2][4];
            #pragma unroll
            for (int mt = 0; mt < 2; mt++)
                ldsm4(Ahf[mt], off + AHI_OFF +
                      (((aRowBase + mt * 16) * ASTRIDE) + aColBase + ks) * 2);
            #pragma unroll
            for (int ntp = 0; ntp < 2; ntp++)
                ldsm4t(Bhf[ntp], off + BHI_OFF +
                       (((bRowBase + ks) * BSTRIDE) + bColBase + ntp * 16) * 2);
            #pragma unroll
            for (int mt = 0; mt < 2; mt++)
                #pragma unroll
                for (int nt = 0; nt < 4; nt++)
                    mma_bf16(acc[mt][nt], Ahf[mt], &Bhf[nt >> 1][(nt & 1) * 2]);
            #pragma unroll
            for (int mt = 0; mt < 2; mt++)
                ldsm4(Alf[mt], off + ALO_OFF +
                      (((aRowBase + mt * 16) * ASTRIDE) + aColBase + ks) * 2);
            #pragma unroll
            for (int mt = 0; mt < 2; mt++)
                #pragma unroll
                for (int nt = 0; nt < 4; nt++)
                    mma_bf16(acc[mt][nt], Alf[mt], &Bhf[nt >> 1][(nt & 1) * 2]);
            #pragma unroll
            for (int ntp = 0; ntp < 2; ntp++)
                ldsm4t(Blf[ntp], off + BLO_OFF +
                       (((bRowBase + ks) * BSTRIDE) + bColBase + ntp * 16) * 2);
            #pragma unroll
            for (int mt = 0; mt < 2; mt++)
                #pragma unroll
                for (int nt = 0; nt < 4; nt++)
                    mma_bf16(acc[mt][nt], Ahf[mt], &Blf[nt >> 1][(nt & 1) * 2]);
        }
    }

    int grp = lane >> 2, tL = lane & 3;
    #pragma unroll
    for (int mt = 0; mt < 2; mt++) {
        #pragma unroll
        for (int nt = 0; nt < 4; nt++) {
            int row = m0 + warpM * 32 + mt * 16 + grp;
            int col = n0 + warpN * 32 + nt * 8 + tL * 2;
            float v0 = acc[mt][nt][0], v1 = acc[mt][nt][1];
            float v2 = acc[mt][nt][2], v3 = acc[mt][nt][3];
            if (mode == 0) {
                float b0 = bq[col], b1 = bq[col + 1];
                v0 = (v0 + b0) * 0.125f; v1 = (v1 + b1) * 0.125f;
                v2 = (v2 + b0) * 0.125f; v3 = (v3 + b1) * 0.125f;
                uint32_t h0, l0, h1, l1;
                split2h(v0, v1, h0, l0);
                split2h(v2, v3, h1, l1);
                *(uint32_t*)((char*)Ch + ((size_t)row * CS + col) * 2)       = h0;
                *(uint32_t*)((char*)Cl + ((size_t)row * CS + col) * 2)       = l0;
                *(uint32_t*)((char*)Ch + ((size_t)(row + 8) * CS + col) * 2) = h1;
                *(uint32_t*)((char*)Cl + ((size_t)(row + 8) * CS + col) * 2) = l1;
            } else if (mode == 1 || mode == 2) {
                __half2 a = __floats2half2_rn(v0, v1);
                __half2 b2 = __floats2half2_rn(v2, v3);
                *(uint32_t*)((char*)Ch + ((size_t)row * CS + col) * 2)       = *(uint32_t*)&a;
                *(uint32_t*)((char*)Ch + ((size_t)(row + 8) * CS + col) * 2) = *(uint32_t*)&b2;
            } else if (mode == 3) {
                v0 = 1.f/(1.f + __expf(-v0)); v1 = 1.f/(1.f + __expf(-v1));
                v2 = 1.f/(1.f + __expf(-v2)); v3 = 1.f/(1.f + __expf(-v3));
                *(float2*)(Cf + (size_t)row * CS + col)       = make_float2(v0, v1);
                *(float2*)(Cf + (size_t)(row + 8) * CS + col) = make_float2(v2, v3);
            } else {
                *(float2*)(Cf + (size_t)row * CS + col)       = make_float2(v0, v1);
                *(float2*)(Cf + (size_t)(row + 8) * CS + col) = make_float2(v2, v3);
            }
        }
    }
}

__global__ void __launch_bounds__(256) proj4_kernel(const float* __restrict__ bq)
{
    int which = blockIdx.z;
    const __nv_bfloat16* Ah = (which == 0 || which == 3) ? d_inh : d_inh + MROWS*CS;
    const __nv_bfloat16* Al = (which == 0 || which == 3) ? d_inl : d_inl + MROWS*CS;
    const __nv_bfloat16* Bh = d_Wh + (size_t)which * WSZ;
    const __nv_bfloat16* Bl = d_Wl + (size_t)which * WSZ;
    __nv_bfloat16* Ch = which == 0 ? d_qh : which == 1 ? d_kh : which == 2 ? d_vh : nullptr;
    __nv_bfloat16* Cl = which == 0 ? d_ql : nullptr;
    gemm_core(Ah, Al, Bh, Bl, bq, which, d_g, Ch, Cl);
}

__global__ void __launch_bounds__(256) final_gemm(float* __restrict__ out)
{
    gemm_core(d_goh, d_gol, d_Wh + 4*(size_t)WSZ, d_Wl + 4*(size_t)WSZ,
              nullptr, 4, out, nullptr, nullptr);
}

// ---------------- fold LN affine into z-projection ----------------
__global__ void prep_kernel(const float* __restrict__ ln_g,
                            const float* __restrict__ ln_b,
                            const float* __restrict__ Wz)
{
    __shared__ float sB[CZ*NH];
    __shared__ float sG[CZ*NH];
    int c = threadIdx.x;
    float g = ln_g[c], bb = ln_b[c];
    #pragma unroll
    for (int h = 0; h < NH; h++) {
        float w = Wz[c*NH + h];
        float gz = g*w;
        d_Gz[c*NH + h] = gz;
        sG[c*NH + h] = gz;
        sB[c*NH + h] = bb*w;
    }
    __syncthreads();
    if (c < NH) {
        float sb = 0.f, sg = 0.f;
        for (int cc = 0; cc < CZ; cc++) { sb += sB[cc*NH + c]; sg += sG[cc*NH + c]; }
        d_Bh[c] = sb;
        d_GzSum[c] = sg;
    }
}

// ====== bias v4: direct gmem fragments with k-permutation (float4 loads), fp16 out ======
#define BM_GH 0
#define BM_GL 6144
#define BM_SG 12288
#define BIAS_SMEM 21504

__global__ void __launch_bounds__(256) bias_mma(const float* __restrict__ z)
{
    extern __shared__ char smraw[];
    uint32_t sb = (uint32_t)__cvta_generic_to_shared(smraw);
    int tid = threadIdx.x, lane = tid & 31, wid = tid >> 5;
    int grp = lane >> 2, tL = lane & 3;
    int t8 = lane >> 3, r8 = lane & 7;

    for (int t = tid; t < CZ*NH; t += 256) {
        int c = t >> 4, hh = t & 15;
        int cb = c & 15, tq = cb >> 2, j = cb & 3;
        int lr = (j < 2) ? (2*tq + j) : (8 + 2*tq + (j - 2));
        int row = (c & 0x70) | lr;
        float w = d_Gz[t];
        __nv_bfloat16 hi = __float2bfloat16(w);
        __nv_bfloat16 lo = __float2bfloat16(w - __bfloat162float(hi));
        ((__nv_bfloat16*)(smraw + BM_GH))[row*24 + hh] = hi;
        ((__nv_bfloat16*)(smraw + BM_GL))[row*24 + hh] = lo;
    }
    __syncthreads();

    const float* z0 = z + (size_t)(blockIdx.x*128 + wid*16 + grp)*CZ;
    const float* z1 = z0 + 8*CZ;

    int gRow = (t8 & 1)*8 + r8;
    int gCol = (t8 >> 1)*8;

    float acc0[4] = {0.f,0.f,0.f,0.f}, acc1[4] = {0.f,0.f,0.f,0.f};
    float s1_0 = 0.f, s2_0 = 0.f, s1_1 = 0.f, s2_1 = 0.f;

    #pragma unroll
    for (int kc = 0; kc < 8; kc++) {
        float4 f = *(const float4*)(z0 + kc*16 + tL*4);
        float4 g = *(const float4*)(z1 + kc*16 + tL*4);

        s1_0 += (f.x + f.y) + (f.z + f.w);
        s2_0 = fmaf(f.x,f.x, fmaf(f.y,f.y, fmaf(f.z,f.z, fmaf(f.w,f.w, s2_0))));
        s1_1 += (g.x + g.y) + (g.z + g.w);
        s2_1 = fmaf(g.x,g.x, fmaf(g.y,g.y, fmaf(g.z,g.z, fmaf(g.w,g.w, s2_1))));

        uint32_t Ahf[4], Alf[4];
        split2(f.x, f.y, Ahf[0], Alf[0]);
        split2(g.x, g.y, Ahf[1], Alf[1]);
        split2(f.z, f.w, Ahf[2], Alf[2]);
        split2(g.z, g.w, Ahf[3], Alf[3]);

        uint32_t Gh[4], Gl[4];
        uint32_t goff = (uint32_t)(((gRow + kc*16)*24 + gCol) * 2);
        ldsm4t(Gh, sb + BM_GH + goff);
        ldsm4t(Gl, sb + BM_GL + goff);

        mma_bf16(acc0, Ahf, &Gh[0]); mma_bf16(acc1, Ahf, &Gh[2]);
        mma_bf16(acc0, Alf, &Gh[0]); mma_bf16(acc1, Alf, &Gh[2]);
        mma_bf16(acc0, Ahf, &Gl[0]); mma_bf16(acc1, Ahf, &Gl[2]);
    }

    s1_0 += __shfl_xor_sync(0xFFFFFFFFu, s1_0, 1);
    s1_0 += __shfl_xor_sync(0xFFFFFFFFu, s1_0, 2);
    s2_0 += __shfl_xor_sync(0xFFFFFFFFu, s2_0, 1);
    s2_0 += __shfl_xor_sync(0xFFFFFFFFu, s2_0, 2);
    s1_1 += __shfl_xor_sync(0xFFFFFFFFu, s1_1, 1);
    s1_1 += __shfl_xor_sync(0xFFFFFFFFu, s1_1, 2);
    s2_1 += __shfl_xor_sync(0xFFFFFFFFu, s2_1, 1);
    s2_1 += __shfl_xor_sync(0xFFFFFFFFu, s2_1, 2);
    float mu0 = s1_0 * (1.f/128.f);
    float rstd0 = rsqrtf(s2_0 * (1.f/128.f) - mu0*mu0 + 1e-5f);
    float mu1 = s1_1 * (1.f/128.f);
    float rstd1 = rsqrtf(s2_1 * (1.f/128.f) - mu1*mu1 + 1e-5f);

    {
        int r0 = wid*16 + grp, r1 = r0 + 8;
        float* stage = (float*)(smraw + BM_SG);
        #pragma unroll
        for (int n = 0; n < 2; n++) {
            float* a = n ? acc1 : acc0;
            int h = n*8 + tL*2;
            float gs0 = d_GzSum[h], gs1 = d_GzSum[h+1];
            float bh0 = d_Bh[h],    bh1 = d_Bh[h+1];
            stage[r0*17 + h]     = rstd0*(a[0] - mu0*gs0) + bh0;
            stage[r0*17 + h + 1] = rstd0*(a[1] - mu0*gs1) + bh1;
            stage[r1*17 + h]     = rstd1*(a[2] - mu1*gs0) + bh0;
            stage[r1*17 + h + 1] = rstd1*(a[3] - mu1*gs1) + bh1;
        }
    }
    __syncthreads();

    {
        int p0  = blockIdx.x * 128;
        int b   = p0 / (Nn*Nn);
        int rem = p0 % (Nn*Nn);
        int ii  = rem / Nn;
        int j0  = rem % Nn;
        float* stage = (float*)(smraw + BM_SG);
        #pragma unroll
        for (int t = tid; t < 128*8; t += 256) {
            int h = t >> 6, rr2 = (t & 63) * 2;
            __half2 val = __floats2half2_rn(stage[rr2*17 + h], stage[(rr2+1)*17 + h]);
            *(__half2*)(d_bias + ((size_t)(b*NH + h)*Nn + ii)*Nn + j0 + rr2) = val;
        }
    }
}

// ========== flash attention v4: 128 threads, 32-row i-tile, 4 blocks/SM ==========
#define AT_STRIDE 72
#define AQ_H 0
#define AQ_L 4608
#define KV0 9216
#define KVSTAGE 18432        // Kh(9216) + Vh(9216)
#define OSM_OFF 0
#define OSM_STRIDE 68
#define STAT_OFF 17408
#define ATT_SMEM 46080

__global__ void __launch_bounds__(128, 4) attn_mma(const float* __restrict__ mask)
{
    extern __shared__ char smraw[];
    uint32_t sb = (uint32_t)__cvta_generic_to_shared(smraw);
    int tid = threadIdx.x, lane = tid & 31, wid = tid >> 5;
    int warpM = wid >> 1, warpN = wid & 1;
    int b = blockIdx.z, h = blockIdx.y, i0 = blockIdx.x * 32;
    int grp = lane >> 2, tL = lane & 3;
    int t8 = lane >> 3, r8 = lane & 7;

    {
        #pragma unroll
        for (int i = 0; i < 4; i++) {
            int g = tid + i*128;
            int mtx = g >> 8, r = (g >> 3) & 31, q = g & 7;
            const __nv_bfloat16* src = (mtx ? d_ql : d_qh) +
                (size_t)(b*Nn + i0 + r)*CS + h*HD + q*8;
            CPA(sb + mtx*4608 + r*144 + q*16, src);
        }
        #pragma unroll
        for (int i = 0; i < 8; i++) {
            int g = tid + i*128;
            int mtx = g >> 9, r = (g >> 3) & 63, q = g & 7;
            const __nv_bfloat16* src = (mtx ? d_vh : d_kh) +
                (size_t)(b*Nn + r)*CS + h*HD + q*8;
            CPA(sb + KV0 + mtx*9216 + r*144 + q*16, src);
        }
        CPCOMMIT();
    }

    float Oa[8][4];
    #pragma unroll
    for (int t = 0; t < 8; t++) { Oa[t][0]=0.f; Oa[t][1]=0.f; Oa[t][2]=0.f; Oa[t][3]=0.f; }
    float mrow0 = -1e30f, mrow1 = -1e30f, lsum0 = 0.f, lsum1 = 0.f;

    const float* maskp = mask + b*Nn;
    const __half* biasbase = d_bias + ((size_t)(b*NH + h)*Nn + (i0 + warpM*16 + grp))*Nn;

    int aRow  = warpM*16 + (t8 & 1)*8 + r8;
    int aCol  = (t8 >> 1)*8;
    int kRowB = warpN*32 + (t8 >> 1)*8 + r8;
    int kColB = (t8 & 1)*8;
    int vRowB = (t8 & 1)*8 + r8;
    int vColB = (t8 >> 1)*8;

    #pragma unroll 1
    for (int jt = 0; jt < 12; jt++) {
        int j0c = jt * 64;
        __syncthreads();
        if (jt + 1 < 12) {
            int st1 = (jt + 1) & 1;
            #pragma unroll
            for (int i = 0; i < 8; i++) {
                int g = tid + i*128;
                int mtx = g >> 9, r = (g >> 3) & 63, q = g & 7;
                const __nv_bfloat16* src = (mtx ? d_vh : d_kh) +
                    (size_t)(b*Nn + j0c + 64 + r)*CS + h*HD + q*8;
                CPA(sb + KV0 + st1*KVSTAGE + mtx*9216 + r*144 + q*16, src);
            }
        }
        CPCOMMIT();
        CPWAIT1();
        __syncthreads();

        uint32_t ks = sb + KV0 + (jt & 1)*KVSTAGE;

        // ---- S = (Qh+Ql) . Kh  (2 terms, fp16) ----
        float S[4][4];
        #pragma unroll
        for (int nt = 0; nt < 4; nt++) { S[nt][0]=0.f; S[nt][1]=0.f; S[nt][2]=0.f; S[nt][3]=0.f; }
        #pragma unroll
        for (int kk = 0; kk < 4; kk++) {
            uint32_t qh_[4], ql_[4], khf[2][4];
            uint32_t aoff = (uint32_t)((aRow*AT_STRIDE + kk*16 + aCol) * 2);
            ldsm4(qh_, sb + AQ_H + aoff);
            ldsm4(ql_, sb + AQ_L + aoff);
            uint32_t koff0 = (uint32_t)((kRowB*AT_STRIDE + kk*16 + kColB) * 2);
            uint32_t koff1 = (uint32_t)(((kRowB+16)*AT_STRIDE + kk*16 + kColB) * 2);
            ldsm4(khf[0], ks + koff0);
            ldsm4(khf[1], ks + koff1);
            #pragma unroll
            for (int nt = 0; nt < 4; nt++)
                mma_f16(S[nt], qh_, &khf[nt >> 1][(nt & 1)*2]);
            #pragma unroll
            for (int nt = 0; nt < 4; nt++)
                mma_f16(S[nt], ql_, &khf[nt >> 1][(nt & 1)*2]);
        }

        #pragma unroll
        for (int nt = 0; nt < 4; nt++) {
            int jc = j0c + warpN*32 + nt*8 + tL*2;
            float2 b0 = __half22float2(*(const __half2*)(biasbase + jc));
            float2 b1 = __half22float2(*(const __half2*)(biasbase + (size_t)8*Nn + jc));
            float2 mv = *(const float2*)(maskp + jc);
            float mk0 = (1.f - mv.x) * (-1000000.0f);
            float mk1 = (1.f - mv.y) * (-1000000.0f);
            S[nt][0] += b0.x + mk0; S[nt][1] += b0.y + mk1;
            S[nt][2] += b1.x + mk0; S[nt][3] += b1.y + mk1;
        }

        float cm0 = fmaxf(fmaxf(S[0][0], S[0][1]), fmaxf(S[1][0], S[1][1]));
        cm0 = fmaxf(cm0, fmaxf(fmaxf(S[2][0], S[2][1]), fmaxf(S[3][0], S[3][1])));
        float cm1 = fmaxf(fmaxf(S[0][2], S[0][3]), fmaxf(S[1][2], S[1][3]));
        cm1 = fmaxf(cm1, fmaxf(fmaxf(S[2][2], S[2][3]), fmaxf(S[3][2], S[3][3])));
        cm0 = fmaxf(cm0, __shfl_xor_sync(0xFFFFFFFFu, cm0, 1));
        cm0 = fmaxf(cm0, __shfl_xor_sync(0xFFFFFFFFu, cm0, 2));
        cm1 = fmaxf(cm1, __shfl_xor_sync(0xFFFFFFFFu, cm1, 1));
        cm1 = fmaxf(cm1, __shfl_xor_sync(0xFFFFFFFFu, cm1, 2));
        float mn0 = fmaxf(mrow0, cm0), mn1 = fmaxf(mrow1, cm1);
        float sc0 = __expf(mrow0 - mn0), sc1 = __expf(mrow1 - mn1);
        mrow0 = mn0; mrow1 = mn1;
        float rs0 = 0.f, rs1 = 0.f;
        #pragma unroll
        for (int nt = 0; nt < 4; nt++) {
            S[nt][0] = __expf(S[nt][0] - mn0);
            S[nt][1] = __expf(S[nt][1] - mn0);
            S[nt][2] = __expf(S[nt][2] - mn1);
            S[nt][3] = __expf(S[nt][3] - mn1);
            rs0 += S[nt][0] + S[nt][1];
            rs1 += S[nt][2] + S[nt][3];
        }
        rs0 += __shfl_xor_sync(0xFFFFFFFFu, rs0, 1);
        rs0 += __shfl_xor_sync(0xFFFFFFFFu, rs0, 2);
        rs1 += __shfl_xor_sync(0xFFFFFFFFu, rs1, 1);
        rs1 += __shfl_xor_sync(0xFFFFFFFFu, rs1, 2);
        lsum0 = lsum0*sc0 + rs0;
        lsum1 = lsum1*sc1 + rs1;
        #pragma unroll
        for (int t = 0; t < 8; t++) {
            Oa[t][0] *= sc0; Oa[t][1] *= sc0;
            Oa[t][2] *= sc1; Oa[t][3] *= sc1;
        }

        uint32_t Ph[2][4], Pl[2][4];
        #pragma unroll
        for (int kf = 0; kf < 2; kf++) {
            split2h(S[2*kf][0],   S[2*kf][1],   Ph[kf][0], Pl[kf][0]);
            split2h(S[2*kf][2],   S[2*kf][3],   Ph[kf][1], Pl[kf][1]);
            split2h(S[2*kf+1][0], S[2*kf+1][1], Ph[kf][2], Pl[kf][2]);
            split2h(S[2*kf+1][2], S[2*kf+1][3], Ph[kf][3], Pl[kf][3]);
        }

        #pragma unroll
        for (int kf = 0; kf < 2; kf++) {
            int kb = warpN*32 + kf*16;
            #pragma unroll
            for (int ntp = 0; ntp < 4; ntp++) {
                uint32_t vhf[4];
                uint32_t voff = (uint32_t)(((kb + vRowB)*AT_STRIDE + ntp*16 + vColB) * 2);
                ldsm4t(vhf, ks + 9216 + voff);
                mma_f16(Oa[ntp*2],   Ph[kf], &vhf[0]);
                mma_f16(Oa[ntp*2+1], Ph[kf], &vhf[2]);
                mma_f16(Oa[ntp*2],   Pl[kf], &vhf[0]);
                mma_f16(Oa[ntp*2+1], Pl[kf], &vhf[2]);
            }
        }
    }

    __syncthreads();
    float* Osm  = (float*)(smraw + OSM_OFF);
    float* stat = (float*)(smraw + STAT_OFF);
    #pragma unroll
    for (int t = 0; t < 8; t++) {
        int dcol = t*8 + tL*2;
        Osm[(wid*16 + grp)*OSM_STRIDE + dcol]       = Oa[t][0];
        Osm[(wid*16 + grp)*OSM_STRIDE + dcol + 1]   = Oa[t][1];
        Osm[(wid*16 + grp+8)*OSM_STRIDE + dcol]     = Oa[t][2];
        Osm[(wid*16 + grp+8)*OSM_STRIDE + dcol + 1] = Oa[t][3];
    }
    if (tL == 0) {
        stat[wid*32 + grp*2]       = mrow0;
        stat[wid*32 + grp*2 + 1]   = lsum0;
        stat[wid*32 + (grp+8)*2]     = mrow1;
        stat[wid*32 + (grp+8)*2 + 1] = lsum1;
    }
    __syncthreads();

    for (int t = tid; t < 32*32; t += 128) {
        int row = t >> 5, d2 = (t & 31)*2;
        int w0 = (row >> 4)*2, rl = row & 15;
        float m0 = stat[w0*32 + rl*2],     l0 = stat[w0*32 + rl*2 + 1];
        float m1 = stat[(w0+1)*32 + rl*2], l1 = stat[(w0+1)*32 + rl*2 + 1];
        float mm = fmaxf(m0, m1);
        float a0 = __expf(m0 - mm), a1 = __expf(m1 - mm);
        float inv = 1.f / (a0*l0 + a1*l1);
        float o0 = (a0*Osm[(w0*16 + rl)*OSM_STRIDE + d2] +
                    a1*Osm[((w0+1)*16 + rl)*OSM_STRIDE + d2]) * inv;
        float o1 = (a0*Osm[(w0*16 + rl)*OSM_STRIDE + d2 + 1] +
                    a1*Osm[((w0+1)*16 + rl)*OSM_STRIDE + d2 + 1]) * inv;
        size_t gi = (size_t)(b*Nn + i0 + row)*CS + h*HD + d2;
        float2 gg = *(const float2*)(d_g + gi);
        uint32_t hh, ll;
        split2(gg.x * o0, gg.y * o1, hh, ll);
        *(uint32_t*)((char*)d_goh + gi*2) = hh;
        *(uint32_t*)((char*)d_gol + gi*2) = ll;
    }
}

// ---------------- launch: fork bias chain; proj4 is submission #4 for ncu ----------------
extern "C" void kernel_launch(void* const* d_in, const int* in_sizes, int n_in,
                              void* d_out, int out_size)
{
    const float* s    = (const float*)d_in[0];
    const float* z    = (const float*)d_in[1];
    const float* mask = (const float*)d_in[2];
    const float* k_in = (const float*)d_in[3];
    const float* Wq   = (const float*)d_in[4];
    const float* bq   = (const float*)d_in[5];
    const float* Wk   = (const float*)d_in[6];
    const float* Wv   = (const float*)d_in[7];
    const float* Wg   = (const float*)d_in[8];
    const float* ln_g = (const float*)d_in[9];
    const float* ln_b = (const float*)d_in[10];
    const float* Wz   = (const float*)d_in[11];
    const float* Wo   = (const float*)d_in[12];
    float* out = (float*)d_out;

    static cudaStream_t s2 = nullptr;
    static cudaEvent_t evF = nullptr, evJ = nullptr;
    if (s2 == nullptr) {
        cudaStreamCreateWithFlags(&s2, cudaStreamNonBlocking);
        cudaEventCreateWithFlags(&evF, cudaEventDisableTiming);
        cudaEventCreateWithFlags(&evJ, cudaEventDisableTiming);
        cudaFuncSetAttribute(proj4_kernel, cudaFuncAttributeMaxDynamicSharedMemorySize, GEMM_SMEM);
        cudaFuncSetAttribute(final_gemm,   cudaFuncAttributeMaxDynamicSharedMemorySize, GEMM_SMEM);
        cudaFuncSetAttribute(attn_mma,     cudaFuncAttributeMaxDynamicSharedMemorySize, ATT_SMEM);
        cudaFuncSetAttribute(bias_mma,     cudaFuncAttributeMaxDynamicSharedMemorySize, BIAS_SMEM);
    }

    // stream A (#1, #2)
    cudaEventRecord(evF, 0);
    cudaStreamWaitEvent(s2, evF, 0);
    wconv_kernel<<<dim3(WSZ/1024, 5), 256>>>(Wq, Wk, Wv, Wg, Wo);
    aconv_kernel<<<dim3(MROWS*CS/1024, 2), 256>>>(s, k_in);

    // stream B: prep (#3); stream A: proj4 (#4 — profiler target); stream B: bias (#5)
    prep_kernel<<<1, 128, 0, s2>>>(ln_g, ln_b, Wz);
    proj4_kernel<<<dim3(CS/64, MROWS/128, 4), 256, GEMM_SMEM>>>(bq);
    bias_mma<<<NPAIR/128, 256, BIAS_SMEM, s2>>>(z);
    cudaEventRecord(evJ, s2);

    // join, then attention (#6) + output projection (#7)
    cudaStreamWaitEvent(0, evJ, 0);
    attn_mma<<<dim3(Nn/32, NH, Bn), 128, ATT_SMEM>>>(mask);
    final_gemm<<<dim3(CS/64, MROWS/128), 256, GEMM_SMEM>>>(out);
}

// round 13
// speedup vs baseline: 4.4629x; 1.1629x over previous
#include <cuda_runtime.h>
#include <cuda_bf16.h>
#include <cuda_fp16.h>
#include <cstdint>
#include <cstddef>

#define Bn 2
#define Nn 768
#define CS 1024
#define CZ 128
#define NH 16
#define HD 64
#define MROWS (Bn*Nn)     // 1536
#define NPAIR (Bn*Nn*Nn)  // 1179648
#define WSZ (CS*CS)

// ---------------- scratch (device globals; no allocations allowed) ----------------
// raw 16-bit storage; content is fp16 bits for everything GEMM/attn-related now
__device__ __nv_bfloat16 d_Wh[5*WSZ];                        // weights, single fp16
__device__ __nv_bfloat16 d_inh[2*MROWS*CS], d_inl[2*MROWS*CS]; // s, k_in fp16 2-term
__device__ __nv_bfloat16 d_qh[MROWS*CS], d_ql[MROWS*CS];    // q fp16 2-term
__device__ __nv_bfloat16 d_kh[MROWS*CS];                    // k fp16
__device__ __nv_bfloat16 d_vh[MROWS*CS];                    // v fp16
__device__ __nv_bfloat16 d_goh[MROWS*CS], d_gol[MROWS*CS];  // go fp16 2-term
__device__ float d_g[MROWS*CS];
__device__ __half d_bias[Bn*NH*Nn*Nn];    // fp16 bias (37.7 MB)
__device__ float d_Gz[CZ*NH];
__device__ float d_Bh[NH];
__device__ float d_GzSum[NH];

// ================= helpers ====================
__device__ __forceinline__ void ldsm4(uint32_t* r, uint32_t a) {
    asm volatile("ldmatrix.sync.aligned.m8n8.x4.shared.b16 {%0,%1,%2,%3}, [%4];"
                 : "=r"(r[0]), "=r"(r[1]), "=r"(r[2]), "=r"(r[3]) : "r"(a));
}
__device__ __forceinline__ void ldsm4t(uint32_t* r, uint32_t a) {
    asm volatile("ldmatrix.sync.aligned.m8n8.x4.trans.shared.b16 {%0,%1,%2,%3}, [%4];"
                 : "=r"(r[0]), "=r"(r[1]), "=r"(r[2]), "=r"(r[3]) : "r"(a));
}
__device__ __forceinline__ void mma_bf16(float* c, const uint32_t* a, const uint32_t* b) {
    asm volatile("mma.sync.aligned.m16n8k16.row.col.f32.bf16.bf16.f32 "
                 "{%0,%1,%2,%3}, {%4,%5,%6,%7}, {%8,%9}, {%0,%1,%2,%3};"
                 : "+f"(c[0]), "+f"(c[1]), "+f"(c[2]), "+f"(c[3])
                 : "r"(a[0]), "r"(a[1]), "r"(a[2]), "r"(a[3]), "r"(b[0]), "r"(b[1]));
}
__device__ __forceinline__ void mma_f16(float* c, const uint32_t* a, const uint32_t* b) {
    asm volatile("mma.sync.aligned.m16n8k16.row.col.f32.f16.f16.f32 "
                 "{%0,%1,%2,%3}, {%4,%5,%6,%7}, {%8,%9}, {%0,%1,%2,%3};"
                 : "+f"(c[0]), "+f"(c[1]), "+f"(c[2]), "+f"(c[3])
                 : "r"(a[0]), "r"(a[1]), "r"(a[2]), "r"(a[3]), "r"(b[0]), "r"(b[1]));
}
__device__ __forceinline__ void split2(float x, float y, uint32_t& hi, uint32_t& lo) {
    __nv_bfloat162 h = __float22bfloat162_rn(make_float2(x, y));
    float2 hf = __bfloat1622float2(h);
    __nv_bfloat162 l = __float22bfloat162_rn(make_float2(x - hf.x, y - hf.y));
    hi = *(uint32_t*)&h;
    lo = *(uint32_t*)&l;
}
__device__ __forceinline__ void split2h(float x, float y, uint32_t& hi, uint32_t& lo) {
    __half2 h = __floats2half2_rn(x, y);
    float2 hf = __half22float2(h);
    __half2 l = __floats2half2_rn(x - hf.x, y - hf.y);
    hi = *(uint32_t*)&h;
    lo = *(uint32_t*)&l;
}
#define CPA(dst, src) asm volatile("cp.async.cg.shared.global [%0], [%1], 16;" :: "r"(dst), "l"(src))
#define CPCOMMIT()    asm volatile("cp.async.commit_group;")
#define CPWAIT1()     asm volatile("cp.async.wait_group 1;")

// ---------------- pre-split converters ----------------
// weights: single fp16
__global__ void __launch_bounds__(256) wconv_kernel(
    const float* __restrict__ W0, const float* __restrict__ W1,
    const float* __restrict__ W2, const float* __restrict__ W3,
    const float* __restrict__ W4)
{
    int which = blockIdx.y;
    const float* src = which == 0 ? W0 : which == 1 ? W1 : which == 2 ? W2 :
                       which == 3 ? W3 : W4;
    size_t idx = ((size_t)blockIdx.x * 256 + threadIdx.x) * 4;
    float4 v = *(const float4*)(src + idx);
    __half2 a = __floats2half2_rn(v.x, v.y);
    __half2 b = __floats2half2_rn(v.z, v.w);
    size_t o = (size_t)which * WSZ + idx;
    *(uint2*)((char*)d_Wh + o*2) = make_uint2(*(uint32_t*)&a, *(uint32_t*)&b);
}
// activations: fp16 2-term split
__global__ void __launch_bounds__(256) aconv_kernel(
    const float* __restrict__ A0, const float* __restrict__ A1)
{
    int which = blockIdx.y;
    const float* src = which == 0 ? A0 : A1;
    size_t idx = ((size_t)blockIdx.x * 256 + threadIdx.x) * 4;
    float4 v = *(const float4*)(src + idx);
    uint32_t h0, l0, h1, l1;
    split2h(v.x, v.y, h0, l0);
    split2h(v.z, v.w, h1, l1);
    size_t o = (size_t)which * MROWS * CS + idx;
    *(uint2*)((char*)d_inh + o*2) = make_uint2(h0, h1);
    *(uint2*)((char*)d_inl + o*2) = make_uint2(l0, l1);
}

// ================= GEMM: fp16 2-term A, single fp16 B, cp.async 3-stage =====
#define ASTRIDE 40
#define BSTRIDE 72
#define AHI_OFF 0
#define ALO_OFF 10240
#define BHI_OFF 20480
#define BUFBYTES 25088
#define GEMM_SMEM (3*BUFBYTES)   // 75264

__device__ __forceinline__ void gemm_core(
    const __nv_bfloat16* __restrict__ Ah, const __nv_bfloat16* __restrict__ Al,
    const __nv_bfloat16* __restrict__ Bh,
    const float* __restrict__ bq, int mode,
    float* __restrict__ Cf, __nv_bfloat16* __restrict__ Ch, __nv_bfloat16* __restrict__ Cl)
{
    extern __shared__ char sm_raw[];
    uint32_t sbase = (uint32_t)__cvta_generic_to_shared(sm_raw);

    int tid = threadIdx.x;
    int wid = tid >> 5, lane = tid & 31;
    int warpM = wid >> 1, warpN = wid & 1;
    int m0 = blockIdx.y * 128, n0 = blockIdx.x * 64;

    float acc[2][4][4];
    #pragma unroll
    for (int mt = 0; mt < 2; mt++)
        #pragma unroll
        for (int nt = 0; nt < 4; nt++)
            #pragma unroll
            for (int i = 0; i < 4; i++) acc[mt][nt][i] = 0.f;

    int matr = lane >> 3, rr = lane & 7;
    int aRowBase = warpM * 32 + (matr & 1) * 8 + rr;
    int aColBase = (matr >> 1) * 8;
    int bRowBase = (matr & 1) * 8 + rr;
    int bColBase = warpN * 32 + (matr >> 1) * 8;

    int arow = tid >> 2, aq = tid & 3;
    int brow = tid >> 3, bqc = tid & 7;

    auto issue = [&](int c, int buf) {
        uint32_t st = sbase + buf * BUFBYTES;
        #pragma unroll
        for (int r = 0; r < 2; r++) {
            int row = arow + r * 64;
            const __nv_bfloat16* sh = Ah + (size_t)(m0 + row) * CS + c * 32 + aq * 8;
            const __nv_bfloat16* sl = Al + (size_t)(m0 + row) * CS + c * 32 + aq * 8;
            uint32_t d = st + row * 80 + aq * 16;
            CPA(d + AHI_OFF, sh);
            CPA(d + ALO_OFF, sl);
        }
        {
            const __nv_bfloat16* sh = Bh + (size_t)(c * 32 + brow) * CS + n0 + bqc * 8;
            CPA(st + BHI_OFF + brow * 144 + bqc * 16, sh);
        }
    };

    issue(0, 0); CPCOMMIT();
    issue(1, 1); CPCOMMIT();

    const int CHUNKS = 32;
    for (int c = 0; c < CHUNKS; c++) {
        CPWAIT1();
        __syncthreads();
        if (c + 2 < CHUNKS) issue(c + 2, (c + 2) % 3);
        CPCOMMIT();

        uint32_t off = sbase + (c % 3) * BUFBYTES;
        #pragma unroll
        for (int ks = 0; ks < 32; ks += 16) {
            uint32_t Ahf[2][4], Alf[2][4], Bhf[2][4];
            #pragma unroll
            for (int mt = 0; mt < 2; mt++)
                ldsm4(Ahf[mt], off + AHI_OFF +
                      (((aRowBase + mt * 16) * ASTRIDE) + aColBase + ks) * 2);
            #pragma unroll
            for (int ntp = 0; ntp < 2; ntp++)
                ldsm4t(Bhf[ntp], off + BHI_OFF +
                       (((bRowBase + ks) * BSTRIDE) + bColBase + ntp * 16) * 2);
            #pragma unroll
            for (int mt = 0; mt < 2; mt++)
                #pragma unroll
                for (int nt = 0; nt < 4; nt++)
                    mma_f16(acc[mt][nt], Ahf[mt], &Bhf[nt >> 1][(nt & 1) * 2]);
            #pragma unroll
            for (int mt = 0; mt < 2; mt++)
                ldsm4(Alf[mt], off + ALO_OFF +
                      (((aRowBase + mt * 16) * ASTRIDE) + aColBase + ks) * 2);
            #pragma unroll
            for (int mt = 0; mt < 2; mt++)
                #pragma unroll
                for (int nt = 0; nt < 4; nt++)
                    mma_f16(acc[mt][nt], Alf[mt], &Bhf[nt >> 1][(nt & 1) * 2]);
        }
    }

    int grp = lane >> 2, tL = lane & 3;
    #pragma unroll
    for (int mt = 0; mt < 2; mt++) {
        #pragma unroll
        for (int nt = 0; nt < 4; nt++) {
            int row = m0 + warpM * 32 + mt * 16 + grp;
            int col = n0 + warpN * 32 + nt * 8 + tL * 2;
            float v0 = acc[mt][nt][0], v1 = acc[mt][nt][1];
            float v2 = acc[mt][nt][2], v3 = acc[mt][nt][3];
            if (mode == 0) {
                float b0 = bq[col], b1 = bq[col + 1];
                v0 = (v0 + b0) * 0.125f; v1 = (v1 + b1) * 0.125f;
                v2 = (v2 + b0) * 0.125f; v3 = (v3 + b1) * 0.125f;
                uint32_t h0, l0, h1, l1;
                split2h(v0, v1, h0, l0);
                split2h(v2, v3, h1, l1);
                *(uint32_t*)((char*)Ch + ((size_t)row * CS + col) * 2)       = h0;
                *(uint32_t*)((char*)Cl + ((size_t)row * CS + col) * 2)       = l0;
                *(uint32_t*)((char*)Ch + ((size_t)(row + 8) * CS + col) * 2) = h1;
                *(uint32_t*)((char*)Cl + ((size_t)(row + 8) * CS + col) * 2) = l1;
            } else if (mode == 1 || mode == 2) {
                __half2 a = __floats2half2_rn(v0, v1);
                __half2 b2 = __floats2half2_rn(v2, v3);
                *(uint32_t*)((char*)Ch + ((size_t)row * CS + col) * 2)       = *(uint32_t*)&a;
                *(uint32_t*)((char*)Ch + ((size_t)(row + 8) * CS + col) * 2) = *(uint32_t*)&b2;
            } else if (mode == 3) {
                v0 = 1.f/(1.f + __expf(-v0)); v1 = 1.f/(1.f + __expf(-v1));
                v2 = 1.f/(1.f + __expf(-v2)); v3 = 1.f/(1.f + __expf(-v3));
                *(float2*)(Cf + (size_t)row * CS + col)       = make_float2(v0, v1);
                *(float2*)(Cf + (size_t)(row + 8) * CS + col) = make_float2(v2, v3);
            } else {
                *(float2*)(Cf + (size_t)row * CS + col)       = make_float2(v0, v1);
                *(float2*)(Cf + (size_t)(row + 8) * CS + col) = make_float2(v2, v3);
            }
        }
    }
}

__global__ void __launch_bounds__(256) proj4_kernel(const float* __restrict__ bq)
{
    int which = blockIdx.z;
    const __nv_bfloat16* Ah = (which == 0 || which == 3) ? d_inh : d_inh + MROWS*CS;
    const __nv_bfloat16* Al = (which == 0 || which == 3) ? d_inl : d_inl + MROWS*CS;
    const __nv_bfloat16* Bh = d_Wh + (size_t)which * WSZ;
    __nv_bfloat16* Ch = which == 0 ? d_qh : which == 1 ? d_kh : which == 2 ? d_vh : nullptr;
    __nv_bfloat16* Cl = which == 0 ? d_ql : nullptr;
    gemm_core(Ah, Al, Bh, bq, which, d_g, Ch, Cl);
}

__global__ void __launch_bounds__(256) final_gemm(float* __restrict__ out)
{
    gemm_core(d_goh, d_gol, d_Wh + 4*(size_t)WSZ, nullptr, 4, out, nullptr, nullptr);
}

// ---------------- fold LN affine into z-projection ----------------
__global__ void prep_kernel(const float* __restrict__ ln_g,
                            const float* __restrict__ ln_b,
                            const float* __restrict__ Wz)
{
    __shared__ float sB[CZ*NH];
    __shared__ float sG[CZ*NH];
    int c = threadIdx.x;
    float g = ln_g[c], bb = ln_b[c];
    #pragma unroll
    for (int h = 0; h < NH; h++) {
        float w = Wz[c*NH + h];
        float gz = g*w;
        d_Gz[c*NH + h] = gz;
        sG[c*NH + h] = gz;
        sB[c*NH + h] = bb*w;
    }
    __syncthreads();
    if (c < NH) {
        float sb = 0.f, sg = 0.f;
        for (int cc = 0; cc < CZ; cc++) { sb += sB[cc*NH + c]; sg += sG[cc*NH + c]; }
        d_Bh[c] = sb;
        d_GzSum[c] = sg;
    }
}

// ====== bias v4: direct gmem fragments with k-permutation (float4 loads), fp16 out ======
#define BM_GH 0
#define BM_GL 6144
#define BM_SG 12288
#define BIAS_SMEM 21504

__global__ void __launch_bounds__(256) bias_mma(const float* __restrict__ z)
{
    extern __shared__ char smraw[];
    uint32_t sb = (uint32_t)__cvta_generic_to_shared(smraw);
    int tid = threadIdx.x, lane = tid & 31, wid = tid >> 5;
    int grp = lane >> 2, tL = lane & 3;
    int t8 = lane >> 3, r8 = lane & 7;

    for (int t = tid; t < CZ*NH; t += 256) {
        int c = t >> 4, hh = t & 15;
        int cb = c & 15, tq = cb >> 2, j = cb & 3;
        int lr = (j < 2) ? (2*tq + j) : (8 + 2*tq + (j - 2));
        int row = (c & 0x70) | lr;
        float w = d_Gz[t];
        __nv_bfloat16 hi = __float2bfloat16(w);
        __nv_bfloat16 lo = __float2bfloat16(w - __bfloat162float(hi));
        ((__nv_bfloat16*)(smraw + BM_GH))[row*24 + hh] = hi;
        ((__nv_bfloat16*)(smraw + BM_GL))[row*24 + hh] = lo;
    }
    __syncthreads();

    const float* z0 = z + (size_t)(blockIdx.x*128 + wid*16 + grp)*CZ;
    const float* z1 = z0 + 8*CZ;

    int gRow = (t8 & 1)*8 + r8;
    int gCol = (t8 >> 1)*8;

    float acc0[4] = {0.f,0.f,0.f,0.f}, acc1[4] = {0.f,0.f,0.f,0.f};
    float s1_0 = 0.f, s2_0 = 0.f, s1_1 = 0.f, s2_1 = 0.f;

    #pragma unroll
    for (int kc = 0; kc < 8; kc++) {
        float4 f = *(const float4*)(z0 + kc*16 + tL*4);
        float4 g = *(const float4*)(z1 + kc*16 + tL*4);

        s1_0 += (f.x + f.y) + (f.z + f.w);
        s2_0 = fmaf(f.x,f.x, fmaf(f.y,f.y, fmaf(f.z,f.z, fmaf(f.w,f.w, s2_0))));
        s1_1 += (g.x + g.y) + (g.z + g.w);
        s2_1 = fmaf(g.x,g.x, fmaf(g.y,g.y, fmaf(g.z,g.z, fmaf(g.w,g.w, s2_1))));

        uint32_t Ahf[4], Alf[4];
        split2(f.x, f.y, Ahf[0], Alf[0]);
        split2(g.x, g.y, Ahf[1], Alf[1]);
        split2(f.z, f.w, Ahf[2], Alf[2]);
        split2(g.z, g.w, Ahf[3], Alf[3]);

        uint32_t Gh[4], Gl[4];
        uint32_t goff = (uint32_t)(((gRow + kc*16)*24 + gCol) * 2);
        ldsm4t(Gh, sb + BM_GH + goff);
        ldsm4t(Gl, sb + BM_GL + goff);

        mma_bf16(acc0, Ahf, &Gh[0]); mma_bf16(acc1, Ahf, &Gh[2]);
        mma_bf16(acc0, Alf, &Gh[0]); mma_bf16(acc1, Alf, &Gh[2]);
        mma_bf16(acc0, Ahf, &Gl[0]); mma_bf16(acc1, Ahf, &Gl[2]);
    }

    s1_0 += __shfl_xor_sync(0xFFFFFFFFu, s1_0, 1);
    s1_0 += __shfl_xor_sync(0xFFFFFFFFu, s1_0, 2);
    s2_0 += __shfl_xor_sync(0xFFFFFFFFu, s2_0, 1);
    s2_0 += __shfl_xor_sync(0xFFFFFFFFu, s2_0, 2);
    s1_1 += __shfl_xor_sync(0xFFFFFFFFu, s1_1, 1);
    s1_1 += __shfl_xor_sync(0xFFFFFFFFu, s1_1, 2);
    s2_1 += __shfl_xor_sync(0xFFFFFFFFu, s2_1, 1);
    s2_1 += __shfl_xor_sync(0xFFFFFFFFu, s2_1, 2);
    float mu0 = s1_0 * (1.f/128.f);
    float rstd0 = rsqrtf(s2_0 * (1.f/128.f) - mu0*mu0 + 1e-5f);
    float mu1 = s1_1 * (1.f/128.f);
    float rstd1 = rsqrtf(s2_1 * (1.f/128.f) - mu1*mu1 + 1e-5f);

    {
        int r0 = wid*16 + grp, r1 = r0 + 8;
        float* stage = (float*)(smraw + BM_SG);
        #pragma unroll
        for (int n = 0; n < 2; n++) {
            float* a = n ? acc1 : acc0;
            int h = n*8 + tL*2;
            float gs0 = d_GzSum[h], gs1 = d_GzSum[h+1];
            float bh0 = d_Bh[h],    bh1 = d_Bh[h+1];
            stage[r0*17 + h]     = rstd0*(a[0] - mu0*gs0) + bh0;
            stage[r0*17 + h + 1] = rstd0*(a[1] - mu0*gs1) + bh1;
            stage[r1*17 + h]     = rstd1*(a[2] - mu1*gs0) + bh0;
            stage[r1*17 + h + 1] = rstd1*(a[3] - mu1*gs1) + bh1;
        }
    }
    __syncthreads();

    {
        int p0  = blockIdx.x * 128;
        int b   = p0 / (Nn*Nn);
        int rem = p0 % (Nn*Nn);
        int ii  = rem / Nn;
        int j0  = rem % Nn;
        float* stage = (float*)(smraw + BM_SG);
        #pragma unroll
        for (int t = tid; t < 128*8; t += 256) {
            int h = t >> 6, rr2 = (t & 63) * 2;
            __half2 val = __floats2half2_rn(stage[rr2*17 + h], stage[(rr2+1)*17 + h]);
            *(__half2*)(d_bias + ((size_t)(b*NH + h)*Nn + ii)*Nn + j0 + rr2) = val;
        }
    }
}

// ========== flash attention: 128 threads, 32-row i-tile, 4 blocks/SM ==========
#define AT_STRIDE 72
#define AQ_H 0
#define AQ_L 4608
#define KV0 9216
#define KVSTAGE 18432        // Kh(9216) + Vh(9216)
#define OSM_OFF 0
#define OSM_STRIDE 68
#define STAT_OFF 17408
#define ATT_SMEM 46080

__global__ void __launch_bounds__(128, 4) attn_mma(const float* __restrict__ mask)
{
    extern __shared__ char smraw[];
    uint32_t sb = (uint32_t)__cvta_generic_to_shared(smraw);
    int tid = threadIdx.x, lane = tid & 31, wid = tid >> 5;
    int warpM = wid >> 1, warpN = wid & 1;
    int b = blockIdx.z, h = blockIdx.y, i0 = blockIdx.x * 32;
    int grp = lane >> 2, tL = lane & 3;
    int t8 = lane >> 3, r8 = lane & 7;

    {
        #pragma unroll
        for (int i = 0; i < 4; i++) {
            int g = tid + i*128;
            int mtx = g >> 8, r = (g >> 3) & 31, q = g & 7;
            const __nv_bfloat16* src = (mtx ? d_ql : d_qh) +
                (size_t)(b*Nn + i0 + r)*CS + h*HD + q*8;
            CPA(sb + mtx*4608 + r*144 + q*16, src);
        }
        #pragma unroll
        for (int i = 0; i < 8; i++) {
            int g = tid + i*128;
            int mtx = g >> 9, r = (g >> 3) & 63, q = g & 7;
            const __nv_bfloat16* src = (mtx ? d_vh : d_kh) +
                (size_t)(b*Nn + r)*CS + h*HD + q*8;
            CPA(sb + KV0 + mtx*9216 + r*144 + q*16, src);
        }
        CPCOMMIT();
    }

    float Oa[8][4];
    #pragma unroll
    for (int t = 0; t < 8; t++) { Oa[t][0]=0.f; Oa[t][1]=0.f; Oa[t][2]=0.f; Oa[t][3]=0.f; }
    float mrow0 = -1e30f, mrow1 = -1e30f, lsum0 = 0.f, lsum1 = 0.f;

    const float* maskp = mask + b*Nn;
    const __half* biasbase = d_bias + ((size_t)(b*NH + h)*Nn + (i0 + warpM*16 + grp))*Nn;

    int aRow  = warpM*16 + (t8 & 1)*8 + r8;
    int aCol  = (t8 >> 1)*8;
    int kRowB = warpN*32 + (t8 >> 1)*8 + r8;
    int kColB = (t8 & 1)*8;
    int vRowB = (t8 & 1)*8 + r8;
    int vColB = (t8 >> 1)*8;

    #pragma unroll 1
    for (int jt = 0; jt < 12; jt++) {
        int j0c = jt * 64;
        __syncthreads();
        if (jt + 1 < 12) {
            int st1 = (jt + 1) & 1;
            #pragma unroll
            for (int i = 0; i < 8; i++) {
                int g = tid + i*128;
                int mtx = g >> 9, r = (g >> 3) & 63, q = g & 7;
                const __nv_bfloat16* src = (mtx ? d_vh : d_kh) +
                    (size_t)(b*Nn + j0c + 64 + r)*CS + h*HD + q*8;
                CPA(sb + KV0 + st1*KVSTAGE + mtx*9216 + r*144 + q*16, src);
            }
        }
        CPCOMMIT();
        CPWAIT1();
        __syncthreads();

        uint32_t ks = sb + KV0 + (jt & 1)*KVSTAGE;

        float S[4][4];
        #pragma unroll
        for (int nt = 0; nt < 4; nt++) { S[nt][0]=0.f; S[nt][1]=0.f; S[nt][2]=0.f; S[nt][3]=0.f; }
        #pragma unroll
        for (int kk = 0; kk < 4; kk++) {
            uint32_t qh_[4], ql_[4], khf[2][4];
            uint32_t aoff = (uint32_t)((aRow*AT_STRIDE + kk*16 + aCol) * 2);
            ldsm4(qh_, sb + AQ_H + aoff);
            ldsm4(ql_, sb + AQ_L + aoff);
            uint32_t koff0 = (uint32_t)((kRowB*AT_STRIDE + kk*16 + kColB) * 2);
            uint32_t koff1 = (uint32_t)(((kRowB+16)*AT_STRIDE + kk*16 + kColB) * 2);
            ldsm4(khf[0], ks + koff0);
            ldsm4(khf[1], ks + koff1);
            #pragma unroll
            for (int nt = 0; nt < 4; nt++)
                mma_f16(S[nt], qh_, &khf[nt >> 1][(nt & 1)*2]);
            #pragma unroll
            for (int nt = 0; nt < 4; nt++)
                mma_f16(S[nt], ql_, &khf[nt >> 1][(nt & 1)*2]);
        }

        #pragma unroll
        for (int nt = 0; nt < 4; nt++) {
            int jc = j0c + warpN*32 + nt*8 + tL*2;
            float2 b0 = __half22float2(*(const __half2*)(biasbase + jc));
            float2 b1 = __half22float2(*(const __half2*)(biasbase + (size_t)8*Nn + jc));
            float2 mv = *(const float2*)(maskp + jc);
            float mk0 = (1.f - mv.x) * (-1000000.0f);
            float mk1 = (1.f - mv.y) * (-1000000.0f);
            S[nt][0] += b0.x + mk0; S[nt][1] += b0.y + mk1;
            S[nt][2] += b1.x + mk0; S[nt][3] += b1.y + mk1;
        }

        float cm0 = fmaxf(fmaxf(S[0][0], S[0][1]), fmaxf(S[1][0], S[1][1]));
        cm0 = fmaxf(cm0, fmaxf(fmaxf(S[2][0], S[2][1]), fmaxf(S[3][0], S[3][1])));
        float cm1 = fmaxf(fmaxf(S[0][2], S[0][3]), fmaxf(S[1][2], S[1][3]));
        cm1 = fmaxf(cm1, fmaxf(fmaxf(S[2][2], S[2][3]), fmaxf(S[3][2], S[3][3])));
        cm0 = fmaxf(cm0, __shfl_xor_sync(0xFFFFFFFFu, cm0, 1));
        cm0 = fmaxf(cm0, __shfl_xor_sync(0xFFFFFFFFu, cm0, 2));
        cm1 = fmaxf(cm1, __shfl_xor_sync(0xFFFFFFFFu, cm1, 1));
        cm1 = fmaxf(cm1, __shfl_xor_sync(0xFFFFFFFFu, cm1, 2));
        float mn0 = fmaxf(mrow0, cm0), mn1 = fmaxf(mrow1, cm1);
        float sc0 = __expf(mrow0 - mn0), sc1 = __expf(mrow1 - mn1);
        mrow0 = mn0; mrow1 = mn1;
        float rs0 = 0.f, rs1 = 0.f;
        #pragma unroll
        for (int nt = 0; nt < 4; nt++) {
            S[nt][0] = __expf(S[nt][0] - mn0);
            S[nt][1] = __expf(S[nt][1] - mn0);
            S[nt][2] = __expf(S[nt][2] - mn1);
            S[nt][3] = __expf(S[nt][3] - mn1);
            rs0 += S[nt][0] + S[nt][1];
            rs1 += S[nt][2] + S[nt][3];
        }
        rs0 += __shfl_xor_sync(0xFFFFFFFFu, rs0, 1);
        rs0 += __shfl_xor_sync(0xFFFFFFFFu, rs0, 2);
        rs1 += __shfl_xor_sync(0xFFFFFFFFu, rs1, 1);
        rs1 += __shfl_xor_sync(0xFFFFFFFFu, rs1, 2);
        lsum0 = lsum0*sc0 + rs0;
        lsum1 = lsum1*sc1 + rs1;
        #pragma unroll
        for (int t = 0; t < 8; t++) {
            Oa[t][0] *= sc0; Oa[t][1] *= sc0;
            Oa[t][2] *= sc1; Oa[t][3] *= sc1;
        }

        uint32_t Ph[2][4], Pl[2][4];
        #pragma unroll
        for (int kf = 0; kf < 2; kf++) {
            split2h(S[2*kf][0],   S[2*kf][1],   Ph[kf][0], Pl[kf][0]);
            split2h(S[2*kf][2],   S[2*kf][3],   Ph[kf][1], Pl[kf][1]);
            split2h(S[2*kf+1][0], S[2*kf+1][1], Ph[kf][2], Pl[kf][2]);
            split2h(S[2*kf+1][2], S[2*kf+1][3], Ph[kf][3], Pl[kf][3]);
        }

        #pragma unroll
        for (int kf = 0; kf < 2; kf++) {
            int kb = warpN*32 + kf*16;
            #pragma unroll
            for (int ntp = 0; ntp < 4; ntp++) {
                uint32_t vhf[4];
                uint32_t voff = (uint32_t)(((kb + vRowB)*AT_STRIDE + ntp*16 + vColB) * 2);
                ldsm4t(vhf, ks + 9216 + voff);
                mma_f16(Oa[ntp*2],   Ph[kf], &vhf[0]);
                mma_f16(Oa[ntp*2+1], Ph[kf], &vhf[2]);
                mma_f16(Oa[ntp*2],   Pl[kf], &vhf[0]);
                mma_f16(Oa[ntp*2+1], Pl[kf], &vhf[2]);
            }
        }
    }

    __syncthreads();
    float* Osm  = (float*)(smraw + OSM_OFF);
    float* stat = (float*)(smraw + STAT_OFF);
    #pragma unroll
    for (int t = 0; t < 8; t++) {
        int dcol = t*8 + tL*2;
        Osm[(wid*16 + grp)*OSM_STRIDE + dcol]       = Oa[t][0];
        Osm[(wid*16 + grp)*OSM_STRIDE + dcol + 1]   = Oa[t][1];
        Osm[(wid*16 + grp+8)*OSM_STRIDE + dcol]     = Oa[t][2];
        Osm[(wid*16 + grp+8)*OSM_STRIDE + dcol + 1] = Oa[t][3];
    }
    if (tL == 0) {
        stat[wid*32 + grp*2]       = mrow0;
        stat[wid*32 + grp*2 + 1]   = lsum0;
        stat[wid*32 + (grp+8)*2]     = mrow1;
        stat[wid*32 + (grp+8)*2 + 1] = lsum1;
    }
    __syncthreads();

    for (int t = tid; t < 32*32; t += 128) {
        int row = t >> 5, d2 = (t & 31)*2;
        int w0 = (row >> 4)*2, rl = row & 15;
        float m0 = stat[w0*32 + rl*2],     l0 = stat[w0*32 + rl*2 + 1];
        float m1 = stat[(w0+1)*32 + rl*2], l1 = stat[(w0+1)*32 + rl*2 + 1];
        float mm = fmaxf(m0, m1);
        float a0 = __expf(m0 - mm), a1 = __expf(m1 - mm);
        float inv = 1.f / (a0*l0 + a1*l1);
        float o0 = (a0*Osm[(w0*16 + rl)*OSM_STRIDE + d2] +
                    a1*Osm[((w0+1)*16 + rl)*OSM_STRIDE + d2]) * inv;
        float o1 = (a0*Osm[(w0*16 + rl)*OSM_STRIDE + d2 + 1] +
                    a1*Osm[((w0+1)*16 + rl)*OSM_STRIDE + d2 + 1]) * inv;
        size_t gi = (size_t)(b*Nn + i0 + row)*CS + h*HD + d2;
        float2 gg = *(const float2*)(d_g + gi);
        uint32_t hh, ll;
        split2h(gg.x * o0, gg.y * o1, hh, ll);
        *(uint32_t*)((char*)d_goh + gi*2) = hh;
        *(uint32_t*)((char*)d_gol + gi*2) = ll;
    }
}

// ---------------- launch: fork bias chain; proj4 is submission #4 for ncu ----------------
extern "C" void kernel_launch(void* const* d_in, const int* in_sizes, int n_in,
                              void* d_out, int out_size)
{
    const float* s    = (const float*)d_in[0];
    const float* z    = (const float*)d_in[1];
    const float* mask = (const float*)d_in[2];
    const float* k_in = (const float*)d_in[3];
    const float* Wq   = (const float*)d_in[4];
    const float* bq   = (const float*)d_in[5];
    const float* Wk   = (const float*)d_in[6];
    const float* Wv   = (const float*)d_in[7];
    const float* Wg   = (const float*)d_in[8];
    const float* ln_g = (const float*)d_in[9];
    const float* ln_b = (const float*)d_in[10];
    const float* Wz   = (const float*)d_in[11];
    const float* Wo   = (const float*)d_in[12];
    float* out = (float*)d_out;

    static cudaStream_t s2 = nullptr;
    static cudaEvent_t evF = nullptr, evJ = nullptr;
    if (s2 == nullptr) {
        cudaStreamCreateWithFlags(&s2, cudaStreamNonBlocking);
        cudaEventCreateWithFlags(&evF, cudaEventDisableTiming);
        cudaEventCreateWithFlags(&evJ, cudaEventDisableTiming);
        cudaFuncSetAttribute(proj4_kernel, cudaFuncAttributeMaxDynamicSharedMemorySize, GEMM_SMEM);
        cudaFuncSetAttribute(final_gemm,   cudaFuncAttributeMaxDynamicSharedMemorySize, GEMM_SMEM);
        cudaFuncSetAttribute(attn_mma,     cudaFuncAttributeMaxDynamicSharedMemorySize, ATT_SMEM);
        cudaFuncSetAttribute(bias_mma,     cudaFuncAttributeMaxDynamicSharedMemorySize, BIAS_SMEM);
    }

    // stream A (#1, #2)
    cudaEventRecord(evF, 0);
    cudaStreamWaitEvent(s2, evF, 0);
    wconv_kernel<<<dim3(WSZ/1024, 5), 256>>>(Wq, Wk, Wv, Wg, Wo);
    aconv_kernel<<<dim3(MROWS*CS/1024, 2), 256>>>(s, k_in);

    // stream B: prep (#3); stream A: proj4 (#4 — profiler target); stream B: bias (#5)
    prep_kernel<<<1, 128, 0, s2>>>(ln_g, ln_b, Wz);
    proj4_kernel<<<dim3(CS/64, MROWS/128, 4), 256, GEMM_SMEM>>>(bq);
    bias_mma<<<NPAIR/128, 256, BIAS_SMEM, s2>>>(z);
    cudaEventRecord(evJ, s2);

    // join, then attention (#6) + output projection (#7)
    cudaStreamWaitEvent(0, evJ, 0);
    attn_mma<<<dim3(Nn/32, NH, Bn), 128, ATT_SMEM>>>(mask);
    final_gemm<<<dim3(CS/64, MROWS/128), 256, GEMM_SMEM>>>(out);
}

// round 14
// speedup vs baseline: 4.6419x; 1.0401x over previous
#include <cuda_runtime.h>
#include <cuda_bf16.h>
#include <cuda_fp16.h>
#include <cstdint>
#include <cstddef>

#define Bn 2
#define Nn 768
#define CS 1024
#define CZ 128
#define NH 16
#define HD 64
#define MROWS (Bn*Nn)     // 1536
#define NPAIR (Bn*Nn*Nn)  // 1179648
#define WSZ (CS*CS)

// ---------------- scratch (device globals; no allocations allowed) ----------------
__device__ __nv_bfloat16 d_Wh[5*WSZ];                        // weights, single fp16
__device__ __nv_bfloat16 d_inh[2*MROWS*CS], d_inl[2*MROWS*CS]; // s, k_in fp16 2-term
__device__ __nv_bfloat16 d_qh[MROWS*CS], d_ql[MROWS*CS];    // q fp16 2-term
__device__ __nv_bfloat16 d_kh[MROWS*CS];                    // k fp16
__device__ __nv_bfloat16 d_vh[MROWS*CS];                    // v fp16
__device__ __nv_bfloat16 d_goh[MROWS*CS], d_gol[MROWS*CS];  // go fp16 2-term
__device__ float d_g[MROWS*CS];
__device__ __half d_bias[Bn*NH*Nn*Nn];    // fp16 bias (37.7 MB)
__device__ float d_Gz[CZ*NH];
__device__ float d_Bh[NH];
__device__ float d_GzSum[NH];

// ================= helpers ====================
__device__ __forceinline__ void ldsm4(uint32_t* r, uint32_t a) {
    asm volatile("ldmatrix.sync.aligned.m8n8.x4.shared.b16 {%0,%1,%2,%3}, [%4];"
                 : "=r"(r[0]), "=r"(r[1]), "=r"(r[2]), "=r"(r[3]) : "r"(a));
}
__device__ __forceinline__ void ldsm4t(uint32_t* r, uint32_t a) {
    asm volatile("ldmatrix.sync.aligned.m8n8.x4.trans.shared.b16 {%0,%1,%2,%3}, [%4];"
                 : "=r"(r[0]), "=r"(r[1]), "=r"(r[2]), "=r"(r[3]) : "r"(a));
}
__device__ __forceinline__ void mma_bf16(float* c, const uint32_t* a, const uint32_t* b) {
    asm volatile("mma.sync.aligned.m16n8k16.row.col.f32.bf16.bf16.f32 "
                 "{%0,%1,%2,%3}, {%4,%5,%6,%7}, {%8,%9}, {%0,%1,%2,%3};"
                 : "+f"(c[0]), "+f"(c[1]), "+f"(c[2]), "+f"(c[3])
                 : "r"(a[0]), "r"(a[1]), "r"(a[2]), "r"(a[3]), "r"(b[0]), "r"(b[1]));
}
__device__ __forceinline__ void mma_f16(float* c, const uint32_t* a, const uint32_t* b) {
    asm volatile("mma.sync.aligned.m16n8k16.row.col.f32.f16.f16.f32 "
                 "{%0,%1,%2,%3}, {%4,%5,%6,%7}, {%8,%9}, {%0,%1,%2,%3};"
                 : "+f"(c[0]), "+f"(c[1]), "+f"(c[2]), "+f"(c[3])
                 : "r"(a[0]), "r"(a[1]), "r"(a[2]), "r"(a[3]), "r"(b[0]), "r"(b[1]));
}
__device__ __forceinline__ void split2(float x, float y, uint32_t& hi, uint32_t& lo) {
    __nv_bfloat162 h = __float22bfloat162_rn(make_float2(x, y));
    float2 hf = __bfloat1622float2(h);
    __nv_bfloat162 l = __float22bfloat162_rn(make_float2(x - hf.x, y - hf.y));
    hi = *(uint32_t*)&h;
    lo = *(uint32_t*)&l;
}
__device__ __forceinline__ void split2h(float x, float y, uint32_t& hi, uint32_t& lo) {
    __half2 h = __floats2half2_rn(x, y);
    float2 hf = __half22float2(h);
    __half2 l = __floats2half2_rn(x - hf.x, y - hf.y);
    hi = *(uint32_t*)&h;
    lo = *(uint32_t*)&l;
}
#define CPA(dst, src) asm volatile("cp.async.cg.shared.global [%0], [%1], 16;" :: "r"(dst), "l"(src))
#define CPCOMMIT()    asm volatile("cp.async.commit_group;")
#define CPWAIT1()     asm volatile("cp.async.wait_group 1;")

// ---------------- pre-split converters ----------------
__global__ void __launch_bounds__(256) wconv_kernel(
    const float* __restrict__ W0, const float* __restrict__ W1,
    const float* __restrict__ W2, const float* __restrict__ W3,
    const float* __restrict__ W4)
{
    int which = blockIdx.y;
    const float* src = which == 0 ? W0 : which == 1 ? W1 : which == 2 ? W2 :
                       which == 3 ? W3 : W4;
    size_t idx = ((size_t)blockIdx.x * 256 + threadIdx.x) * 4;
    float4 v = *(const float4*)(src + idx);
    __half2 a = __floats2half2_rn(v.x, v.y);
    __half2 b = __floats2half2_rn(v.z, v.w);
    size_t o = (size_t)which * WSZ + idx;
    *(uint2*)((char*)d_Wh + o*2) = make_uint2(*(uint32_t*)&a, *(uint32_t*)&b);
}
__global__ void __launch_bounds__(256) aconv_kernel(
    const float* __restrict__ A0, const float* __restrict__ A1)
{
    int which = blockIdx.y;
    const float* src = which == 0 ? A0 : A1;
    size_t idx = ((size_t)blockIdx.x * 256 + threadIdx.x) * 4;
    float4 v = *(const float4*)(src + idx);
    uint32_t h0, l0, h1, l1;
    split2h(v.x, v.y, h0, l0);
    split2h(v.z, v.w, h1, l1);
    size_t o = (size_t)which * MROWS * CS + idx;
    *(uint2*)((char*)d_inh + o*2) = make_uint2(h0, h1);
    *(uint2*)((char*)d_inl + o*2) = make_uint2(l0, l1);
}

// ================= GEMM: fp16 2-term A (1-term for sigmoid gate), fp16 B =====
#define ASTRIDE 40
#define BSTRIDE 72
#define AHI_OFF 0
#define ALO_OFF 10240
#define BHI_OFF 20480
#define BUFBYTES 25088
#define GEMM_SMEM (3*BUFBYTES)   // 75264

__device__ __forceinline__ void gemm_core(
    const __nv_bfloat16* __restrict__ Ah, const __nv_bfloat16* __restrict__ Al,
    const __nv_bfloat16* __restrict__ Bh,
    const float* __restrict__ bq, int mode,
    float* __restrict__ Cf, __nv_bfloat16* __restrict__ Ch, __nv_bfloat16* __restrict__ Cl)
{
    extern __shared__ char sm_raw[];
    uint32_t sbase = (uint32_t)__cvta_generic_to_shared(sm_raw);
    const bool twoterm = (mode != 3);   // sigmoid gate tolerates 1-term

    int tid = threadIdx.x;
    int wid = tid >> 5, lane = tid & 31;
    int warpM = wid >> 1, warpN = wid & 1;
    int m0 = blockIdx.y * 128, n0 = blockIdx.x * 64;

    float acc[2][4][4];
    #pragma unroll
    for (int mt = 0; mt < 2; mt++)
        #pragma unroll
        for (int nt = 0; nt < 4; nt++)
            #pragma unroll
            for (int i = 0; i < 4; i++) acc[mt][nt][i] = 0.f;

    int matr = lane >> 3, rr = lane & 7;
    int aRowBase = warpM * 32 + (matr & 1) * 8 + rr;
    int aColBase = (matr >> 1) * 8;
    int bRowBase = (matr & 1) * 8 + rr;
    int bColBase = warpN * 32 + (matr >> 1) * 8;

    int arow = tid >> 2, aq = tid & 3;
    int brow = tid >> 3, bqc = tid & 7;

    auto issue = [&](int c, int buf) {
        uint32_t st = sbase + buf * BUFBYTES;
        #pragma unroll
        for (int r = 0; r < 2; r++) {
            int row = arow + r * 64;
            const __nv_bfloat16* sh = Ah + (size_t)(m0 + row) * CS + c * 32 + aq * 8;
            uint32_t d = st + row * 80 + aq * 16;
            CPA(d + AHI_OFF, sh);
            if (twoterm) {
                const __nv_bfloat16* sl = Al + (size_t)(m0 + row) * CS + c * 32 + aq * 8;
                CPA(d + ALO_OFF, sl);
            }
        }
        {
            const __nv_bfloat16* sh = Bh + (size_t)(c * 32 + brow) * CS + n0 + bqc * 8;
            CPA(st + BHI_OFF + brow * 144 + bqc * 16, sh);
        }
    };

    issue(0, 0); CPCOMMIT();
    issue(1, 1); CPCOMMIT();

    const int CHUNKS = 32;
    for (int c = 0; c < CHUNKS; c++) {
        CPWAIT1();
        __syncthreads();
        if (c + 2 < CHUNKS) issue(c + 2, (c + 2) % 3);
        CPCOMMIT();

        uint32_t off = sbase + (c % 3) * BUFBYTES;
        #pragma unroll
        for (int ks = 0; ks < 32; ks += 16) {
            uint32_t Ahf[2][4], Alf[2][4], Bhf[2][4];
            #pragma unroll
            for (int mt = 0; mt < 2; mt++)
                ldsm4(Ahf[mt], off + AHI_OFF +
                      (((aRowBase + mt * 16) * ASTRIDE) + aColBase + ks) * 2);
            #pragma unroll
            for (int ntp = 0; ntp < 2; ntp++)
                ldsm4t(Bhf[ntp], off + BHI_OFF +
                       (((bRowBase + ks) * BSTRIDE) + bColBase + ntp * 16) * 2);
            #pragma unroll
            for (int mt = 0; mt < 2; mt++)
                #pragma unroll
                for (int nt = 0; nt < 4; nt++)
                    mma_f16(acc[mt][nt], Ahf[mt], &Bhf[nt >> 1][(nt & 1) * 2]);
            if (twoterm) {
                #pragma unroll
                for (int mt = 0; mt < 2; mt++)
                    ldsm4(Alf[mt], off + ALO_OFF +
                          (((aRowBase + mt * 16) * ASTRIDE) + aColBase + ks) * 2);
                #pragma unroll
                for (int mt = 0; mt < 2; mt++)
                    #pragma unroll
                    for (int nt = 0; nt < 4; nt++)
                        mma_f16(acc[mt][nt], Alf[mt], &Bhf[nt >> 1][(nt & 1) * 2]);
            }
        }
    }

    int grp = lane >> 2, tL = lane & 3;
    #pragma unroll
    for (int mt = 0; mt < 2; mt++) {
        #pragma unroll
        for (int nt = 0; nt < 4; nt++) {
            int row = m0 + warpM * 32 + mt * 16 + grp;
            int col = n0 + warpN * 32 + nt * 8 + tL * 2;
            float v0 = acc[mt][nt][0], v1 = acc[mt][nt][1];
            float v2 = acc[mt][nt][2], v3 = acc[mt][nt][3];
            if (mode == 0) {
                float b0 = bq[col], b1 = bq[col + 1];
                v0 = (v0 + b0) * 0.125f; v1 = (v1 + b1) * 0.125f;
                v2 = (v2 + b0) * 0.125f; v3 = (v3 + b1) * 0.125f;
                uint32_t h0, l0, h1, l1;
                split2h(v0, v1, h0, l0);
                split2h(v2, v3, h1, l1);
                *(uint32_t*)((char*)Ch + ((size_t)row * CS + col) * 2)       = h0;
                *(uint32_t*)((char*)Cl + ((size_t)row * CS + col) * 2)       = l0;
                *(uint32_t*)((char*)Ch + ((size_t)(row + 8) * CS + col) * 2) = h1;
                *(uint32_t*)((char*)Cl + ((size_t)(row + 8) * CS + col) * 2) = l1;
            } else if (mode == 1 || mode == 2) {
                __half2 a = __floats2half2_rn(v0, v1);
                __half2 b2 = __floats2half2_rn(v2, v3);
                *(uint32_t*)((char*)Ch + ((size_t)row * CS + col) * 2)       = *(uint32_t*)&a;
                *(uint32_t*)((char*)Ch + ((size_t)(row + 8) * CS + col) * 2) = *(uint32_t*)&b2;
            } else if (mode == 3) {
                v0 = 1.f/(1.f + __expf(-v0)); v1 = 1.f/(1.f + __expf(-v1));
                v2 = 1.f/(1.f + __expf(-v2)); v3 = 1.f/(1.f + __expf(-v3));
                *(float2*)(Cf + (size_t)row * CS + col)       = make_float2(v0, v1);
                *(float2*)(Cf + (size_t)(row + 8) * CS + col) = make_float2(v2, v3);
            } else {
                *(float2*)(Cf + (size_t)row * CS + col)       = make_float2(v0, v1);
                *(float2*)(Cf + (size_t)(row + 8) * CS + col) = make_float2(v2, v3);
            }
        }
    }
}

__global__ void __launch_bounds__(256) proj4_kernel(const float* __restrict__ bq)
{
    int which = blockIdx.z;
    const __nv_bfloat16* Ah = (which == 0 || which == 3) ? d_inh : d_inh + MROWS*CS;
    const __nv_bfloat16* Al = (which == 0 || which == 3) ? d_inl : d_inl + MROWS*CS;
    const __nv_bfloat16* Bh = d_Wh + (size_t)which * WSZ;
    __nv_bfloat16* Ch = which == 0 ? d_qh : which == 1 ? d_kh : which == 2 ? d_vh : nullptr;
    __nv_bfloat16* Cl = which == 0 ? d_ql : nullptr;
    gemm_core(Ah, Al, Bh, bq, which, d_g, Ch, Cl);
}

__global__ void __launch_bounds__(256) final_gemm(float* __restrict__ out)
{
    gemm_core(d_goh, d_gol, d_Wh + 4*(size_t)WSZ, nullptr, 4, out, nullptr, nullptr);
}

// ---------------- fold LN affine into z-projection ----------------
__global__ void prep_kernel(const float* __restrict__ ln_g,
                            const float* __restrict__ ln_b,
                            const float* __restrict__ Wz)
{
    __shared__ float sB[CZ*NH];
    __shared__ float sG[CZ*NH];
    int c = threadIdx.x;
    float g = ln_g[c], bb = ln_b[c];
    #pragma unroll
    for (int h = 0; h < NH; h++) {
        float w = Wz[c*NH + h];
        float gz = g*w;
        d_Gz[c*NH + h] = gz;
        sG[c*NH + h] = gz;
        sB[c*NH + h] = bb*w;
    }
    __syncthreads();
    if (c < NH) {
        float sb = 0.f, sg = 0.f;
        for (int cc = 0; cc < CZ; cc++) { sb += sB[cc*NH + c]; sg += sG[cc*NH + c]; }
        d_Bh[c] = sb;
        d_GzSum[c] = sg;
    }
}

// ====== bias v4: direct gmem fragments with k-permutation (float4 loads), fp16 out ======
#define BM_GH 0
#define BM_GL 6144
#define BM_SG 12288
#define BIAS_SMEM 21504

__global__ void __launch_bounds__(256) bias_mma(const float* __restrict__ z)
{
    extern __shared__ char smraw[];
    uint32_t sb = (uint32_t)__cvta_generic_to_shared(smraw);
    int tid = threadIdx.x, lane = tid & 31, wid = tid >> 5;
    int grp = lane >> 2, tL = lane & 3;
    int t8 = lane >> 3, r8 = lane & 7;

    for (int t = tid; t < CZ*NH; t += 256) {
        int c = t >> 4, hh = t & 15;
        int cb = c & 15, tq = cb >> 2, j = cb & 3;
        int lr = (j < 2) ? (2*tq + j) : (8 + 2*tq + (j - 2));
        int row = (c & 0x70) | lr;
        float w = d_Gz[t];
        __nv_bfloat16 hi = __float2bfloat16(w);
        __nv_bfloat16 lo = __float2bfloat16(w - __bfloat162float(hi));
        ((__nv_bfloat16*)(smraw + BM_GH))[row*24 + hh] = hi;
        ((__nv_bfloat16*)(smraw + BM_GL))[row*24 + hh] = lo;
    }
    __syncthreads();

    const float* z0 = z + (size_t)(blockIdx.x*128 + wid*16 + grp)*CZ;
    const float* z1 = z0 + 8*CZ;

    int gRow = (t8 & 1)*8 + r8;
    int gCol = (t8 >> 1)*8;

    float acc0[4] = {0.f,0.f,0.f,0.f}, acc1[4] = {0.f,0.f,0.f,0.f};
    float s1_0 = 0.f, s2_0 = 0.f, s1_1 = 0.f, s2_1 = 0.f;

    #pragma unroll
    for (int kc = 0; kc < 8; kc++) {
        float4 f = *(const float4*)(z0 + kc*16 + tL*4);
        float4 g = *(const float4*)(z1 + kc*16 + tL*4);

        s1_0 += (f.x + f.y) + (f.z + f.w);
        s2_0 = fmaf(f.x,f.x, fmaf(f.y,f.y, fmaf(f.z,f.z, fmaf(f.w,f.w, s2_0))));
        s1_1 += (g.x + g.y) + (g.z + g.w);
        s2_1 = fmaf(g.x,g.x, fmaf(g.y,g.y, fmaf(g.z,g.z, fmaf(g.w,g.w, s2_1))));

        uint32_t Ahf[4], Alf[4];
        split2(f.x, f.y, Ahf[0], Alf[0]);
        split2(g.x, g.y, Ahf[1], Alf[1]);
        split2(f.z, f.w, Ahf[2], Alf[2]);
        split2(g.z, g.w, Ahf[3], Alf[3]);

        uint32_t Gh[4], Gl[4];
        uint32_t goff = (uint32_t)(((gRow + kc*16)*24 + gCol) * 2);
        ldsm4t(Gh, sb + BM_GH + goff);
        ldsm4t(Gl, sb + BM_GL + goff);

        mma_bf16(acc0, Ahf, &Gh[0]); mma_bf16(acc1, Ahf, &Gh[2]);
        mma_bf16(acc0, Alf, &Gh[0]); mma_bf16(acc1, Alf, &Gh[2]);
        mma_bf16(acc0, Ahf, &Gl[0]); mma_bf16(acc1, Ahf, &Gl[2]);
    }

    s1_0 += __shfl_xor_sync(0xFFFFFFFFu, s1_0, 1);
    s1_0 += __shfl_xor_sync(0xFFFFFFFFu, s1_0, 2);
    s2_0 += __shfl_xor_sync(0xFFFFFFFFu, s2_0, 1);
    s2_0 += __shfl_xor_sync(0xFFFFFFFFu, s2_0, 2);
    s1_1 += __shfl_xor_sync(0xFFFFFFFFu, s1_1, 1);
    s1_1 += __shfl_xor_sync(0xFFFFFFFFu, s1_1, 2);
    s2_1 += __shfl_xor_sync(0xFFFFFFFFu, s2_1, 1);
    s2_1 += __shfl_xor_sync(0xFFFFFFFFu, s2_1, 2);
    float mu0 = s1_0 * (1.f/128.f);
    float rstd0 = rsqrtf(s2_0 * (1.f/128.f) - mu0*mu0 + 1e-5f);
    float mu1 = s1_1 * (1.f/128.f);
    float rstd1 = rsqrtf(s2_1 * (1.f/128.f) - mu1*mu1 + 1e-5f);

    {
        int r0 = wid*16 + grp, r1 = r0 + 8;
        float* stage = (float*)(smraw + BM_SG);
        #pragma unroll
        for (int n = 0; n < 2; n++) {
            float* a = n ? acc1 : acc0;
            int h = n*8 + tL*2;
            float gs0 = d_GzSum[h], gs1 = d_GzSum[h+1];
            float bh0 = d_Bh[h],    bh1 = d_Bh[h+1];
            stage[r0*17 + h]     = rstd0*(a[0] - mu0*gs0) + bh0;
            stage[r0*17 + h + 1] = rstd0*(a[1] - mu0*gs1) + bh1;
            stage[r1*17 + h]     = rstd1*(a[2] - mu1*gs0) + bh0;
            stage[r1*17 + h + 1] = rstd1*(a[3] - mu1*gs1) + bh1;
        }
    }
    __syncthreads();

    {
        int p0  = blockIdx.x * 128;
        int b   = p0 / (Nn*Nn);
        int rem = p0 % (Nn*Nn);
        int ii  = rem / Nn;
        int j0  = rem % Nn;
        float* stage = (float*)(smraw + BM_SG);
        #pragma unroll
        for (int t = tid; t < 128*8; t += 256) {
            int h = t >> 6, rr2 = (t & 63) * 2;
            __half2 val = __floats2half2_rn(stage[rr2*17 + h], stage[(rr2+1)*17 + h]);
            *(__half2*)(d_bias + ((size_t)(b*NH + h)*Nn + ii)*Nn + j0 + rr2) = val;
        }
    }
}

// ========== flash attention: 128 threads, 32-row i-tile, 4 blocks/SM ==========
#define AT_STRIDE 72
#define AQ_H 0
#define AQ_L 4608
#define KV0 9216
#define KVSTAGE 18432
#define OSM_OFF 0
#define OSM_STRIDE 68
#define STAT_OFF 17408
#define ATT_SMEM 46080

__global__ void __launch_bounds__(128, 4) attn_mma(const float* __restrict__ mask)
{
    extern __shared__ char smraw[];
    uint32_t sb = (uint32_t)__cvta_generic_to_shared(smraw);
    int tid = threadIdx.x, lane = tid & 31, wid = tid >> 5;
    int warpM = wid >> 1, warpN = wid & 1;
    int b = blockIdx.z, h = blockIdx.y, i0 = blockIdx.x * 32;
    int grp = lane >> 2, tL = lane & 3;
    int t8 = lane >> 3, r8 = lane & 7;

    {
        #pragma unroll
        for (int i = 0; i < 4; i++) {
            int g = tid + i*128;
            int mtx = g >> 8, r = (g >> 3) & 31, q = g & 7;
            const __nv_bfloat16* src = (mtx ? d_ql : d_qh) +
                (size_t)(b*Nn + i0 + r)*CS + h*HD + q*8;
            CPA(sb + mtx*4608 + r*144 + q*16, src);
        }
        #pragma unroll
        for (int i = 0; i < 8; i++) {
            int g = tid + i*128;
            int mtx = g >> 9, r = (g >> 3) & 63, q = g & 7;
            const __nv_bfloat16* src = (mtx ? d_vh : d_kh) +
                (size_t)(b*Nn + r)*CS + h*HD + q*8;
            CPA(sb + KV0 + mtx*9216 + r*144 + q*16, src);
        }
        CPCOMMIT();
    }

    float Oa[8][4];
    #pragma unroll
    for (int t = 0; t < 8; t++) { Oa[t][0]=0.f; Oa[t][1]=0.f; Oa[t][2]=0.f; Oa[t][3]=0.f; }
    float mrow0 = -1e30f, mrow1 = -1e30f, lsum0 = 0.f, lsum1 = 0.f;

    const float* maskp = mask + b*Nn;
    const __half* biasbase = d_bias + ((size_t)(b*NH + h)*Nn + (i0 + warpM*16 + grp))*Nn;

    int aRow  = warpM*16 + (t8 & 1)*8 + r8;
    int aCol  = (t8 >> 1)*8;
    int kRowB = warpN*32 + (t8 >> 1)*8 + r8;
    int kColB = (t8 & 1)*8;
    int vRowB = (t8 & 1)*8 + r8;
    int vColB = (t8 >> 1)*8;

    #pragma unroll 1
    for (int jt = 0; jt < 12; jt++) {
        int j0c = jt * 64;
        __syncthreads();
        if (jt + 1 < 12) {
            int st1 = (jt + 1) & 1;
            #pragma unroll
            for (int i = 0; i < 8; i++) {
                int g = tid + i*128;
                int mtx = g >> 9, r = (g >> 3) & 63, q = g & 7;
                const __nv_bfloat16* src = (mtx ? d_vh : d_kh) +
                    (size_t)(b*Nn + j0c + 64 + r)*CS + h*HD + q*8;
                CPA(sb + KV0 + st1*KVSTAGE + mtx*9216 + r*144 + q*16, src);
            }
        }
        CPCOMMIT();
        CPWAIT1();
        __syncthreads();

        uint32_t ks = sb + KV0 + (jt & 1)*KVSTAGE;

        float S[4][4];
        #pragma unroll
        for (int nt = 0; nt < 4; nt++) { S[nt][0]=0.f; S[nt][1]=0.f; S[nt][2]=0.f; S[nt][3]=0.f; }
        #pragma unroll
        for (int kk = 0; kk < 4; kk++) {
            uint32_t qh_[4], ql_[4], khf[2][4];
            uint32_t aoff = (uint32_t)((aRow*AT_STRIDE + kk*16 + aCol) * 2);
            ldsm4(qh_, sb + AQ_H + aoff);
            ldsm4(ql_, sb + AQ_L + aoff);
            uint32_t koff0 = (uint32_t)((kRowB*AT_STRIDE + kk*16 + kColB) * 2);
            uint32_t koff1 = (uint32_t)(((kRowB+16)*AT_STRIDE + kk*16 + kColB) * 2);
            ldsm4(khf[0], ks + koff0);
            ldsm4(khf[1], ks + koff1);
            #pragma unroll
            for (int nt = 0; nt < 4; nt++)
                mma_f16(S[nt], qh_, &khf[nt >> 1][(nt & 1)*2]);
            #pragma unroll
            for (int nt = 0; nt < 4; nt++)
                mma_f16(S[nt], ql_, &khf[nt >> 1][(nt & 1)*2]);
        }

        #pragma unroll
        for (int nt = 0; nt < 4; nt++) {
            int jc = j0c + warpN*32 + nt*8 + tL*2;
            float2 b0 = __half22float2(*(const __half2*)(biasbase + jc));
            float2 b1 = __half22float2(*(const __half2*)(biasbase + (size_t)8*Nn + jc));
            float2 mv = *(const float2*)(maskp + jc);
            float mk0 = (1.f - mv.x) * (-1000000.0f);
            float mk1 = (1.f - mv.y) * (-1000000.0f);
            S[nt][0] += b0.x + mk0; S[nt][1] += b0.y + mk1;
            S[nt][2] += b1.x + mk0; S[nt][3] += b1.y + mk1;
        }

        float cm0 = fmaxf(fmaxf(S[0][0], S[0][1]), fmaxf(S[1][0], S[1][1]));
        cm0 = fmaxf(cm0, fmaxf(fmaxf(S[2][0], S[2][1]), fmaxf(S[3][0], S[3][1])));
        float cm1 = fmaxf(fmaxf(S[0][2], S[0][3]), fmaxf(S[1][2], S[1][3]));
        cm1 = fmaxf(cm1, fmaxf(fmaxf(S[2][2], S[2][3]), fmaxf(S[3][2], S[3][3])));
        cm0 = fmaxf(cm0, __shfl_xor_sync(0xFFFFFFFFu, cm0, 1));
        cm0 = fmaxf(cm0, __shfl_xor_sync(0xFFFFFFFFu, cm0, 2));
        cm1 = fmaxf(cm1, __shfl_xor_sync(0xFFFFFFFFu, cm1, 1));
        cm1 = fmaxf(cm1, __shfl_xor_sync(0xFFFFFFFFu, cm1, 2));
        float mn0 = fmaxf(mrow0, cm0), mn1 = fmaxf(mrow1, cm1);
        float sc0 = __expf(mrow0 - mn0), sc1 = __expf(mrow1 - mn1);
        mrow0 = mn0; mrow1 = mn1;
        float rs0 = 0.f, rs1 = 0.f;
        #pragma unroll
        for (int nt = 0; nt < 4; nt++) {
            S[nt][0] = __expf(S[nt][0] - mn0);
            S[nt][1] = __expf(S[nt][1] - mn0);
            S[nt][2] = __expf(S[nt][2] - mn1);
            S[nt][3] = __expf(S[nt][3] - mn1);
            rs0 += S[nt][0] + S[nt][1];
            rs1 += S[nt][2] + S[nt][3];
        }
        rs0 += __shfl_xor_sync(0xFFFFFFFFu, rs0, 1);
        rs0 += __shfl_xor_sync(0xFFFFFFFFu, rs0, 2);
        rs1 += __shfl_xor_sync(0xFFFFFFFFu, rs1, 1);
        rs1 += __shfl_xor_sync(0xFFFFFFFFu, rs1, 2);
        lsum0 = lsum0*sc0 + rs0;
        lsum1 = lsum1*sc1 + rs1;
        #pragma unroll
        for (int t = 0; t < 8; t++) {
            Oa[t][0] *= sc0; Oa[t][1] *= sc0;
            Oa[t][2] *= sc1; Oa[t][3] *= sc1;
        }

        uint32_t Ph[2][4], Pl[2][4];
        #pragma unroll
        for (int kf = 0; kf < 2; kf++) {
            split2h(S[2*kf][0],   S[2*kf][1],   Ph[kf][0], Pl[kf][0]);
            split2h(S[2*kf][2],   S[2*kf][3],   Ph[kf][1], Pl[kf][1]);
            split2h(S[2*kf+1][0], S[2*kf+1][1], Ph[kf][2], Pl[kf][2]);
            split2h(S[2*kf+1][2], S[2*kf+1][3], Ph[kf][3], Pl[kf][3]);
        }

        #pragma unroll
        for (int kf = 0; kf < 2; kf++) {
            int kb = warpN*32 + kf*16;
            #pragma unroll
            for (int ntp = 0; ntp < 4; ntp++) {
                uint32_t vhf[4];
                uint32_t voff = (uint32_t)(((kb + vRowB)*AT_STRIDE + ntp*16 + vColB) * 2);
                ldsm4t(vhf, ks + 9216 + voff);
                mma_f16(Oa[ntp*2],   Ph[kf], &vhf[0]);
                mma_f16(Oa[ntp*2+1], Ph[kf], &vhf[2]);
                mma_f16(Oa[ntp*2],   Pl[kf], &vhf[0]);
                mma_f16(Oa[ntp*2+1], Pl[kf], &vhf[2]);
            }
        }
    }

    __syncthreads();
    float* Osm  = (float*)(smraw + OSM_OFF);
    float* stat = (float*)(smraw + STAT_OFF);
    #pragma unroll
    for (int t = 0; t < 8; t++) {
        int dcol = t*8 + tL*2;
        Osm[(wid*16 + grp)*OSM_STRIDE + dcol]       = Oa[t][0];
        Osm[(wid*16 + grp)*OSM_STRIDE + dcol + 1]   = Oa[t][1];
        Osm[(wid*16 + grp+8)*OSM_STRIDE + dcol]     = Oa[t][2];
        Osm[(wid*16 + grp+8)*OSM_STRIDE + dcol + 1] = Oa[t][3];
    }
    if (tL == 0) {
        stat[wid*32 + grp*2]       = mrow0;
        stat[wid*32 + grp*2 + 1]   = lsum0;
        stat[wid*32 + (grp+8)*2]     = mrow1;
        stat[wid*32 + (grp+8)*2 + 1] = lsum1;
    }
    __syncthreads();

    for (int t = tid; t < 32*32; t += 128) {
        int row = t >> 5, d2 = (t & 31)*2;
        int w0 = (row >> 4)*2, rl = row & 15;
        float m0 = stat[w0*32 + rl*2],     l0 = stat[w0*32 + rl*2 + 1];
        float m1 = stat[(w0+1)*32 + rl*2], l1 = stat[(w0+1)*32 + rl*2 + 1];
        float mm = fmaxf(m0, m1);
        float a0 = __expf(m0 - mm), a1 = __expf(m1 - mm);
        float inv = 1.f / (a0*l0 + a1*l1);
        float o0 = (a0*Osm[(w0*16 + rl)*OSM_STRIDE + d2] +
                    a1*Osm[((w0+1)*16 + rl)*OSM_STRIDE + d2]) * inv;
        float o1 = (a0*Osm[(w0*16 + rl)*OSM_STRIDE + d2 + 1] +
                    a1*Osm[((w0+1)*16 + rl)*OSM_STRIDE + d2 + 1]) * inv;
        size_t gi = (size_t)(b*Nn + i0 + row)*CS + h*HD + d2;
        float2 gg = *(const float2*)(d_g + gi);
        uint32_t hh, ll;
        split2h(gg.x * o0, gg.y * o1, hh, ll);
        *(uint32_t*)((char*)d_goh + gi*2) = hh;
        *(uint32_t*)((char*)d_gol + gi*2) = ll;
    }
}

// ---------------- launch: BOTH chains on non-blocking streams (legacy stream 0 ----------------
// serializes with all streams — that bug killed overlap in earlier rounds).
extern "C" void kernel_launch(void* const* d_in, const int* in_sizes, int n_in,
                              void* d_out, int out_size)
{
    const float* s    = (const float*)d_in[0];
    const float* z    = (const float*)d_in[1];
    const float* mask = (const float*)d_in[2];
    const float* k_in = (const float*)d_in[3];
    const float* Wq   = (const float*)d_in[4];
    const float* bq   = (const float*)d_in[5];
    const float* Wk   = (const float*)d_in[6];
    const float* Wv   = (const float*)d_in[7];
    const float* Wg   = (const float*)d_in[8];
    const float* ln_g = (const float*)d_in[9];
    const float* ln_b = (const float*)d_in[10];
    const float* Wz   = (const float*)d_in[11];
    const float* Wo   = (const float*)d_in[12];
    float* out = (float*)d_out;

    static cudaStream_t s1 = nullptr, s2 = nullptr;
    static cudaEvent_t evF = nullptr, evJ1 = nullptr, evJ2 = nullptr;
    if (s1 == nullptr) {
        cudaStreamCreateWithFlags(&s1, cudaStreamNonBlocking);
        cudaStreamCreateWithFlags(&s2, cudaStreamNonBlocking);
        cudaEventCreateWithFlags(&evF,  cudaEventDisableTiming);
        cudaEventCreateWithFlags(&evJ1, cudaEventDisableTiming);
        cudaEventCreateWithFlags(&evJ2, cudaEventDisableTiming);
        cudaFuncSetAttribute(proj4_kernel, cudaFuncAttributeMaxDynamicSharedMemorySize, GEMM_SMEM);
        cudaFuncSetAttribute(final_gemm,   cudaFuncAttributeMaxDynamicSharedMemorySize, GEMM_SMEM);
        cudaFuncSetAttribute(attn_mma,     cudaFuncAttributeMaxDynamicSharedMemorySize, ATT_SMEM);
        cudaFuncSetAttribute(bias_mma,     cudaFuncAttributeMaxDynamicSharedMemorySize, BIAS_SMEM);
    }

    // fork both chains off the capture stream
    cudaEventRecord(evF, 0);
    cudaStreamWaitEvent(s1, evF, 0);
    cudaStreamWaitEvent(s2, evF, 0);

    // chain A (s1): conversions + projections  (#1, #2, #4)
    wconv_kernel<<<dim3(WSZ/1024, 5), 256, 0, s1>>>(Wq, Wk, Wv, Wg, Wo);
    aconv_kernel<<<dim3(MROWS*CS/1024, 2), 256, 0, s1>>>(s, k_in);

    // chain B (s2): prep + bias  (#3, #5)
    prep_kernel<<<1, 128, 0, s2>>>(ln_g, ln_b, Wz);
    proj4_kernel<<<dim3(CS/64, MROWS/128, 4), 256, GEMM_SMEM, s1>>>(bq);
    bias_mma<<<NPAIR/128, 256, BIAS_SMEM, s2>>>(z);

    cudaEventRecord(evJ1, s1);
    cudaEventRecord(evJ2, s2);

    // join on the capture stream, then attention (#6) + output projection (#7)
    cudaStreamWaitEvent(0, evJ1, 0);
    cudaStreamWaitEvent(0, evJ2, 0);
    attn_mma<<<dim3(Nn/32, NH, Bn), 128, ATT_SMEM>>>(mask);
    final_gemm<<<dim3(CS/64, MROWS/128), 256, GEMM_SMEM>>>(out);
}